// round 2
// baseline (speedup 1.0000x reference)
#include <cuda_runtime.h>
#include <math.h>

#define BB 16
#define NN 64
#define DD 4
#define TT 40
#define LL 10
#define HH 128
#define KK 4
#define EE (NN*(NN-1))   // 4032
#define EPN (NN-1)       // 63 edges per receiver

// ---------------- persistent device state ----------------
__device__ float g_hidden[BB*NN*HH];     // [B,N,H]
__device__ float g_pred[BB*NN*DD];       // [B,N,D] previous prediction
__device__ float g_uv[BB*KK*2*NN*HH];    // [B,K,2,N,H]  u (send part) / v (recv part)
__device__ float g_agg[BB*NN*HH];        // [B,N,H]

// ---------------- f32x2 packed helpers ----------------
__device__ __forceinline__ unsigned long long pk2(float a, float b) {
    unsigned long long r;
    asm("mov.b64 %0, {%1, %2};" : "=l"(r) : "f"(a), "f"(b));
    return r;
}
__device__ __forceinline__ void fma2(unsigned long long& d, unsigned long long a, unsigned long long b) {
    asm("fma.rn.f32x2 %0, %1, %2, %0;" : "+l"(d) : "l"(a), "l"(b));
}
__device__ __forceinline__ float2 upk(unsigned long long a) {
    float2 r;
    asm("mov.b64 {%0, %1}, %2;" : "=f"(r.x), "=f"(r.y) : "l"(a));
    return r;
}

__device__ __forceinline__ float sigmoidf_(float x) { return 1.0f / (1.0f + expf(-x)); }

// ---------------- init ----------------
__global__ void init_kernel() {
    int i = blockIdx.x * blockDim.x + threadIdx.x;
    if (i < BB*NN*HH) g_hidden[i] = 0.0f;
    if (i < BB*NN*DD) g_pred[i]   = 0.0f;
}

// ---------------- UV: u/v = hidden @ W1 halves ----------------
// grid (8, B): blockIdx.x = k*2+s  (s=0: send-half weights, s=1: recv-half), 256 thr
__global__ __launch_bounds__(256)
void uv_kernel(const float* __restrict__ W1) {
    extern __shared__ float sm[];
    float* Ws = sm;            // 128x128
    float* Xs = sm + HH*HH;    // 64x128 hidden rows of this batch
    int ks = blockIdx.x;
    int b  = blockIdx.y;
    // W1 layout [K][2H][H]; slice (k,s) is the contiguous 128x128 block at (k*2+s)*H*H
    const float* Wsrc = W1 + ks * HH * HH;
    for (int idx = threadIdx.x; idx < HH*HH/4; idx += blockDim.x)
        ((float4*)Ws)[idx] = ((const float4*)Wsrc)[idx];
    const float* Hsrc = g_hidden + b*NN*HH;
    for (int idx = threadIdx.x; idx < NN*HH/4; idx += blockDim.x)
        ((float4*)Xs)[idx] = ((const float4*)Hsrc)[idx];
    __syncthreads();

    int h    = threadIdx.x & 127;
    int half = threadIdx.x >> 7;
    float* out = g_uv + (size_t)(b*KK*2 + ks) * NN * HH;
    for (int n = half; n < NN; n += 2) {
        const float* x = Xs + n*HH;
        float acc = 0.0f;
        #pragma unroll
        for (int f4 = 0; f4 < HH; f4 += 4) {
            float4 xv = *(const float4*)(x + f4);
            acc += xv.x * Ws[(f4+0)*HH + h];
            acc += xv.y * Ws[(f4+1)*HH + h];
            acc += xv.z * Ws[(f4+2)*HH + h];
            acc += xv.w * Ws[(f4+3)*HH + h];
        }
        out[n*HH + h] = acc;
    }
}

// ---------------- MSG: fused layer1-assembly + layer2 GEMM + rel_type reduce ----------------
// grid (N, B): one block per (batch, receiver node). 256 threads.
// Exploits np.where structure: edges [i*63, i*63+63) all share recv == i.
__global__ __launch_bounds__(256)
void msg_kernel(const float* __restrict__ W2, const float* __restrict__ b1,
                const float* __restrict__ b2, const float* __restrict__ rel,
                const int* __restrict__ recv_idx, const int* __restrict__ send_idx) {
    extern __shared__ float sm[];
    float* Ws   = sm;                 // 128x128 W2[k]
    float* M1   = Ws + 16384;         // 64x128 (row 63 = zero pad)
    float* Red  = M1 + 8192;          // 8x128 cross-warp reduction
    float* RelS = Red + 1024;         // 64x4
    int*  SendS = (int*)(RelS + 256); // 64

    int i = blockIdx.x, b = blockIdx.y;
    int tid = threadIdx.x;
    int e0 = i * EPN;

    if (tid < 64) {
        if (tid < EPN) {
            SendS[tid] = send_idx[e0 + tid];
            #pragma unroll
            for (int k = 0; k < KK; k++)
                RelS[tid*KK + k] = rel[(size_t)(b*EE + e0 + tid)*KK + k];
        } else {
            SendS[tid] = 0;
            #pragma unroll
            for (int k = 0; k < KK; k++) RelS[tid*KK + k] = 0.0f;
        }
    }
    int ri = recv_idx[e0];

    int hg = tid & 31, eg = tid >> 5;
    int h0 = hg * 4, eb = eg * 8;

    float4 macc[8];
    #pragma unroll
    for (int e = 0; e < 8; e++) macc[e] = make_float4(0.f, 0.f, 0.f, 0.f);

    for (int k = 0; k < KK; k++) {
        __syncthreads();   // protect Ws/M1 (and initial SendS/RelS) before overwrite/use
        // load W2[k]
        const float* Wsrc = W2 + k*HH*HH;
        for (int idx = tid; idx < HH*HH/4; idx += blockDim.x)
            ((float4*)Ws)[idx] = ((const float4*)Wsrc)[idx];
        // build m1 = tanh(u[send] + v[recv] + b1[k])
        const float* u   = g_uv + (size_t)((b*KK + k)*2 + 0) * NN * HH;
        const float* v   = g_uv + (size_t)((b*KK + k)*2 + 1) * NN * HH + (size_t)ri * HH;
        const float* b1k = b1 + k*HH;
        for (int idx = tid; idx < 64*HH; idx += 256) {
            int e = idx >> 7, h = idx & 127;
            float val = 0.0f;
            if (e < EPN) {
                int sn = SendS[e];
                val = tanhf(u[sn*HH + h] + v[h] + b1k[h]);
            }
            M1[idx] = val;
        }
        __syncthreads();

        // layer-2 GEMM: acc[e][h] = sum_f m1[e][f] * W2[k][f][h]  (f32x2 packed)
        unsigned long long acc01[8], acc23[8];
        #pragma unroll
        for (int e = 0; e < 8; e++) { acc01[e] = 0ull; acc23[e] = 0ull; }

        for (int f4 = 0; f4 < HH/4; f4++) {
            int f = f4 * 4;
            float4 w0 = *(const float4*)&Ws[(f+0)*HH + h0];
            float4 w1 = *(const float4*)&Ws[(f+1)*HH + h0];
            float4 w2 = *(const float4*)&Ws[(f+2)*HH + h0];
            float4 w3 = *(const float4*)&Ws[(f+3)*HH + h0];
            unsigned long long w0a = pk2(w0.x, w0.y), w0b = pk2(w0.z, w0.w);
            unsigned long long w1a = pk2(w1.x, w1.y), w1b = pk2(w1.z, w1.w);
            unsigned long long w2a = pk2(w2.x, w2.y), w2b = pk2(w2.z, w2.w);
            unsigned long long w3a = pk2(w3.x, w3.y), w3b = pk2(w3.z, w3.w);
            #pragma unroll
            for (int e = 0; e < 8; e++) {
                float4 a = *(const float4*)&M1[(eb+e)*HH + f];
                unsigned long long a0 = pk2(a.x, a.x);
                unsigned long long a1 = pk2(a.y, a.y);
                unsigned long long a2 = pk2(a.z, a.z);
                unsigned long long a3 = pk2(a.w, a.w);
                fma2(acc01[e], a0, w0a); fma2(acc23[e], a0, w0b);
                fma2(acc01[e], a1, w1a); fma2(acc23[e], a1, w1b);
                fma2(acc01[e], a2, w2a); fma2(acc23[e], a2, w2b);
                fma2(acc01[e], a3, w3a); fma2(acc23[e], a3, w3b);
            }
        }
        // m2 = tanh(acc + b2[k]); weighted by rel_type, accumulate over k
        const float* b2k = b2 + k*HH;
        float bb0 = b2k[h0+0], bb1 = b2k[h0+1], bb2 = b2k[h0+2], bb3 = b2k[h0+3];
        #pragma unroll
        for (int e = 0; e < 8; e++) {
            float relw = RelS[(eb+e)*KK + k];
            float2 p0 = upk(acc01[e]);
            float2 p1 = upk(acc23[e]);
            macc[e].x += relw * tanhf(p0.x + bb0);
            macc[e].y += relw * tanhf(p0.y + bb1);
            macc[e].z += relw * tanhf(p1.x + bb2);
            macc[e].w += relw * tanhf(p1.y + bb3);
        }
    }

    // segment sum over the 63 edges of this receiver (8 per thread, then 8 warps)
    float4 s = macc[0];
    #pragma unroll
    for (int e = 1; e < 8; e++) { s.x += macc[e].x; s.y += macc[e].y; s.z += macc[e].z; s.w += macc[e].w; }
    *(float4*)&Red[eg*HH + h0] = s;
    __syncthreads();
    if (tid < HH) {
        float acc = 0.0f;
        #pragma unroll
        for (int w = 0; w < 8; w++) acc += Red[w*HH + tid];
        g_agg[(size_t)(b*NN + ri)*HH + tid] = acc * (1.0f / (KK * DD));
    }
}

// ---------------- NODE: GRU cell + output MLP ----------------
// grid (4, B): 16 nodes per block, 128 threads (thread = h)
__global__ __launch_bounds__(128)
void node_kernel(const float* __restrict__ data, int step,
                 const float* __restrict__ Wr_h, const float* __restrict__ Wi_h,
                 const float* __restrict__ Wh_h,
                 const float* __restrict__ Wr_in, const float* __restrict__ br_in,
                 const float* __restrict__ Wi_in, const float* __restrict__ bi_in,
                 const float* __restrict__ Wn_in, const float* __restrict__ bn_in,
                 const float* __restrict__ Wo1, const float* __restrict__ bo1,
                 const float* __restrict__ Wo2, const float* __restrict__ bo2,
                 const float* __restrict__ Wo3, const float* __restrict__ bo3,
                 float* __restrict__ out) {
    extern __shared__ float sm[];
    float* Wb   = sm;            // 128x128
    float* aggS = Wb + 16384;    // 16x128
    float* hidS = aggS + 2048;   // 16x128
    float* t1   = hidS + 2048;   // 16x128
    float* t2   = t1 + 2048;     // 16x128
    float* insS = t2 + 2048;     // 16x4

    int q = blockIdx.x, b = blockIdx.y;
    int n0 = q * 16;
    int tid = threadIdx.x;       // 0..127
    int h = tid;

    const float* ag = g_agg    + (size_t)(b*NN + n0) * HH;
    const float* hg = g_hidden + (size_t)(b*NN + n0) * HH;
    for (int idx = tid; idx < 2048/4; idx += 128) {
        ((float4*)aggS)[idx] = ((const float4*)ag)[idx];
        ((float4*)hidS)[idx] = ((const float4*)hg)[idx];
    }
    if (tid < 64) {
        int n = tid >> 2, d = tid & 3;
        float v;
        if (step < TT) v = data[(size_t)((b*NN + n0 + n)*DD + d)*TT + step];
        else           v = g_pred[(b*NN + n0 + n)*DD + d];
        insS[tid] = v;
    }

    // ---- P1: r = sigmoid(ins@Wr_in + br_in + agg@Wr_h) ----
    for (int idx = tid; idx < HH*HH/4; idx += 128)
        ((float4*)Wb)[idx] = ((const float4*)Wr_h)[idx];
    __syncthreads();
    for (int n = 0; n < 16; n++) {
        float acc = br_in[h];
        #pragma unroll
        for (int d = 0; d < 4; d++) acc += insS[n*4+d] * Wr_in[d*HH + h];
        const float* vv = aggS + n*HH;
        #pragma unroll 8
        for (int f4 = 0; f4 < HH/4; f4++) {
            float4 x = ((const float4*)vv)[f4];
            acc += x.x * Wb[(f4*4+0)*HH + h] + x.y * Wb[(f4*4+1)*HH + h]
                 + x.z * Wb[(f4*4+2)*HH + h] + x.w * Wb[(f4*4+3)*HH + h];
        }
        t1[n*HH + h] = sigmoidf_(acc);
    }
    __syncthreads();

    // ---- P2: i = sigmoid(ins@Wi_in + bi_in + agg@Wi_h) ----
    for (int idx = tid; idx < HH*HH/4; idx += 128)
        ((float4*)Wb)[idx] = ((const float4*)Wi_h)[idx];
    __syncthreads();
    for (int n = 0; n < 16; n++) {
        float acc = bi_in[h];
        #pragma unroll
        for (int d = 0; d < 4; d++) acc += insS[n*4+d] * Wi_in[d*HH + h];
        const float* vv = aggS + n*HH;
        #pragma unroll 8
        for (int f4 = 0; f4 < HH/4; f4++) {
            float4 x = ((const float4*)vv)[f4];
            acc += x.x * Wb[(f4*4+0)*HH + h] + x.y * Wb[(f4*4+1)*HH + h]
                 + x.z * Wb[(f4*4+2)*HH + h] + x.w * Wb[(f4*4+3)*HH + h];
        }
        t2[n*HH + h] = sigmoidf_(acc);
    }
    __syncthreads();

    // ---- P3: n = tanh(ins@Wn_in + bn_in + r*(agg@Wh_h)); hidden update ----
    for (int idx = tid; idx < HH*HH/4; idx += 128)
        ((float4*)Wb)[idx] = ((const float4*)Wh_h)[idx];
    __syncthreads();
    for (int n = 0; n < 16; n++) {
        float accin = bn_in[h];
        #pragma unroll
        for (int d = 0; d < 4; d++) accin += insS[n*4+d] * Wn_in[d*HH + h];
        float aggdot = 0.0f;
        const float* vv = aggS + n*HH;
        #pragma unroll 8
        for (int f4 = 0; f4 < HH/4; f4++) {
            float4 x = ((const float4*)vv)[f4];
            aggdot += x.x * Wb[(f4*4+0)*HH + h] + x.y * Wb[(f4*4+1)*HH + h]
                    + x.z * Wb[(f4*4+2)*HH + h] + x.w * Wb[(f4*4+3)*HH + h];
        }
        float r  = t1[n*HH + h];
        float ii = t2[n*HH + h];
        float nn = tanhf(accin + r * aggdot);
        float oldh = hidS[n*HH + h];
        float nh = (1.0f - ii) * nn + ii * oldh;
        hidS[n*HH + h] = nh;
        g_hidden[(size_t)(b*NN + n0 + n)*HH + h] = nh;
    }
    __syncthreads();

    // ---- P4: y1 = relu(hidden@Wo1 + bo1) ----
    for (int idx = tid; idx < HH*HH/4; idx += 128)
        ((float4*)Wb)[idx] = ((const float4*)Wo1)[idx];
    __syncthreads();
    for (int n = 0; n < 16; n++) {
        float acc = bo1[h];
        const float* vv = hidS + n*HH;
        #pragma unroll 8
        for (int f4 = 0; f4 < HH/4; f4++) {
            float4 x = ((const float4*)vv)[f4];
            acc += x.x * Wb[(f4*4+0)*HH + h] + x.y * Wb[(f4*4+1)*HH + h]
                 + x.z * Wb[(f4*4+2)*HH + h] + x.w * Wb[(f4*4+3)*HH + h];
        }
        t1[n*HH + h] = fmaxf(acc, 0.0f);
    }
    __syncthreads();

    // ---- P5: y2 = relu(y1@Wo2 + bo2) ----
    for (int idx = tid; idx < HH*HH/4; idx += 128)
        ((float4*)Wb)[idx] = ((const float4*)Wo2)[idx];
    __syncthreads();
    for (int n = 0; n < 16; n++) {
        float acc = bo2[h];
        const float* vv = t1 + n*HH;
        #pragma unroll 8
        for (int f4 = 0; f4 < HH/4; f4++) {
            float4 x = ((const float4*)vv)[f4];
            acc += x.x * Wb[(f4*4+0)*HH + h] + x.y * Wb[(f4*4+1)*HH + h]
                 + x.z * Wb[(f4*4+2)*HH + h] + x.w * Wb[(f4*4+3)*HH + h];
        }
        t2[n*HH + h] = fmaxf(acc, 0.0f);
    }
    __syncthreads();

    // ---- P6: pred = ins + y2@Wo3 + bo3 ----
    if (tid < 64) {
        int n = tid >> 2, d = tid & 3;
        float acc = bo3[d];
        const float* vv = t2 + n*HH;
        #pragma unroll 4
        for (int hh = 0; hh < HH; hh++) acc += vv[hh] * Wo3[hh*DD + d];
        float pred = insS[tid] + acc;
        g_pred[(b*NN + n0 + n)*DD + d] = pred;
        if (step >= TT)
            out[(size_t)((b*NN + n0 + n)*DD + d)*LL + (step - TT)] = pred;
    }
}

// ---------------- launch ----------------
extern "C" void kernel_launch(void* const* d_in, const int* in_sizes, int n_in,
                              void* d_out, int out_size) {
    const float* data  = (const float*)d_in[0];
    const float* rel   = (const float*)d_in[1];
    const float* W1    = (const float*)d_in[2];
    const float* b1    = (const float*)d_in[3];
    const float* W2    = (const float*)d_in[4];
    const float* b2    = (const float*)d_in[5];
    const float* Wr_h  = (const float*)d_in[6];
    const float* Wi_h  = (const float*)d_in[7];
    const float* Wh_h  = (const float*)d_in[8];
    const float* Wr_in = (const float*)d_in[9];
    const float* br_in = (const float*)d_in[10];
    const float* Wi_in = (const float*)d_in[11];
    const float* bi_in = (const float*)d_in[12];
    const float* Wn_in = (const float*)d_in[13];
    const float* bn_in = (const float*)d_in[14];
    const float* Wo1   = (const float*)d_in[15];
    const float* bo1   = (const float*)d_in[16];
    const float* Wo2   = (const float*)d_in[17];
    const float* bo2   = (const float*)d_in[18];
    const float* Wo3   = (const float*)d_in[19];
    const float* bo3   = (const float*)d_in[20];
    const int* recv_idx = (const int*)d_in[21];
    const int* send_idx = (const int*)d_in[22];
    float* out = (float*)d_out;

    const int UV_SMEM   = (16384 + 8192) * 4;                      // 98304
    const int MSG_SMEM  = (16384 + 8192 + 1024 + 256) * 4 + 64*4;  // 103680
    const int NODE_SMEM = (16384 + 2048*4 + 64) * 4;               // 98560

    cudaFuncSetAttribute(uv_kernel,   cudaFuncAttributeMaxDynamicSharedMemorySize, UV_SMEM);
    cudaFuncSetAttribute(msg_kernel,  cudaFuncAttributeMaxDynamicSharedMemorySize, MSG_SMEM);
    cudaFuncSetAttribute(node_kernel, cudaFuncAttributeMaxDynamicSharedMemorySize, NODE_SMEM);

    init_kernel<<<512, 256>>>();
    for (int s = 0; s < TT + LL; s++) {
        uv_kernel<<<dim3(8, BB), 256, UV_SMEM>>>(W1);
        msg_kernel<<<dim3(NN, BB), 256, MSG_SMEM>>>(W2, b1, b2, rel, recv_idx, send_idx);
        node_kernel<<<dim3(4, BB), 128, NODE_SMEM>>>(data, s,
            Wr_h, Wi_h, Wh_h, Wr_in, br_in, Wi_in, bi_in, Wn_in, bn_in,
            Wo1, bo1, Wo2, bo2, Wo3, bo3, out);
    }
}

// round 3
// speedup vs baseline: 1.0043x; 1.0043x over previous
#include <cuda_runtime.h>
#include <math.h>

#define BB 16
#define NN 64
#define DD 4
#define TT 40
#define LL 10
#define HH 128
#define KK 4
#define EE (NN*(NN-1))   // 4032
#define EPN (NN-1)       // 63 edges per receiver

// ---------------- persistent device state ----------------
__device__ float g_hidden[BB*NN*HH];     // [B,N,H]
__device__ float g_pred[BB*NN*DD];       // [B,N,D] previous prediction
__device__ float g_uv[BB*KK*2*NN*HH];    // [B,K,2,N,H]  u (send part) / v (recv part)
__device__ float g_agg[BB*NN*HH];        // [B,N,H]

// ---------------- f32x2 packed helpers ----------------
__device__ __forceinline__ unsigned long long pk2(float a, float b) {
    unsigned long long r;
    asm("mov.b64 %0, {%1, %2};" : "=l"(r) : "f"(a), "f"(b));
    return r;
}
__device__ __forceinline__ void fma2(unsigned long long& d, unsigned long long a, unsigned long long b) {
    asm("fma.rn.f32x2 %0, %1, %2, %0;" : "+l"(d) : "l"(a), "l"(b));
}
__device__ __forceinline__ float2 upk(unsigned long long a) {
    float2 r;
    asm("mov.b64 {%0, %1}, %2;" : "=f"(r.x), "=f"(r.y) : "l"(a));
    return r;
}

__device__ __forceinline__ float sigmoidf_(float x) { return 1.0f / (1.0f + expf(-x)); }

// ---------------- init ----------------
__global__ void init_kernel() {
    int i = blockIdx.x * blockDim.x + threadIdx.x;
    if (i < BB*NN*HH) g_hidden[i] = 0.0f;
    if (i < BB*NN*DD) g_pred[i]   = 0.0f;
}

// ---------------- UV: u/v = hidden @ W1 halves ----------------
// grid (8, B): blockIdx.x = k*2+s  (s=0: send-half weights, s=1: recv-half), 256 thr
__global__ __launch_bounds__(256)
void uv_kernel(const float* __restrict__ W1) {
    extern __shared__ float sm[];
    float* Ws = sm;            // 128x128
    float* Xs = sm + HH*HH;    // 64x128 hidden rows of this batch
    int ks = blockIdx.x;
    int b  = blockIdx.y;
    // W1 layout [K][2H][H]; slice (k,s) is the contiguous 128x128 block at (k*2+s)*H*H
    const float* Wsrc = W1 + ks * HH * HH;
    for (int idx = threadIdx.x; idx < HH*HH/4; idx += blockDim.x)
        ((float4*)Ws)[idx] = ((const float4*)Wsrc)[idx];
    const float* Hsrc = g_hidden + b*NN*HH;
    for (int idx = threadIdx.x; idx < NN*HH/4; idx += blockDim.x)
        ((float4*)Xs)[idx] = ((const float4*)Hsrc)[idx];
    __syncthreads();

    int h    = threadIdx.x & 127;
    int half = threadIdx.x >> 7;
    float* out = g_uv + (size_t)(b*KK*2 + ks) * NN * HH;
    for (int n = half; n < NN; n += 2) {
        const float* x = Xs + n*HH;
        float acc = 0.0f;
        #pragma unroll
        for (int f4 = 0; f4 < HH; f4 += 4) {
            float4 xv = *(const float4*)(x + f4);
            acc += xv.x * Ws[(f4+0)*HH + h];
            acc += xv.y * Ws[(f4+1)*HH + h];
            acc += xv.z * Ws[(f4+2)*HH + h];
            acc += xv.w * Ws[(f4+3)*HH + h];
        }
        out[n*HH + h] = acc;
    }
}

// ---------------- MSG: fused layer1-assembly + layer2 GEMM + rel_type reduce ----------------
// grid (N, B): one block per (batch, receiver node). 256 threads.
// Exploits np.where structure: edges [i*63, i*63+63) all share recv == i.
__global__ __launch_bounds__(256)
void msg_kernel(const float* __restrict__ W2, const float* __restrict__ b1,
                const float* __restrict__ b2, const float* __restrict__ rel,
                const int* __restrict__ recv_idx, const int* __restrict__ send_idx) {
    extern __shared__ float sm[];
    float* Ws   = sm;                 // 128x128 W2[k]
    float* M1   = Ws + 16384;         // 64x128 (row 63 = zero pad)
    float* Red  = M1 + 8192;          // 8x128 cross-warp reduction
    float* RelS = Red + 1024;         // 64x4
    int*  SendS = (int*)(RelS + 256); // 64

    int i = blockIdx.x, b = blockIdx.y;
    int tid = threadIdx.x;
    int e0 = i * EPN;

    if (tid < 64) {
        if (tid < EPN) {
            SendS[tid] = send_idx[e0 + tid];
            #pragma unroll
            for (int k = 0; k < KK; k++)
                RelS[tid*KK + k] = rel[(size_t)(b*EE + e0 + tid)*KK + k];
        } else {
            SendS[tid] = 0;
            #pragma unroll
            for (int k = 0; k < KK; k++) RelS[tid*KK + k] = 0.0f;
        }
    }
    int ri = recv_idx[e0];

    int hg = tid & 31, eg = tid >> 5;
    int h0 = hg * 4, eb = eg * 8;

    float4 macc[8];
    #pragma unroll
    for (int e = 0; e < 8; e++) macc[e] = make_float4(0.f, 0.f, 0.f, 0.f);

    for (int k = 0; k < KK; k++) {
        __syncthreads();   // protect Ws/M1 (and initial SendS/RelS) before overwrite/use
        // load W2[k]
        const float* Wsrc = W2 + k*HH*HH;
        for (int idx = tid; idx < HH*HH/4; idx += blockDim.x)
            ((float4*)Ws)[idx] = ((const float4*)Wsrc)[idx];
        // build m1 = tanh(u[send] + v[recv] + b1[k])
        const float* u   = g_uv + (size_t)((b*KK + k)*2 + 0) * NN * HH;
        const float* v   = g_uv + (size_t)((b*KK + k)*2 + 1) * NN * HH + (size_t)ri * HH;
        const float* b1k = b1 + k*HH;
        for (int idx = tid; idx < 64*HH; idx += 256) {
            int e = idx >> 7, h = idx & 127;
            float val = 0.0f;
            if (e < EPN) {
                int sn = SendS[e];
                val = tanhf(u[sn*HH + h] + v[h] + b1k[h]);
            }
            M1[idx] = val;
        }
        __syncthreads();

        // layer-2 GEMM: acc[e][h] = sum_f m1[e][f] * W2[k][f][h]  (f32x2 packed)
        unsigned long long acc01[8], acc23[8];
        #pragma unroll
        for (int e = 0; e < 8; e++) { acc01[e] = 0ull; acc23[e] = 0ull; }

        for (int f4 = 0; f4 < HH/4; f4++) {
            int f = f4 * 4;
            float4 w0 = *(const float4*)&Ws[(f+0)*HH + h0];
            float4 w1 = *(const float4*)&Ws[(f+1)*HH + h0];
            float4 w2 = *(const float4*)&Ws[(f+2)*HH + h0];
            float4 w3 = *(const float4*)&Ws[(f+3)*HH + h0];
            unsigned long long w0a = pk2(w0.x, w0.y), w0b = pk2(w0.z, w0.w);
            unsigned long long w1a = pk2(w1.x, w1.y), w1b = pk2(w1.z, w1.w);
            unsigned long long w2a = pk2(w2.x, w2.y), w2b = pk2(w2.z, w2.w);
            unsigned long long w3a = pk2(w3.x, w3.y), w3b = pk2(w3.z, w3.w);
            #pragma unroll
            for (int e = 0; e < 8; e++) {
                float4 a = *(const float4*)&M1[(eb+e)*HH + f];
                unsigned long long a0 = pk2(a.x, a.x);
                unsigned long long a1 = pk2(a.y, a.y);
                unsigned long long a2 = pk2(a.z, a.z);
                unsigned long long a3 = pk2(a.w, a.w);
                fma2(acc01[e], a0, w0a); fma2(acc23[e], a0, w0b);
                fma2(acc01[e], a1, w1a); fma2(acc23[e], a1, w1b);
                fma2(acc01[e], a2, w2a); fma2(acc23[e], a2, w2b);
                fma2(acc01[e], a3, w3a); fma2(acc23[e], a3, w3b);
            }
        }
        // m2 = tanh(acc + b2[k]); weighted by rel_type, accumulate over k
        const float* b2k = b2 + k*HH;
        float bb0 = b2k[h0+0], bb1 = b2k[h0+1], bb2 = b2k[h0+2], bb3 = b2k[h0+3];
        #pragma unroll
        for (int e = 0; e < 8; e++) {
            float relw = RelS[(eb+e)*KK + k];
            float2 p0 = upk(acc01[e]);
            float2 p1 = upk(acc23[e]);
            macc[e].x += relw * tanhf(p0.x + bb0);
            macc[e].y += relw * tanhf(p0.y + bb1);
            macc[e].z += relw * tanhf(p1.x + bb2);
            macc[e].w += relw * tanhf(p1.y + bb3);
        }
    }

    // segment sum over the 63 edges of this receiver (8 per thread, then 8 warps)
    float4 s = macc[0];
    #pragma unroll
    for (int e = 1; e < 8; e++) { s.x += macc[e].x; s.y += macc[e].y; s.z += macc[e].z; s.w += macc[e].w; }
    *(float4*)&Red[eg*HH + h0] = s;
    __syncthreads();
    if (tid < HH) {
        float acc = 0.0f;
        #pragma unroll
        for (int w = 0; w < 8; w++) acc += Red[w*HH + tid];
        g_agg[(size_t)(b*NN + ri)*HH + tid] = acc * (1.0f / (KK * DD));
    }
}

// ---------------- NODE: GRU cell + output MLP ----------------
// grid (4, B): 16 nodes per block, 128 threads (thread = h)
__global__ __launch_bounds__(128)
void node_kernel(const float* __restrict__ data, int step,
                 const float* __restrict__ Wr_h, const float* __restrict__ Wi_h,
                 const float* __restrict__ Wh_h,
                 const float* __restrict__ Wr_in, const float* __restrict__ br_in,
                 const float* __restrict__ Wi_in, const float* __restrict__ bi_in,
                 const float* __restrict__ Wn_in, const float* __restrict__ bn_in,
                 const float* __restrict__ Wo1, const float* __restrict__ bo1,
                 const float* __restrict__ Wo2, const float* __restrict__ bo2,
                 const float* __restrict__ Wo3, const float* __restrict__ bo3,
                 float* __restrict__ out) {
    extern __shared__ float sm[];
    float* Wb   = sm;            // 128x128
    float* aggS = Wb + 16384;    // 16x128
    float* hidS = aggS + 2048;   // 16x128
    float* t1   = hidS + 2048;   // 16x128
    float* t2   = t1 + 2048;     // 16x128
    float* insS = t2 + 2048;     // 16x4

    int q = blockIdx.x, b = blockIdx.y;
    int n0 = q * 16;
    int tid = threadIdx.x;       // 0..127
    int h = tid;

    const float* ag = g_agg    + (size_t)(b*NN + n0) * HH;
    const float* hg = g_hidden + (size_t)(b*NN + n0) * HH;
    for (int idx = tid; idx < 2048/4; idx += 128) {
        ((float4*)aggS)[idx] = ((const float4*)ag)[idx];
        ((float4*)hidS)[idx] = ((const float4*)hg)[idx];
    }
    if (tid < 64) {
        int n = tid >> 2, d = tid & 3;
        float v;
        if (step < TT) v = data[(size_t)((b*NN + n0 + n)*DD + d)*TT + step];
        else           v = g_pred[(b*NN + n0 + n)*DD + d];
        insS[tid] = v;
    }

    // ---- P1: r = sigmoid(ins@Wr_in + br_in + agg@Wr_h) ----
    for (int idx = tid; idx < HH*HH/4; idx += 128)
        ((float4*)Wb)[idx] = ((const float4*)Wr_h)[idx];
    __syncthreads();
    for (int n = 0; n < 16; n++) {
        float acc = br_in[h];
        #pragma unroll
        for (int d = 0; d < 4; d++) acc += insS[n*4+d] * Wr_in[d*HH + h];
        const float* vv = aggS + n*HH;
        #pragma unroll 8
        for (int f4 = 0; f4 < HH/4; f4++) {
            float4 x = ((const float4*)vv)[f4];
            acc += x.x * Wb[(f4*4+0)*HH + h] + x.y * Wb[(f4*4+1)*HH + h]
                 + x.z * Wb[(f4*4+2)*HH + h] + x.w * Wb[(f4*4+3)*HH + h];
        }
        t1[n*HH + h] = sigmoidf_(acc);
    }
    __syncthreads();

    // ---- P2: i = sigmoid(ins@Wi_in + bi_in + agg@Wi_h) ----
    for (int idx = tid; idx < HH*HH/4; idx += 128)
        ((float4*)Wb)[idx] = ((const float4*)Wi_h)[idx];
    __syncthreads();
    for (int n = 0; n < 16; n++) {
        float acc = bi_in[h];
        #pragma unroll
        for (int d = 0; d < 4; d++) acc += insS[n*4+d] * Wi_in[d*HH + h];
        const float* vv = aggS + n*HH;
        #pragma unroll 8
        for (int f4 = 0; f4 < HH/4; f4++) {
            float4 x = ((const float4*)vv)[f4];
            acc += x.x * Wb[(f4*4+0)*HH + h] + x.y * Wb[(f4*4+1)*HH + h]
                 + x.z * Wb[(f4*4+2)*HH + h] + x.w * Wb[(f4*4+3)*HH + h];
        }
        t2[n*HH + h] = sigmoidf_(acc);
    }
    __syncthreads();

    // ---- P3: n = tanh(ins@Wn_in + bn_in + r*(agg@Wh_h)); hidden update ----
    for (int idx = tid; idx < HH*HH/4; idx += 128)
        ((float4*)Wb)[idx] = ((const float4*)Wh_h)[idx];
    __syncthreads();
    for (int n = 0; n < 16; n++) {
        float accin = bn_in[h];
        #pragma unroll
        for (int d = 0; d < 4; d++) accin += insS[n*4+d] * Wn_in[d*HH + h];
        float aggdot = 0.0f;
        const float* vv = aggS + n*HH;
        #pragma unroll 8
        for (int f4 = 0; f4 < HH/4; f4++) {
            float4 x = ((const float4*)vv)[f4];
            aggdot += x.x * Wb[(f4*4+0)*HH + h] + x.y * Wb[(f4*4+1)*HH + h]
                    + x.z * Wb[(f4*4+2)*HH + h] + x.w * Wb[(f4*4+3)*HH + h];
        }
        float r  = t1[n*HH + h];
        float ii = t2[n*HH + h];
        float nn = tanhf(accin + r * aggdot);
        float oldh = hidS[n*HH + h];
        float nh = (1.0f - ii) * nn + ii * oldh;
        hidS[n*HH + h] = nh;
        g_hidden[(size_t)(b*NN + n0 + n)*HH + h] = nh;
    }
    __syncthreads();

    // ---- P4: y1 = relu(hidden@Wo1 + bo1) ----
    for (int idx = tid; idx < HH*HH/4; idx += 128)
        ((float4*)Wb)[idx] = ((const float4*)Wo1)[idx];
    __syncthreads();
    for (int n = 0; n < 16; n++) {
        float acc = bo1[h];
        const float* vv = hidS + n*HH;
        #pragma unroll 8
        for (int f4 = 0; f4 < HH/4; f4++) {
            float4 x = ((const float4*)vv)[f4];
            acc += x.x * Wb[(f4*4+0)*HH + h] + x.y * Wb[(f4*4+1)*HH + h]
                 + x.z * Wb[(f4*4+2)*HH + h] + x.w * Wb[(f4*4+3)*HH + h];
        }
        t1[n*HH + h] = fmaxf(acc, 0.0f);
    }
    __syncthreads();

    // ---- P5: y2 = relu(y1@Wo2 + bo2) ----
    for (int idx = tid; idx < HH*HH/4; idx += 128)
        ((float4*)Wb)[idx] = ((const float4*)Wo2)[idx];
    __syncthreads();
    for (int n = 0; n < 16; n++) {
        float acc = bo2[h];
        const float* vv = t1 + n*HH;
        #pragma unroll 8
        for (int f4 = 0; f4 < HH/4; f4++) {
            float4 x = ((const float4*)vv)[f4];
            acc += x.x * Wb[(f4*4+0)*HH + h] + x.y * Wb[(f4*4+1)*HH + h]
                 + x.z * Wb[(f4*4+2)*HH + h] + x.w * Wb[(f4*4+3)*HH + h];
        }
        t2[n*HH + h] = fmaxf(acc, 0.0f);
    }
    __syncthreads();

    // ---- P6: pred = ins + y2@Wo3 + bo3 ----
    if (tid < 64) {
        int n = tid >> 2, d = tid & 3;
        float acc = bo3[d];
        const float* vv = t2 + n*HH;
        #pragma unroll 4
        for (int hh = 0; hh < HH; hh++) acc += vv[hh] * Wo3[hh*DD + d];
        float pred = insS[tid] + acc;
        g_pred[(b*NN + n0 + n)*DD + d] = pred;
        if (step >= TT)
            out[(size_t)((b*NN + n0 + n)*DD + d)*LL + (step - TT)] = pred;
    }
}

// ---------------- launch ----------------
extern "C" void kernel_launch(void* const* d_in, const int* in_sizes, int n_in,
                              void* d_out, int out_size) {
    const float* data  = (const float*)d_in[0];
    const float* rel   = (const float*)d_in[1];
    const float* W1    = (const float*)d_in[2];
    const float* b1    = (const float*)d_in[3];
    const float* W2    = (const float*)d_in[4];
    const float* b2    = (const float*)d_in[5];
    const float* Wr_h  = (const float*)d_in[6];
    const float* Wi_h  = (const float*)d_in[7];
    const float* Wh_h  = (const float*)d_in[8];
    const float* Wr_in = (const float*)d_in[9];
    const float* br_in = (const float*)d_in[10];
    const float* Wi_in = (const float*)d_in[11];
    const float* bi_in = (const float*)d_in[12];
    const float* Wn_in = (const float*)d_in[13];
    const float* bn_in = (const float*)d_in[14];
    const float* Wo1   = (const float*)d_in[15];
    const float* bo1   = (const float*)d_in[16];
    const float* Wo2   = (const float*)d_in[17];
    const float* bo2   = (const float*)d_in[18];
    const float* Wo3   = (const float*)d_in[19];
    const float* bo3   = (const float*)d_in[20];
    const int* recv_idx = (const int*)d_in[21];
    const int* send_idx = (const int*)d_in[22];
    float* out = (float*)d_out;

    const int UV_SMEM   = (16384 + 8192) * 4;                      // 98304
    const int MSG_SMEM  = (16384 + 8192 + 1024 + 256) * 4 + 64*4;  // 103680
    const int NODE_SMEM = (16384 + 2048*4 + 64) * 4;               // 98560

    cudaFuncSetAttribute(uv_kernel,   cudaFuncAttributeMaxDynamicSharedMemorySize, UV_SMEM);
    cudaFuncSetAttribute(msg_kernel,  cudaFuncAttributeMaxDynamicSharedMemorySize, MSG_SMEM);
    cudaFuncSetAttribute(node_kernel, cudaFuncAttributeMaxDynamicSharedMemorySize, NODE_SMEM);

    init_kernel<<<512, 256>>>();
    for (int s = 0; s < TT + LL; s++) {
        uv_kernel<<<dim3(8, BB), 256, UV_SMEM>>>(W1);
        msg_kernel<<<dim3(NN, BB), 256, MSG_SMEM>>>(W2, b1, b2, rel, recv_idx, send_idx);
        node_kernel<<<dim3(4, BB), 128, NODE_SMEM>>>(data, s,
            Wr_h, Wi_h, Wh_h, Wr_in, br_in, Wi_in, bi_in, Wn_in, bn_in,
            Wo1, bo1, Wo2, bo2, Wo3, bo3, out);
    }
}

// round 6
// speedup vs baseline: 1.3586x; 1.3528x over previous
#include <cuda_runtime.h>
#include <cuda_bf16.h>
#include <stdint.h>
#include <math.h>

#define BB 16
#define NN 64
#define DD 4
#define TT 40
#define LL 10
#define HH 128
#define KK 4
#define EE (NN*(NN-1))

// padded bf16 tile: 128 rows x 136 cols (272 B/row) -> conflict-free fragment LDS
#define SP   136
#define SPB  272
#define TILE_B (128*SPB)          // 34816 bytes per (hi or lo) tile
#define TILE2_B (2*TILE_B)        // 69632 bytes hi+lo

// ---------------- persistent device state ----------------
__device__ float g_hidden[BB*NN*HH];
__device__ float g_pred[BB*NN*DD];
__device__ float g_uv[BB*8*NN*HH];      // [B][ks][N][H]
__device__ float g_agg[BB*NN*HH];
__device__ __align__(16) __nv_bfloat16 g_W1T[8*2*128*SP]; // [ks][hi|lo][128][136]
__device__ __align__(16) __nv_bfloat16 g_W2T[4*2*128*SP]; // [k][hi|lo][128][136]

// ---------------- PTX helpers ----------------
__device__ __forceinline__ uint32_t smem_u32(const void* p) {
    uint32_t a;
    asm("{ .reg .u64 t; cvta.to.shared.u64 t, %1; cvt.u32.u64 %0, t; }" : "=r"(a) : "l"(p));
    return a;
}
#define MBAR_INIT(mb, c)  asm volatile("mbarrier.init.shared.b64 [%0], %1;" :: "r"(mb), "r"(c) : "memory")
#define MBAR_EXPECT_TX(mb, n) asm volatile("mbarrier.arrive.expect_tx.shared.b64 _, [%0], %1;" :: "r"(mb), "r"(n) : "memory")
#define FENCE_ASYNC()     asm volatile("fence.proxy.async.shared::cta;" ::: "memory")
#define BULK_CP(dst, src, bytes, mb) \
    asm volatile("cp.async.bulk.shared::cta.global.mbarrier::complete_tx::bytes [%0], [%1], %2, [%3];" \
        :: "r"(dst), "l"(src), "r"(bytes), "r"(mb) : "memory")

#define MBAR_WAIT(mb, ph) do { \
    uint32_t _m = (mb); uint32_t _p = (ph); uint32_t _d; \
    asm volatile("{\n\t.reg .pred p;\n\tmbarrier.try_wait.parity.acquire.cta.shared::cta.b64 p, [%1], %2;\n\tselp.b32 %0, 1, 0, p;\n\t}" \
        : "=r"(_d) : "r"(_m), "r"(_p) : "memory"); \
    if (!_d) { \
        asm volatile("{\n\t.reg .pred P1;\n\tWL_%=:\n\tmbarrier.try_wait.parity.acquire.cta.shared::cta.b64 P1, [%0], %1, 0x989680;\n\t@P1 bra.uni WD_%=;\n\tbra.uni WL_%=;\n\tWD_%=:\n\t}" \
            :: "r"(_m), "r"(_p) : "memory"); \
    } \
} while (0)

// bf16 mma: D(16x8,f32) += A(16x16,row) * B(16x8,col)
__device__ __forceinline__ void mma_bf16(float d[4], uint32_t a0, uint32_t a1, uint32_t a2, uint32_t a3,
                                         uint32_t b0, uint32_t b1) {
    asm volatile("mma.sync.aligned.m16n8k16.row.col.f32.bf16.bf16.f32 "
        "{%0,%1,%2,%3}, {%4,%5,%6,%7}, {%8,%9}, {%0,%1,%2,%3};"
        : "+f"(d[0]), "+f"(d[1]), "+f"(d[2]), "+f"(d[3])
        : "r"(a0), "r"(a1), "r"(a2), "r"(a3), "r"(b0), "r"(b1));
}

// 128x128x128 GEMM, 3 split-bf16 combos (AhBh + AhBl + AlBh), warp tile 32(m) x 64(n)
__device__ __forceinline__ void gemm_tile(const char* Ah, const char* Al,
                                          const char* Bh, const char* Bl,
                                          float acc[2][8][4], int mblk, int nblk, int lane) {
    int gid = lane >> 2, tig = lane & 3;
    int arow = mblk * 32 + gid;
    int brow = nblk * 64 + gid;
    #pragma unroll
    for (int combo = 0; combo < 3; combo++) {
        const char* A = (combo == 2) ? Al : Ah;
        const char* B = (combo == 1) ? Bl : Bh;
        const char* ap0 = A + arow * SPB + tig * 4;
        const char* bp0 = B + brow * SPB + tig * 4;
        #pragma unroll
        for (int ks = 0; ks < 8; ks++) {
            int kb = ks * 32;
            uint32_t a[2][4];
            #pragma unroll
            for (int mf = 0; mf < 2; mf++) {
                const char* ap = ap0 + mf * 16 * SPB + kb;
                a[mf][0] = *(const uint32_t*)ap;
                a[mf][1] = *(const uint32_t*)(ap + 8 * SPB);
                a[mf][2] = *(const uint32_t*)(ap + 16);
                a[mf][3] = *(const uint32_t*)(ap + 8 * SPB + 16);
            }
            #pragma unroll
            for (int nf = 0; nf < 8; nf++) {
                const char* bp = bp0 + nf * 8 * SPB + kb;
                uint32_t b0 = *(const uint32_t*)bp;
                uint32_t b1 = *(const uint32_t*)(bp + 16);
                mma_bf16(acc[0][nf], a[0][0], a[0][1], a[0][2], a[0][3], b0, b1);
                mma_bf16(acc[1][nf], a[1][0], a[1][1], a[1][2], a[1][3], b0, b1);
            }
        }
    }
}

// ---------------- fast math ----------------
__device__ __forceinline__ float fex2_(float x) { float r; asm("ex2.approx.f32 %0, %1;" : "=f"(r) : "f"(x)); return r; }
__device__ __forceinline__ float frcp_(float x) { float r; asm("rcp.approx.f32 %0, %1;" : "=f"(r) : "f"(x)); return r; }
__device__ __forceinline__ float ftanh_(float x) { return fmaf(-2.0f, frcp_(fex2_(x * 2.885390081777927f) + 1.0f), 1.0f); }
__device__ __forceinline__ float fsig_(float x)  { return frcp_(1.0f + fex2_(-1.4426950408889634f * x)); }

// ---------------- init ----------------
__global__ void init_kernel() {
    int i = blockIdx.x * blockDim.x + threadIdx.x;
    if (i < BB*NN*HH) g_hidden[i] = 0.0f;
    if (i < BB*NN*DD) g_pred[i]   = 0.0f;
}

// ---------------- prep: transposed split-bf16 padded tiles ----------------
// grid 12: 0..7 -> W1 slice ks; 8..11 -> W2 slice k.  T[n][f] = W[f][n]
__global__ __launch_bounds__(256)
void prep_kernel(const float* __restrict__ W1, const float* __restrict__ W2) {
    int s = blockIdx.x;
    const float* src = (s < 8) ? (W1 + s * 16384) : (W2 + (s - 8) * 16384);
    __nv_bfloat16* dhi = (s < 8) ? (g_W1T + s * 2 * 128 * SP) : (g_W2T + (s - 8) * 2 * 128 * SP);
    __nv_bfloat16* dlo = dhi + 128 * SP;
    for (int t = threadIdx.x; t < 16384; t += 256) {
        int n = t >> 7, f = t & 127;
        float v = src[f * 128 + n];
        __nv_bfloat16 hi = __float2bfloat16_rn(v);
        __nv_bfloat16 lo = __float2bfloat16_rn(v - __bfloat162float(hi));
        dhi[n * SP + f] = hi;
        dlo[n * SP + f] = lo;
    }
}

// ---------------- UV: u/v = hidden @ W1T[ks] ----------------
#define UV_AH 0
#define UV_AL TILE_B
#define UV_B  TILE2_B            /* 69632: hi+lo */
#define UV_MB (TILE2_B + TILE2_B) /* 139264 */
#define UV_SMEM (UV_MB + 32)

__global__ __launch_bounds__(256)
void uv_kernel() {
    extern __shared__ char sm[];
    uint32_t smb = smem_u32(sm);
    int tid = threadIdx.x;
    int ks = blockIdx.x, bp = blockIdx.y;
    uint32_t mbt = smb + UV_MB;

    if (tid == 0) {
        MBAR_INIT(mbt, 1);
        FENCE_ASYNC();
        MBAR_EXPECT_TX(mbt, TILE2_B);
        BULK_CP(smb + UV_B, (const char*)g_W1T + (size_t)ks * TILE2_B, TILE2_B, mbt);
    }
    // A: rows 0-63 = batch 2bp, rows 64-127 = batch 2bp+1 ; split bf16 hi/lo
    for (int idx = tid; idx < 128 * 64; idx += 256) {
        int row = idx >> 6, fp = (idx & 63) * 2;
        int b = bp * 2 + (row >> 6);
        int node = row & 63;
        float2 hv = *(const float2*)(g_hidden + ((size_t)(b * NN + node)) * HH + fp);
        __nv_bfloat16 h0 = __float2bfloat16_rn(hv.x);
        __nv_bfloat16 h1 = __float2bfloat16_rn(hv.y);
        __nv_bfloat16 l0 = __float2bfloat16_rn(hv.x - __bfloat162float(h0));
        __nv_bfloat16 l1 = __float2bfloat16_rn(hv.y - __bfloat162float(h1));
        int off = row * SPB + fp * 2;
        __nv_bfloat162 ph; ph.x = h0; ph.y = h1;
        __nv_bfloat162 pl; pl.x = l0; pl.y = l1;
        *(__nv_bfloat162*)(sm + UV_AH + off) = ph;
        *(__nv_bfloat162*)(sm + UV_AL + off) = pl;
    }
    __syncthreads();
    MBAR_WAIT(mbt, 0);

    int w = tid >> 5, lane = tid & 31;
    int mblk = w & 3, nblk = w >> 2;
    int gid = lane >> 2, tig = lane & 3;

    float acc[2][8][4];
    #pragma unroll
    for (int mf = 0; mf < 2; mf++)
        #pragma unroll
        for (int nf = 0; nf < 8; nf++)
            #pragma unroll
            for (int j = 0; j < 4; j++) acc[mf][nf][j] = 0.0f;

    gemm_tile(sm + UV_AH, sm + UV_AL, sm + UV_B, sm + UV_B + TILE_B, acc, mblk, nblk, lane);
    __syncthreads();   // done reading A; reuse AH+AL as fp32 staging (128 x 132)

    float* Msm = (float*)(sm + UV_AH);
    #pragma unroll
    for (int mf = 0; mf < 2; mf++) {
        int r0 = mblk * 32 + mf * 16 + gid;
        #pragma unroll
        for (int nf = 0; nf < 8; nf++) {
            int c = nblk * 64 + nf * 8 + tig * 2;
            *(float2*)&Msm[r0 * 132 + c]       = make_float2(acc[mf][nf][0], acc[mf][nf][1]);
            *(float2*)&Msm[(r0 + 8) * 132 + c] = make_float2(acc[mf][nf][2], acc[mf][nf][3]);
        }
    }
    __syncthreads();
    for (int idx = tid; idx < 128 * 32; idx += 256) {
        int row = idx >> 5, c4 = (idx & 31) * 4;
        float4 v = *(const float4*)&Msm[row * 132 + c4];
        int b = bp * 2 + (row >> 6), node = row & 63;
        *(float4*)(g_uv + (((size_t)(b * 8 + ks)) * 64 + node) * 128 + c4) = v;
    }
}

// ---------------- MSG kernel ----------------
#define MS_AH 0
#define MS_AL TILE_B
#define MS_B0 TILE2_B              /* 69632  */
#define MS_B1 (TILE2_B + TILE2_B)  /* 139264 */
#define MS_MS TILE2_B              /* staging reuses B0 after GEMMs */
#define MS_REL  208896
#define MS_SEND 210944
#define MS_B1S  211456
#define MS_B2S  213504
#define MS_VS   215552
#define MS_MB   216576
#define MSG_SMEM 216608

__global__ __launch_bounds__(256)
void msg_kernel(const float* __restrict__ b1, const float* __restrict__ b2,
                const float* __restrict__ rel,
                const int* __restrict__ recv_idx, const int* __restrict__ send_idx) {
    extern __shared__ char sm[];
    uint32_t smb = smem_u32(sm);
    int tid = threadIdx.x;
    int p = blockIdx.x, b = blockIdx.y;

    float* RelS  = (float*)(sm + MS_REL);
    int*   SendS = (int*)(sm + MS_SEND);
    float* b1S   = (float*)(sm + MS_B1S);
    float* b2S   = (float*)(sm + MS_B2S);
    float* vS    = (float*)(sm + MS_VS);
    uint32_t mb_t0 = smb + MS_MB, mb_t1 = smb + MS_MB + 8;

    if (tid == 0) {
        MBAR_INIT(mb_t0, 1);
        MBAR_INIT(mb_t1, 1);
        FENCE_ASYNC();
        MBAR_EXPECT_TX(mb_t0, TILE2_B);
        BULK_CP(smb + MS_B0, (const char*)g_W2T + 0 * TILE2_B, TILE2_B, mb_t0);
        MBAR_EXPECT_TX(mb_t1, TILE2_B);
        BULK_CP(smb + MS_B1, (const char*)g_W2T + 1 * TILE2_B, TILE2_B, mb_t1);
    }
    if (tid < 128) {
        int row = tid;
        float r0 = 0, r1 = 0, r2 = 0, r3 = 0;
        int sn = 0;
        if (row != 63 && row != 127) {
            int e = (row < 64) ? (p * 126 + row) : (p * 126 + row - 1);
            sn = send_idx[e];
            const float* rp = rel + ((size_t)(b * EE + e)) * KK;
            r0 = rp[0]; r1 = rp[1]; r2 = rp[2]; r3 = rp[3];
        }
        SendS[row] = sn;
        RelS[row * 4 + 0] = r0; RelS[row * 4 + 1] = r1;
        RelS[row * 4 + 2] = r2; RelS[row * 4 + 3] = r3;
        #pragma unroll
        for (int k = 0; k < 4; k++) {
            b1S[k * 128 + tid] = b1[k * 128 + tid];
            b2S[k * 128 + tid] = b2[k * 128 + tid];
        }
    }
    int r0n = recv_idx[p * 126];
    int r1n = recv_idx[p * 126 + 63];
    __syncthreads();

    int w = tid >> 5, lane = tid & 31;
    int mblk = w & 3, nblk = w >> 2;
    int gid = lane >> 2, tig = lane & 3;

    float macc[2][8][4];
    #pragma unroll
    for (int mf = 0; mf < 2; mf++)
        #pragma unroll
        for (int nf = 0; nf < 8; nf++)
            #pragma unroll
            for (int j = 0; j < 4; j++) macc[mf][nf][j] = 0.0f;

    for (int k = 0; k < 4; k++) {
        // stage v[recv] + b1 for the two receivers of this block
        {
            int f = tid & 127, rh = tid >> 7;
            int rv = rh ? r1n : r0n;
            const float* v = g_uv + ((size_t)(b * 8 + 2 * k + 1)) * NN * HH;
            vS[rh * 128 + f] = v[rv * 128 + f] + b1S[k * 128 + f];
        }
        __syncthreads();
        // A = tanh(u[send] + vS), split bf16 hi/lo; rows 63/127 zero-padded
        const float* u = g_uv + ((size_t)(b * 8 + 2 * k)) * NN * HH;
        for (int idx = tid; idx < 128 * 64; idx += 256) {
            int row = idx >> 6, fp = (idx & 63) * 2;
            float val0 = 0.0f, val1 = 0.0f;
            if (row != 63 && row != 127) {
                int sn = SendS[row];
                int rh = row >> 6;
                float2 uu = *(const float2*)(u + sn * 128 + fp);
                val0 = ftanh_(uu.x + vS[rh * 128 + fp]);
                val1 = ftanh_(uu.y + vS[rh * 128 + fp + 1]);
            }
            __nv_bfloat16 h0 = __float2bfloat16_rn(val0);
            __nv_bfloat16 h1 = __float2bfloat16_rn(val1);
            __nv_bfloat16 l0 = __float2bfloat16_rn(val0 - __bfloat162float(h0));
            __nv_bfloat16 l1 = __float2bfloat16_rn(val1 - __bfloat162float(h1));
            int off = row * SPB + fp * 2;
            __nv_bfloat162 ph; ph.x = h0; ph.y = h1;
            __nv_bfloat162 pl; pl.x = l0; pl.y = l1;
            *(__nv_bfloat162*)(sm + MS_AH + off) = ph;
            *(__nv_bfloat162*)(sm + MS_AL + off) = pl;
        }
        __syncthreads();

        uint32_t mbt = (k & 1) ? mb_t1 : mb_t0;
        MBAR_WAIT(mbt, (k >> 1) & 1);
        const char* Bb = sm + ((k & 1) ? MS_B1 : MS_B0);

        float acc[2][8][4];
        #pragma unroll
        for (int mf = 0; mf < 2; mf++)
            #pragma unroll
            for (int nf = 0; nf < 8; nf++)
                #pragma unroll
                for (int j = 0; j < 4; j++) acc[mf][nf][j] = 0.0f;

        gemm_tile(sm + MS_AH, sm + MS_AL, Bb, Bb + TILE_B, acc, mblk, nblk, lane);

        // epilogue: m2 = tanh(acc + b2); weighted by rel_type; accumulate over k
        #pragma unroll
        for (int mf = 0; mf < 2; mf++) {
            int r0 = mblk * 32 + mf * 16 + gid;
            float relw0 = RelS[r0 * 4 + k];
            float relw1 = RelS[(r0 + 8) * 4 + k];
            #pragma unroll
            for (int nf = 0; nf < 8; nf++) {
                int c = nblk * 64 + nf * 8 + tig * 2;
                float bb0 = b2S[k * 128 + c], bb1 = b2S[k * 128 + c + 1];
                macc[mf][nf][0] += relw0 * ftanh_(acc[mf][nf][0] + bb0);
                macc[mf][nf][1] += relw0 * ftanh_(acc[mf][nf][1] + bb1);
                macc[mf][nf][2] += relw1 * ftanh_(acc[mf][nf][2] + bb0);
                macc[mf][nf][3] += relw1 * ftanh_(acc[mf][nf][3] + bb1);
            }
        }
        __syncthreads();   // all warps done reading A and B[kbuf]
        if (tid == 0 && k + 2 <= 3) {
            uint32_t mbn = ((k + 2) & 1) ? mb_t1 : mb_t0;
            uint32_t dst = ((k + 2) & 1) ? (smb + MS_B1) : (smb + MS_B0);
            MBAR_EXPECT_TX(mbn, TILE2_B);
            BULK_CP(dst, (const char*)g_W2T + (size_t)(k + 2) * TILE2_B, TILE2_B, mbn);
        }
    }

    // stage fragments to SMEM (stride 132), then segment-sum 63 edges per receiver
    float* Msm = (float*)(sm + MS_MS);
    #pragma unroll
    for (int mf = 0; mf < 2; mf++) {
        int r0 = mblk * 32 + mf * 16 + gid;
        #pragma unroll
        for (int nf = 0; nf < 8; nf++) {
            int c = nblk * 64 + nf * 8 + tig * 2;
            *(float2*)&Msm[r0 * 132 + c]       = make_float2(macc[mf][nf][0], macc[mf][nf][1]);
            *(float2*)&Msm[(r0 + 8) * 132 + c] = make_float2(macc[mf][nf][2], macc[mf][nf][3]);
        }
    }
    __syncthreads();
    {
        int h = tid & 127, rh = tid >> 7;
        const float* src = Msm + (rh * 64) * 132 + h;
        float acc = 0.0f;
        #pragma unroll 9
        for (int r = 0; r < 63; r++) acc += src[r * 132];
        int rv = rh ? r1n : r0n;
        g_agg[((size_t)(b * NN + rv)) * HH + h] = acc * (1.0f / 16.0f);
    }
}

// ---------------- NODE kernel: GRU + output MLP ----------------
#define ND_WB0 0
#define ND_WB1 65536
#define ND_AGG 131072
#define ND_HID 135168
#define ND_T1  139264
#define ND_T2  143360
#define ND_INS 147456
#define ND_WIN 147712
#define ND_BIA 153856
#define ND_WO3 156416
#define ND_BO3 158464
#define ND_MB  158480
#define NODE_SMEM 158592

__global__ __launch_bounds__(256)
void node_kernel(const float* __restrict__ data, int step,
                 const float* __restrict__ Wr_h, const float* __restrict__ Wi_h,
                 const float* __restrict__ Wh_h,
                 const float* __restrict__ Wr_in, const float* __restrict__ br_in,
                 const float* __restrict__ Wi_in, const float* __restrict__ bi_in,
                 const float* __restrict__ Wn_in, const float* __restrict__ bn_in,
                 const float* __restrict__ Wo1, const float* __restrict__ bo1,
                 const float* __restrict__ Wo2, const float* __restrict__ bo2,
                 const float* __restrict__ Wo3, const float* __restrict__ bo3,
                 float* __restrict__ out) {
    extern __shared__ char sm[];
    uint32_t smb = smem_u32(sm);
    int q = blockIdx.x, b = blockIdx.y;
    int n0 = q * 8;
    int tid = threadIdx.x;

    float* aggS = (float*)(sm + ND_AGG);
    float* hidS = (float*)(sm + ND_HID);
    float* t1   = (float*)(sm + ND_T1);
    float* t2   = (float*)(sm + ND_T2);
    float* insS = (float*)(sm + ND_INS);
    float* WinS = (float*)(sm + ND_WIN);
    float* biaS = (float*)(sm + ND_BIA);
    float* Wo3S = (float*)(sm + ND_WO3);
    float* bo3S = (float*)(sm + ND_BO3);
    uint32_t mb0 = smb + ND_MB, mb1 = smb + ND_MB + 8;

    if (tid == 0) {
        MBAR_INIT(mb0, 1);
        MBAR_INIT(mb1, 1);
        FENCE_ASYNC();
        MBAR_EXPECT_TX(mb0, 65536);
        BULK_CP(smb + ND_WB0, (const void*)Wr_h, 65536, mb0);
        MBAR_EXPECT_TX(mb1, 65536);
        BULK_CP(smb + ND_WB1, (const void*)Wi_h, 65536, mb1);
    }
    {
        const float* ag = g_agg    + ((size_t)(b * NN + n0)) * HH;
        const float* hg = g_hidden + ((size_t)(b * NN + n0)) * HH;
        ((float4*)aggS)[tid] = ((const float4*)ag)[tid];
        ((float4*)hidS)[tid] = ((const float4*)hg)[tid];
    }
    if (tid < 32) {
        int n = tid >> 2, d = tid & 3;
        float v;
        if (step < TT) v = data[(((size_t)(b * NN + n0 + n)) * DD + d) * TT + step];
        else           v = g_pred[(b * NN + n0 + n) * DD + d];
        insS[tid] = v;
    }
    for (int i = tid; i < 512; i += 256) {
        WinS[i]        = Wr_in[i];
        WinS[512 + i]  = Wi_in[i];
        WinS[1024 + i] = Wn_in[i];
        Wo3S[i]        = Wo3[i];
    }
    if (tid < 128) {
        biaS[tid]       = br_in[tid];
        biaS[128 + tid] = bi_in[tid];
        biaS[256 + tid] = bn_in[tid];
        biaS[384 + tid] = bo1[tid];
        biaS[512 + tid] = bo2[tid];
    }
    if (tid < 4) bo3S[tid] = bo3[tid];
    __syncthreads();

    int h = tid & 127, ng = (tid >> 7) * 4;

    #define GEMV4(ACT, WB, OUTARR) do { \
        const float* _wb = (WB); \
        _Pragma("unroll") \
        for (int nn = 0; nn < 4; nn++) { \
            const float* av = (ACT) + (ng + nn) * 128; \
            float a = 0.0f; \
            _Pragma("unroll 8") \
            for (int f4 = 0; f4 < 32; f4++) { \
                float4 x = ((const float4*)av)[f4]; \
                a += x.x * _wb[(f4*4+0)*128 + h] + x.y * _wb[(f4*4+1)*128 + h] \
                   + x.z * _wb[(f4*4+2)*128 + h] + x.w * _wb[(f4*4+3)*128 + h]; \
            } \
            (OUTARR)[nn] = a; \
        } \
    } while (0)

    float acc[4];
    float rr[4], ii[4];

    // P1: r gate (Wr_h in buf0)
    MBAR_WAIT(mb0, 0);
    GEMV4(aggS, (const float*)(sm + ND_WB0), acc);
    #pragma unroll
    for (int nn = 0; nn < 4; nn++) {
        int n = ng + nn;
        float a = acc[nn] + biaS[h];
        #pragma unroll
        for (int d = 0; d < 4; d++) a += insS[n*4+d] * WinS[d*128 + h];
        t1[n*128 + h] = fsig_(a);
    }
    __syncthreads();
    if (tid == 0) { MBAR_EXPECT_TX(mb0, 65536); BULK_CP(smb + ND_WB0, (const void*)Wh_h, 65536, mb0); }

    // P2: i gate (Wi_h in buf1)
    MBAR_WAIT(mb1, 0);
    GEMV4(aggS, (const float*)(sm + ND_WB1), acc);
    #pragma unroll
    for (int nn = 0; nn < 4; nn++) {
        int n = ng + nn;
        float a = acc[nn] + biaS[128 + h];
        #pragma unroll
        for (int d = 0; d < 4; d++) a += insS[n*4+d] * WinS[512 + d*128 + h];
        ii[nn] = fsig_(a);
        rr[nn] = t1[n*128 + h];
    }
    __syncthreads();
    if (tid == 0) { MBAR_EXPECT_TX(mb1, 65536); BULK_CP(smb + ND_WB1, (const void*)Wo1, 65536, mb1); }

    // P3: candidate + hidden update (Wh_h in buf0, parity 1)
    MBAR_WAIT(mb0, 1);
    GEMV4(aggS, (const float*)(sm + ND_WB0), acc);
    #pragma unroll
    for (int nn = 0; nn < 4; nn++) {
        int n = ng + nn;
        float a = biaS[256 + h];
        #pragma unroll
        for (int d = 0; d < 4; d++) a += insS[n*4+d] * WinS[1024 + d*128 + h];
        float nv = ftanh_(a + rr[nn] * acc[nn]);
        float hn = (1.0f - ii[nn]) * nv + ii[nn] * hidS[n*128 + h];
        hidS[n*128 + h] = hn;
        g_hidden[((size_t)(b * NN + n0 + n)) * HH + h] = hn;
    }
    __syncthreads();
    if (tid == 0) { MBAR_EXPECT_TX(mb0, 65536); BULK_CP(smb + ND_WB0, (const void*)Wo2, 65536, mb0); }

    // P4: y1 = relu(hidden@Wo1+bo1) (Wo1 in buf1, parity 1)
    MBAR_WAIT(mb1, 1);
    GEMV4(hidS, (const float*)(sm + ND_WB1), acc);
    #pragma unroll
    for (int nn = 0; nn < 4; nn++)
        t1[(ng+nn)*128 + h] = fmaxf(acc[nn] + biaS[384 + h], 0.0f);
    __syncthreads();

    // P5: y2 = relu(y1@Wo2+bo2) (Wo2 in buf0, parity 0)
    MBAR_WAIT(mb0, 0);
    GEMV4(t1, (const float*)(sm + ND_WB0), acc);
    #pragma unroll
    for (int nn = 0; nn < 4; nn++)
        t2[(ng+nn)*128 + h] = fmaxf(acc[nn] + biaS[512 + h], 0.0f);
    __syncthreads();

    // P6: pred = ins + y2@Wo3 + bo3
    if (tid < 32) {
        int n = tid >> 2, d = tid & 3;
        float a = bo3S[d];
        const float* vv = t2 + n*128;
        #pragma unroll 8
        for (int hh = 0; hh < 128; hh++) a += vv[hh] * Wo3S[hh*4 + d];
        float pred = insS[tid] + a;
        g_pred[(b * NN + n0 + n) * DD + d] = pred;
        if (step >= TT)
            out[(((size_t)(b * NN + n0 + n)) * DD + d) * LL + (step - TT)] = pred;
    }
    #undef GEMV4
}

// ---------------- launch ----------------
extern "C" void kernel_launch(void* const* d_in, const int* in_sizes, int n_in,
                              void* d_out, int out_size) {
    const float* data  = (const float*)d_in[0];
    const float* rel   = (const float*)d_in[1];
    const float* W1    = (const float*)d_in[2];
    const float* b1    = (const float*)d_in[3];
    const float* W2    = (const float*)d_in[4];
    const float* b2    = (const float*)d_in[5];
    const float* Wr_h  = (const float*)d_in[6];
    const float* Wi_h  = (const float*)d_in[7];
    const float* Wh_h  = (const float*)d_in[8];
    const float* Wr_in = (const float*)d_in[9];
    const float* br_in = (const float*)d_in[10];
    const float* Wi_in = (const float*)d_in[11];
    const float* bi_in = (const float*)d_in[12];
    const float* Wn_in = (const float*)d_in[13];
    const float* bn_in = (const float*)d_in[14];
    const float* Wo1   = (const float*)d_in[15];
    const float* bo1   = (const float*)d_in[16];
    const float* Wo2   = (const float*)d_in[17];
    const float* bo2   = (const float*)d_in[18];
    const float* Wo3   = (const float*)d_in[19];
    const float* bo3   = (const float*)d_in[20];
    const int* recv_idx = (const int*)d_in[21];
    const int* send_idx = (const int*)d_in[22];
    float* out = (float*)d_out;

    cudaFuncSetAttribute(uv_kernel,   cudaFuncAttributeMaxDynamicSharedMemorySize, UV_SMEM);
    cudaFuncSetAttribute(msg_kernel,  cudaFuncAttributeMaxDynamicSharedMemorySize, MSG_SMEM);
    cudaFuncSetAttribute(node_kernel, cudaFuncAttributeMaxDynamicSharedMemorySize, NODE_SMEM);

    init_kernel<<<512, 256>>>();
    prep_kernel<<<12, 256>>>(W1, W2);
    for (int s = 0; s < TT + LL; s++) {
        uv_kernel<<<dim3(8, 8), 256, UV_SMEM>>>();
        msg_kernel<<<dim3(32, BB), 256, MSG_SMEM>>>(b1, b2, rel, recv_idx, send_idx);
        node_kernel<<<dim3(8, BB), 256, NODE_SMEM>>>(data, s,
            Wr_h, Wi_h, Wh_h, Wr_in, br_in, Wi_in, bi_in, Wn_in, bn_in,
            Wo1, bo1, Wo2, bo2, Wo3, bo3, out);
    }
}

// round 7
// speedup vs baseline: 2.9416x; 2.1652x over previous
#include <cuda_runtime.h>
#include <cuda_bf16.h>
#include <stdint.h>
#include <math.h>

#define BB 16
#define NN 64
#define DD 4
#define TT 40
#define LL 10
#define HH 128
#define KK 4
#define EE (NN*(NN-1))

// fp32 tile: 128 rows x 132 words (528 B/row) -> conflict-free fragment LDS
#define SPW  132
#define TILEF_B (128*SPW*4)   // 67584 bytes

// ---------------- persistent device state ----------------
__device__ float g_hidden[BB*NN*HH];
__device__ float g_pred[BB*NN*DD];
__device__ float g_uv[BB*8*NN*HH];          // [B][ks][N][H]
__device__ float g_agg[BB*NN*HH];
__device__ __align__(16) float g_W1T[8*128*SPW]; // [ks][128][132]  T[n][f]=W[f][n]
__device__ __align__(16) float g_W2T[4*128*SPW]; // [k][128][132]

// ---------------- PTX helpers ----------------
__device__ __forceinline__ uint32_t smem_u32(const void* p) {
    uint32_t a;
    asm("{ .reg .u64 t; cvta.to.shared.u64 t, %1; cvt.u32.u64 %0, t; }" : "=r"(a) : "l"(p));
    return a;
}
#define MBAR_INIT(mb, c)  asm volatile("mbarrier.init.shared.b64 [%0], %1;" :: "r"(mb), "r"(c) : "memory")
#define MBAR_EXPECT_TX(mb, n) asm volatile("mbarrier.arrive.expect_tx.shared.b64 _, [%0], %1;" :: "r"(mb), "r"(n) : "memory")
#define FENCE_ASYNC()     asm volatile("fence.proxy.async.shared::cta;" ::: "memory")
#define BULK_CP(dst, src, bytes, mb) \
    asm volatile("cp.async.bulk.shared::cta.global.mbarrier::complete_tx::bytes [%0], [%1], %2, [%3];" \
        :: "r"(dst), "l"(src), "r"(bytes), "r"(mb) : "memory")

#define MBAR_WAIT(mb, ph) do { \
    uint32_t _m = (mb); uint32_t _p = (ph); uint32_t _d; \
    asm volatile("{\n\t.reg .pred p;\n\tmbarrier.try_wait.parity.acquire.cta.shared::cta.b64 p, [%1], %2;\n\tselp.b32 %0, 1, 0, p;\n\t}" \
        : "=r"(_d) : "r"(_m), "r"(_p) : "memory"); \
    if (!_d) { \
        asm volatile("{\n\t.reg .pred P1;\n\tWL_%=:\n\tmbarrier.try_wait.parity.acquire.cta.shared::cta.b64 P1, [%0], %1, 0x989680;\n\t@P1 bra.uni WD_%=;\n\tbra.uni WL_%=;\n\tWD_%=:\n\t}" \
            :: "r"(_m), "r"(_p) : "memory"); \
    } \
} while (0)

// tf32 mma: D(16x8,f32) += A(16x8,row) * B(8x8,col)
__device__ __forceinline__ void mma_tf32(float d[4], uint32_t a0, uint32_t a1, uint32_t a2, uint32_t a3,
                                         uint32_t b0, uint32_t b1) {
    asm volatile("mma.sync.aligned.m16n8k8.row.col.f32.tf32.tf32.f32 "
        "{%0,%1,%2,%3}, {%4,%5,%6,%7}, {%8,%9}, {%0,%1,%2,%3};"
        : "+f"(d[0]), "+f"(d[1]), "+f"(d[2]), "+f"(d[3])
        : "r"(a0), "r"(a1), "r"(a2), "r"(a3), "r"(b0), "r"(b1));
}

// 128x128x128 tf32 GEMM chunk; 16 warps, warp tile 32(m) x 32(n)
__device__ __forceinline__ void gemm_tf32(const float* __restrict__ A, const float* __restrict__ B,
                                          float acc[2][4][4], int mblk, int nblk, int lane) {
    int gid = lane >> 2, tig = lane & 3;
    const float* ap0 = A + (mblk * 32 + gid) * SPW + tig;
    const float* bp0 = B + (nblk * 32 + gid) * SPW + tig;
    #pragma unroll
    for (int ks = 0; ks < 16; ks++) {
        int k0 = ks * 8;
        uint32_t a[2][4];
        #pragma unroll
        for (int mf = 0; mf < 2; mf++) {
            const float* ap = ap0 + mf * 16 * SPW + k0;
            a[mf][0] = __float_as_uint(ap[0]);
            a[mf][1] = __float_as_uint(ap[8 * SPW]);
            a[mf][2] = __float_as_uint(ap[4]);
            a[mf][3] = __float_as_uint(ap[8 * SPW + 4]);
        }
        #pragma unroll
        for (int nf = 0; nf < 4; nf++) {
            const float* bp = bp0 + nf * 8 * SPW + k0;
            uint32_t b0 = __float_as_uint(bp[0]);
            uint32_t b1 = __float_as_uint(bp[4]);
            mma_tf32(acc[0][nf], a[0][0], a[0][1], a[0][2], a[0][3], b0, b1);
            mma_tf32(acc[1][nf], a[1][0], a[1][1], a[1][2], a[1][3], b0, b1);
        }
    }
}

// ---------------- fast math ----------------
__device__ __forceinline__ float fex2_(float x) { float r; asm("ex2.approx.f32 %0, %1;" : "=f"(r) : "f"(x)); return r; }
__device__ __forceinline__ float frcp_(float x) { float r; asm("rcp.approx.f32 %0, %1;" : "=f"(r) : "f"(x)); return r; }
__device__ __forceinline__ float ftanh_(float x) { return fmaf(-2.0f, frcp_(fex2_(x * 2.885390081777927f) + 1.0f), 1.0f); }
__device__ __forceinline__ float fsig_(float x)  { return frcp_(1.0f + fex2_(-1.4426950408889634f * x)); }
__device__ __forceinline__ float ftanha_(float x){ float r; asm("tanh.approx.f32 %0, %1;" : "=f"(r) : "f"(x)); return r; }

// ---------------- init ----------------
__global__ void init_kernel() {
    int i = blockIdx.x * blockDim.x + threadIdx.x;
    if (i < BB*NN*HH) g_hidden[i] = 0.0f;
    if (i < BB*NN*DD) g_pred[i]   = 0.0f;
}

// ---------------- prep: transposed padded fp32 tiles ----------------
__global__ __launch_bounds__(256)
void prep_kernel(const float* __restrict__ W1, const float* __restrict__ W2) {
    int s = blockIdx.x;
    const float* src = (s < 8) ? (W1 + s * 16384) : (W2 + (s - 8) * 16384);
    float* dst = (s < 8) ? (g_W1T + s * 128 * SPW) : (g_W2T + (s - 8) * 128 * SPW);
    for (int t = threadIdx.x; t < 16384; t += 256) {
        int n = t >> 7, f = t & 127;
        dst[n * SPW + f] = src[f * 128 + n];
    }
}

// ---------------- UV: u/v = hidden @ W1T[ks] ----------------
#define UV_A  0
#define UV_B  TILEF_B
#define UV_MB (2*TILEF_B)
#define UV_SMEM (UV_MB + 32)

__global__ __launch_bounds__(512)
void uv_kernel() {
    extern __shared__ char sm[];
    uint32_t smb = smem_u32(sm);
    int tid = threadIdx.x;
    int ks = blockIdx.x, bp = blockIdx.y;
    uint32_t mbt = smb + UV_MB;
    float* A = (float*)(sm + UV_A);
    const float* Bt = (const float*)(sm + UV_B);

    if (tid == 0) {
        MBAR_INIT(mbt, 1);
        FENCE_ASYNC();
        MBAR_EXPECT_TX(mbt, TILEF_B);
        BULK_CP(smb + UV_B, (const char*)(g_W1T + (size_t)ks * 128 * SPW), TILEF_B, mbt);
    }
    // A rows 0-63 = batch 2bp, 64-127 = batch 2bp+1 (fp32, padded stride)
    for (int idx = tid; idx < 128 * 32; idx += 512) {
        int row = idx >> 5, f4 = (idx & 31) * 4;
        int b = bp * 2 + (row >> 6), node = row & 63;
        float4 v = *(const float4*)(g_hidden + ((size_t)(b * NN + node)) * HH + f4);
        *(float4*)&A[row * SPW + f4] = v;
    }
    __syncthreads();
    MBAR_WAIT(mbt, 0);

    int w = tid >> 5, lane = tid & 31;
    int mblk = w & 3, nblk = w >> 2;
    int gid = lane >> 2, tig = lane & 3;

    float acc[2][4][4];
    #pragma unroll
    for (int mf = 0; mf < 2; mf++)
        #pragma unroll
        for (int nf = 0; nf < 4; nf++)
            #pragma unroll
            for (int j = 0; j < 4; j++) acc[mf][nf][j] = 0.0f;

    gemm_tf32(A, Bt, acc, mblk, nblk, lane);
    __syncthreads();   // done reading A; reuse as staging

    #pragma unroll
    for (int mf = 0; mf < 2; mf++) {
        int r0 = mblk * 32 + mf * 16 + gid;
        #pragma unroll
        for (int nf = 0; nf < 4; nf++) {
            int c = nblk * 32 + nf * 8 + tig * 2;
            *(float2*)&A[r0 * SPW + c]       = make_float2(acc[mf][nf][0], acc[mf][nf][1]);
            *(float2*)&A[(r0 + 8) * SPW + c] = make_float2(acc[mf][nf][2], acc[mf][nf][3]);
        }
    }
    __syncthreads();
    for (int idx = tid; idx < 128 * 32; idx += 512) {
        int row = idx >> 5, c4 = (idx & 31) * 4;
        float4 v = *(const float4*)&A[row * SPW + c4];
        int b = bp * 2 + (row >> 6), node = row & 63;
        *(float4*)(g_uv + (((size_t)(b * 8 + ks)) * 64 + node) * 128 + c4) = v;
    }
}

// ---------------- MSG kernel ----------------
#define MS_A   0
#define MS_B0  TILEF_B          /* 67584  */
#define MS_B1  (2*TILEF_B)      /* 135168 */
#define MS_REL 202752           /* 128x4 floats = 2048 */
#define MS_SEND 204800          /* 128 ints = 512 */
#define MS_B1S 205312           /* 4x128 floats = 2048 */
#define MS_B2S 207360           /* 4x128 floats = 2048 */
#define MS_VS  209408           /* 2x128 floats = 1024 */
#define MS_MB  210432
#define MSG_SMEM 210496

__global__ __launch_bounds__(512)
void msg_kernel(const float* __restrict__ b1, const float* __restrict__ b2,
                const float* __restrict__ rel,
                const int* __restrict__ recv_idx, const int* __restrict__ send_idx) {
    extern __shared__ char sm[];
    uint32_t smb = smem_u32(sm);
    int tid = threadIdx.x;
    int p = blockIdx.x, b = blockIdx.y;

    float* A     = (float*)(sm + MS_A);
    float* RelS  = (float*)(sm + MS_REL);
    int*   SendS = (int*)(sm + MS_SEND);
    float* b1S   = (float*)(sm + MS_B1S);
    float* b2S   = (float*)(sm + MS_B2S);
    float* vS    = (float*)(sm + MS_VS);
    uint32_t mb_t0 = smb + MS_MB, mb_t1 = smb + MS_MB + 8;

    if (tid == 0) {
        MBAR_INIT(mb_t0, 1);
        MBAR_INIT(mb_t1, 1);
        FENCE_ASYNC();
        MBAR_EXPECT_TX(mb_t0, TILEF_B);
        BULK_CP(smb + MS_B0, (const char*)(g_W2T + 0), TILEF_B, mb_t0);
        MBAR_EXPECT_TX(mb_t1, TILEF_B);
        BULK_CP(smb + MS_B1, (const char*)(g_W2T + 128 * SPW), TILEF_B, mb_t1);
    }
    if (tid < 128) {
        int row = tid;
        float r0 = 0, r1 = 0, r2 = 0, r3 = 0;
        int sn = 0;
        if (row != 63 && row != 127) {
            int e = (row < 64) ? (p * 126 + row) : (p * 126 + row - 1);
            sn = send_idx[e];
            const float* rp = rel + ((size_t)(b * EE + e)) * KK;
            r0 = rp[0]; r1 = rp[1]; r2 = rp[2]; r3 = rp[3];
        }
        SendS[row] = sn;
        RelS[row * 4 + 0] = r0; RelS[row * 4 + 1] = r1;
        RelS[row * 4 + 2] = r2; RelS[row * 4 + 3] = r3;
        #pragma unroll
        for (int k = 0; k < 4; k++) {
            b1S[k * 128 + tid] = b1[k * 128 + tid];
            b2S[k * 128 + tid] = b2[k * 128 + tid];
        }
    }
    int r0n = recv_idx[p * 126];
    int r1n = recv_idx[p * 126 + 63];
    __syncthreads();

    int w = tid >> 5, lane = tid & 31;
    int mblk = w & 3, nblk = w >> 2;
    int gid = lane >> 2, tig = lane & 3;

    float macc[2][4][4];
    #pragma unroll
    for (int mf = 0; mf < 2; mf++)
        #pragma unroll
        for (int nf = 0; nf < 4; nf++)
            #pragma unroll
            for (int j = 0; j < 4; j++) macc[mf][nf][j] = 0.0f;

    for (int k = 0; k < 4; k++) {
        // stage v[recv] + b1 for the two receivers
        if (tid < 256) {
            int f = tid & 127, rh = tid >> 7;
            int rv = rh ? r1n : r0n;
            const float* v = g_uv + ((size_t)(b * 8 + 2 * k + 1)) * NN * HH;
            vS[rh * 128 + f] = v[rv * 128 + f] + b1S[k * 128 + f];
        }
        __syncthreads();
        // A = tanh(u[send] + vS), fp32; rows 63/127 zero
        const float* u = g_uv + ((size_t)(b * 8 + 2 * k)) * NN * HH;
        for (int idx = tid; idx < 128 * 32; idx += 512) {
            int row = idx >> 5, f4 = (idx & 31) * 4;
            float4 o = make_float4(0.f, 0.f, 0.f, 0.f);
            if (row != 63 && row != 127) {
                int sn = SendS[row];
                int rh = row >> 6;
                float4 uu = *(const float4*)(u + sn * 128 + f4);
                const float* vv = vS + rh * 128 + f4;
                o.x = ftanha_(uu.x + vv[0]);
                o.y = ftanha_(uu.y + vv[1]);
                o.z = ftanha_(uu.z + vv[2]);
                o.w = ftanha_(uu.w + vv[3]);
            }
            *(float4*)&A[row * SPW + f4] = o;
        }
        __syncthreads();

        uint32_t mbt = (k & 1) ? mb_t1 : mb_t0;
        MBAR_WAIT(mbt, (k >> 1) & 1);
        const float* Bt = (const float*)(sm + ((k & 1) ? MS_B1 : MS_B0));

        float acc[2][4][4];
        #pragma unroll
        for (int mf = 0; mf < 2; mf++)
            #pragma unroll
            for (int nf = 0; nf < 4; nf++)
                #pragma unroll
                for (int j = 0; j < 4; j++) acc[mf][nf][j] = 0.0f;

        gemm_tf32(A, Bt, acc, mblk, nblk, lane);

        // epilogue: macc += relw * tanh(acc + b2)
        #pragma unroll
        for (int mf = 0; mf < 2; mf++) {
            int r0 = mblk * 32 + mf * 16 + gid;
            float relw0 = RelS[r0 * 4 + k];
            float relw1 = RelS[(r0 + 8) * 4 + k];
            #pragma unroll
            for (int nf = 0; nf < 4; nf++) {
                int c = nblk * 32 + nf * 8 + tig * 2;
                float bb0 = b2S[k * 128 + c], bb1 = b2S[k * 128 + c + 1];
                macc[mf][nf][0] += relw0 * ftanha_(acc[mf][nf][0] + bb0);
                macc[mf][nf][1] += relw0 * ftanha_(acc[mf][nf][1] + bb1);
                macc[mf][nf][2] += relw1 * ftanha_(acc[mf][nf][2] + bb0);
                macc[mf][nf][3] += relw1 * ftanha_(acc[mf][nf][3] + bb1);
            }
        }
        __syncthreads();   // all warps done with A and B[kbuf]
        if (tid == 0 && k < 2) {
            uint32_t mbn = ((k + 2) & 1) ? mb_t1 : mb_t0;
            uint32_t dst = ((k + 2) & 1) ? (smb + MS_B1) : (smb + MS_B0);
            MBAR_EXPECT_TX(mbn, TILEF_B);
            BULK_CP(dst, (const char*)(g_W2T + (size_t)(k + 2) * 128 * SPW), TILEF_B, mbn);
        }
    }

    // stage macc into A region, then segment-sum 63 edges per receiver
    #pragma unroll
    for (int mf = 0; mf < 2; mf++) {
        int r0 = mblk * 32 + mf * 16 + gid;
        #pragma unroll
        for (int nf = 0; nf < 4; nf++) {
            int c = nblk * 32 + nf * 8 + tig * 2;
            *(float2*)&A[r0 * SPW + c]       = make_float2(macc[mf][nf][0], macc[mf][nf][1]);
            *(float2*)&A[(r0 + 8) * SPW + c] = make_float2(macc[mf][nf][2], macc[mf][nf][3]);
        }
    }
    __syncthreads();
    // partial sums: seg = tid>>7: receiver = seg&1, part = seg>>1 (rows part*32..)
    {
        int h = tid & 127, seg = tid >> 7;
        int rh = seg & 1, part = seg >> 1;
        int nrows = part ? 31 : 32;          // part0: 0..31, part1: 32..62
        const float* src = A + (rh * 64 + part * 32) * SPW + h;
        float acc = 0.0f;
        for (int r = 0; r < nrows; r++) acc += src[r * SPW];
        b1S[seg * 128 + h] = acc;            // reuse b1S as scratch
    }
    __syncthreads();
    if (tid < 256) {
        int h = tid & 127, rh = tid >> 7;
        float acc = b1S[rh * 128 + h] + b1S[(2 + rh) * 128 + h];
        int rv = rh ? r1n : r0n;
        g_agg[((size_t)(b * NN + rv)) * HH + h] = acc * (1.0f / 16.0f);
    }
}

// ---------------- NODE kernel: GRU + output MLP ----------------
#define ND_WB0 0
#define ND_WB1 65536
#define ND_AGG 131072
#define ND_HID 135168
#define ND_T1  139264
#define ND_T2  143360
#define ND_INS 147456
#define ND_WIN 147712
#define ND_BIA 153856
#define ND_WO3 156416
#define ND_BO3 158464
#define ND_MB  158480
#define NODE_SMEM 158592

__global__ __launch_bounds__(256)
void node_kernel(const float* __restrict__ data, int step,
                 const float* __restrict__ Wr_h, const float* __restrict__ Wi_h,
                 const float* __restrict__ Wh_h,
                 const float* __restrict__ Wr_in, const float* __restrict__ br_in,
                 const float* __restrict__ Wi_in, const float* __restrict__ bi_in,
                 const float* __restrict__ Wn_in, const float* __restrict__ bn_in,
                 const float* __restrict__ Wo1, const float* __restrict__ bo1,
                 const float* __restrict__ Wo2, const float* __restrict__ bo2,
                 const float* __restrict__ Wo3, const float* __restrict__ bo3,
                 float* __restrict__ out) {
    extern __shared__ char sm[];
    uint32_t smb = smem_u32(sm);
    int q = blockIdx.x, b = blockIdx.y;
    int n0 = q * 8;
    int tid = threadIdx.x;

    float* aggS = (float*)(sm + ND_AGG);
    float* hidS = (float*)(sm + ND_HID);
    float* t1   = (float*)(sm + ND_T1);
    float* t2   = (float*)(sm + ND_T2);
    float* insS = (float*)(sm + ND_INS);
    float* WinS = (float*)(sm + ND_WIN);
    float* biaS = (float*)(sm + ND_BIA);
    float* Wo3S = (float*)(sm + ND_WO3);
    float* bo3S = (float*)(sm + ND_BO3);
    uint32_t mb0 = smb + ND_MB, mb1 = smb + ND_MB + 8;

    if (tid == 0) {
        MBAR_INIT(mb0, 1);
        MBAR_INIT(mb1, 1);
        FENCE_ASYNC();
        MBAR_EXPECT_TX(mb0, 65536);
        BULK_CP(smb + ND_WB0, (const void*)Wr_h, 65536, mb0);
        MBAR_EXPECT_TX(mb1, 65536);
        BULK_CP(smb + ND_WB1, (const void*)Wi_h, 65536, mb1);
    }
    {
        const float* ag = g_agg    + ((size_t)(b * NN + n0)) * HH;
        const float* hg = g_hidden + ((size_t)(b * NN + n0)) * HH;
        ((float4*)aggS)[tid] = ((const float4*)ag)[tid];
        ((float4*)hidS)[tid] = ((const float4*)hg)[tid];
    }
    if (tid < 32) {
        int n = tid >> 2, d = tid & 3;
        float v;
        if (step < TT) v = data[(((size_t)(b * NN + n0 + n)) * DD + d) * TT + step];
        else           v = g_pred[(b * NN + n0 + n) * DD + d];
        insS[tid] = v;
    }
    for (int i = tid; i < 512; i += 256) {
        WinS[i]        = Wr_in[i];
        WinS[512 + i]  = Wi_in[i];
        WinS[1024 + i] = Wn_in[i];
        Wo3S[i]        = Wo3[i];
    }
    if (tid < 128) {
        biaS[tid]       = br_in[tid];
        biaS[128 + tid] = bi_in[tid];
        biaS[256 + tid] = bn_in[tid];
        biaS[384 + tid] = bo1[tid];
        biaS[512 + tid] = bo2[tid];
    }
    if (tid < 4) bo3S[tid] = bo3[tid];
    __syncthreads();

    int h = tid & 127, ng = (tid >> 7) * 4;

    #define GEMV4(ACT, WB, OUTARR) do { \
        const float* _wb = (WB); \
        _Pragma("unroll") \
        for (int nn = 0; nn < 4; nn++) { \
            const float* av = (ACT) + (ng + nn) * 128; \
            float a = 0.0f; \
            _Pragma("unroll 8") \
            for (int f4 = 0; f4 < 32; f4++) { \
                float4 x = ((const float4*)av)[f4]; \
                a += x.x * _wb[(f4*4+0)*128 + h] + x.y * _wb[(f4*4+1)*128 + h] \
                   + x.z * _wb[(f4*4+2)*128 + h] + x.w * _wb[(f4*4+3)*128 + h]; \
            } \
            (OUTARR)[nn] = a; \
        } \
    } while (0)

    float acc[4];
    float rr[4], ii[4];

    MBAR_WAIT(mb0, 0);
    GEMV4(aggS, (const float*)(sm + ND_WB0), acc);
    #pragma unroll
    for (int nn = 0; nn < 4; nn++) {
        int n = ng + nn;
        float a = acc[nn] + biaS[h];
        #pragma unroll
        for (int d = 0; d < 4; d++) a += insS[n*4+d] * WinS[d*128 + h];
        t1[n*128 + h] = fsig_(a);
    }
    __syncthreads();
    if (tid == 0) { MBAR_EXPECT_TX(mb0, 65536); BULK_CP(smb + ND_WB0, (const void*)Wh_h, 65536, mb0); }

    MBAR_WAIT(mb1, 0);
    GEMV4(aggS, (const float*)(sm + ND_WB1), acc);
    #pragma unroll
    for (int nn = 0; nn < 4; nn++) {
        int n = ng + nn;
        float a = acc[nn] + biaS[128 + h];
        #pragma unroll
        for (int d = 0; d < 4; d++) a += insS[n*4+d] * WinS[512 + d*128 + h];
        ii[nn] = fsig_(a);
        rr[nn] = t1[n*128 + h];
    }
    __syncthreads();
    if (tid == 0) { MBAR_EXPECT_TX(mb1, 65536); BULK_CP(smb + ND_WB1, (const void*)Wo1, 65536, mb1); }

    MBAR_WAIT(mb0, 1);
    GEMV4(aggS, (const float*)(sm + ND_WB0), acc);
    #pragma unroll
    for (int nn = 0; nn < 4; nn++) {
        int n = ng + nn;
        float a = biaS[256 + h];
        #pragma unroll
        for (int d = 0; d < 4; d++) a += insS[n*4+d] * WinS[1024 + d*128 + h];
        float nv = ftanh_(a + rr[nn] * acc[nn]);
        float hn = (1.0f - ii[nn]) * nv + ii[nn] * hidS[n*128 + h];
        hidS[n*128 + h] = hn;
        g_hidden[((size_t)(b * NN + n0 + n)) * HH + h] = hn;
    }
    __syncthreads();
    if (tid == 0) { MBAR_EXPECT_TX(mb0, 65536); BULK_CP(smb + ND_WB0, (const void*)Wo2, 65536, mb0); }

    MBAR_WAIT(mb1, 1);
    GEMV4(hidS, (const float*)(sm + ND_WB1), acc);
    #pragma unroll
    for (int nn = 0; nn < 4; nn++)
        t1[(ng+nn)*128 + h] = fmaxf(acc[nn] + biaS[384 + h], 0.0f);
    __syncthreads();

    MBAR_WAIT(mb0, 0);
    GEMV4(t1, (const float*)(sm + ND_WB0), acc);
    #pragma unroll
    for (int nn = 0; nn < 4; nn++)
        t2[(ng+nn)*128 + h] = fmaxf(acc[nn] + biaS[512 + h], 0.0f);
    __syncthreads();

    if (tid < 32) {
        int n = tid >> 2, d = tid & 3;
        float a = bo3S[d];
        const float* vv = t2 + n*128;
        #pragma unroll 8
        for (int hh = 0; hh < 128; hh++) a += vv[hh] * Wo3S[hh*4 + d];
        float pred = insS[tid] + a;
        g_pred[(b * NN + n0 + n) * DD + d] = pred;
        if (step >= TT)
            out[(((size_t)(b * NN + n0 + n)) * DD + d) * LL + (step - TT)] = pred;
    }
    #undef GEMV4
}

// ---------------- launch ----------------
extern "C" void kernel_launch(void* const* d_in, const int* in_sizes, int n_in,
                              void* d_out, int out_size) {
    const float* data  = (const float*)d_in[0];
    const float* rel   = (const float*)d_in[1];
    const float* W1    = (const float*)d_in[2];
    const float* b1    = (const float*)d_in[3];
    const float* W2    = (const float*)d_in[4];
    const float* b2    = (const float*)d_in[5];
    const float* Wr_h  = (const float*)d_in[6];
    const float* Wi_h  = (const float*)d_in[7];
    const float* Wh_h  = (const float*)d_in[8];
    const float* Wr_in = (const float*)d_in[9];
    const float* br_in = (const float*)d_in[10];
    const float* Wi_in = (const float*)d_in[11];
    const float* bi_in = (const float*)d_in[12];
    const float* Wn_in = (const float*)d_in[13];
    const float* bn_in = (const float*)d_in[14];
    const float* Wo1   = (const float*)d_in[15];
    const float* bo1   = (const float*)d_in[16];
    const float* Wo2   = (const float*)d_in[17];
    const float* bo2   = (const float*)d_in[18];
    const float* Wo3   = (const float*)d_in[19];
    const float* bo3   = (const float*)d_in[20];
    const int* recv_idx = (const int*)d_in[21];
    const int* send_idx = (const int*)d_in[22];
    float* out = (float*)d_out;

    cudaFuncSetAttribute(uv_kernel,   cudaFuncAttributeMaxDynamicSharedMemorySize, UV_SMEM);
    cudaFuncSetAttribute(msg_kernel,  cudaFuncAttributeMaxDynamicSharedMemorySize, MSG_SMEM);
    cudaFuncSetAttribute(node_kernel, cudaFuncAttributeMaxDynamicSharedMemorySize, NODE_SMEM);

    init_kernel<<<512, 256>>>();
    prep_kernel<<<12, 256>>>(W1, W2);
    for (int s = 0; s < TT + LL; s++) {
        uv_kernel<<<dim3(8, 8), 512, UV_SMEM>>>();
        msg_kernel<<<dim3(32, BB), 512, MSG_SMEM>>>(b1, b2, rel, recv_idx, send_idx);
        node_kernel<<<dim3(8, BB), 256, NODE_SMEM>>>(data, s,
            Wr_h, Wi_h, Wh_h, Wr_in, br_in, Wi_in, bi_in, Wn_in, bn_in,
            Wo1, bo1, Wo2, bo2, Wo3, bo3, out);
    }
}

// round 8
// speedup vs baseline: 3.7230x; 1.2657x over previous
#include <cuda_runtime.h>
#include <cuda_bf16.h>
#include <stdint.h>
#include <math.h>

#define BB 16
#define NN 64
#define DD 4
#define TT 40
#define LL 10
#define HH 128
#define KK 4
#define EE (NN*(NN-1))

// fp32 tile (uv): 128 x 132 words
#define SPW  132
#define TILEF_B (128*SPW*4)   // 67584
// bf16 tile (msg): 128 x 136 halves (272 B/row)
#define SP   136
#define SPB  272
#define TILEH_B (128*SPB)     // 34816

// ---------------- persistent device state ----------------
__device__ float g_hidden[BB*NN*HH];
__device__ float g_pred[BB*NN*DD];
__device__ __nv_bfloat16 g_uv[BB*8*NN*HH];       // [B][ks][N][H] bf16
__device__ float g_agg[BB*NN*HH];
__device__ __align__(16) float g_W1T[8*128*SPW];          // fp32 [ks][128][132]
__device__ __align__(16) __nv_bfloat16 g_W2T[4*128*SP];   // bf16 [k][128][136]

// ---------------- PTX helpers ----------------
__device__ __forceinline__ uint32_t smem_u32(const void* p) {
    uint32_t a;
    asm("{ .reg .u64 t; cvta.to.shared.u64 t, %1; cvt.u32.u64 %0, t; }" : "=r"(a) : "l"(p));
    return a;
}
#define MBAR_INIT(mb, c)  asm volatile("mbarrier.init.shared.b64 [%0], %1;" :: "r"(mb), "r"(c) : "memory")
#define MBAR_EXPECT_TX(mb, n) asm volatile("mbarrier.arrive.expect_tx.shared.b64 _, [%0], %1;" :: "r"(mb), "r"(n) : "memory")
#define FENCE_ASYNC()     asm volatile("fence.proxy.async.shared::cta;" ::: "memory")
#define BULK_CP(dst, src, bytes, mb) \
    asm volatile("cp.async.bulk.shared::cta.global.mbarrier::complete_tx::bytes [%0], [%1], %2, [%3];" \
        :: "r"(dst), "l"(src), "r"(bytes), "r"(mb) : "memory")

#define MBAR_WAIT(mb, ph) do { \
    uint32_t _m = (mb); uint32_t _p = (ph); uint32_t _d; \
    asm volatile("{\n\t.reg .pred p;\n\tmbarrier.try_wait.parity.acquire.cta.shared::cta.b64 p, [%1], %2;\n\tselp.b32 %0, 1, 0, p;\n\t}" \
        : "=r"(_d) : "r"(_m), "r"(_p) : "memory"); \
    if (!_d) { \
        asm volatile("{\n\t.reg .pred P1;\n\tWL_%=:\n\tmbarrier.try_wait.parity.acquire.cta.shared::cta.b64 P1, [%0], %1, 0x989680;\n\t@P1 bra.uni WD_%=;\n\tbra.uni WL_%=;\n\tWD_%=:\n\t}" \
            :: "r"(_m), "r"(_p) : "memory"); \
    } \
} while (0)

// tf32 mma m16n8k8
__device__ __forceinline__ void mma_tf32(float d[4], uint32_t a0, uint32_t a1, uint32_t a2, uint32_t a3,
                                         uint32_t b0, uint32_t b1) {
    asm volatile("mma.sync.aligned.m16n8k8.row.col.f32.tf32.tf32.f32 "
        "{%0,%1,%2,%3}, {%4,%5,%6,%7}, {%8,%9}, {%0,%1,%2,%3};"
        : "+f"(d[0]), "+f"(d[1]), "+f"(d[2]), "+f"(d[3])
        : "r"(a0), "r"(a1), "r"(a2), "r"(a3), "r"(b0), "r"(b1));
}
// bf16 mma m16n8k16
__device__ __forceinline__ void mma_bf16(float d[4], uint32_t a0, uint32_t a1, uint32_t a2, uint32_t a3,
                                         uint32_t b0, uint32_t b1) {
    asm volatile("mma.sync.aligned.m16n8k16.row.col.f32.bf16.bf16.f32 "
        "{%0,%1,%2,%3}, {%4,%5,%6,%7}, {%8,%9}, {%0,%1,%2,%3};"
        : "+f"(d[0]), "+f"(d[1]), "+f"(d[2]), "+f"(d[3])
        : "r"(a0), "r"(a1), "r"(a2), "r"(a3), "r"(b0), "r"(b1));
}

// tf32 GEMM (uv): 16 warps, warp tile 32m x 32n
__device__ __forceinline__ void gemm_tf32(const float* __restrict__ A, const float* __restrict__ B,
                                          float acc[2][4][4], int mblk, int nblk, int lane) {
    int gid = lane >> 2, tig = lane & 3;
    const float* ap0 = A + (mblk * 32 + gid) * SPW + tig;
    const float* bp0 = B + (nblk * 32 + gid) * SPW + tig;
    #pragma unroll
    for (int ks = 0; ks < 16; ks++) {
        int k0 = ks * 8;
        uint32_t a[2][4];
        #pragma unroll
        for (int mf = 0; mf < 2; mf++) {
            const float* ap = ap0 + mf * 16 * SPW + k0;
            a[mf][0] = __float_as_uint(ap[0]);
            a[mf][1] = __float_as_uint(ap[8 * SPW]);
            a[mf][2] = __float_as_uint(ap[4]);
            a[mf][3] = __float_as_uint(ap[8 * SPW + 4]);
        }
        #pragma unroll
        for (int nf = 0; nf < 4; nf++) {
            const float* bp = bp0 + nf * 8 * SPW + k0;
            uint32_t b0 = __float_as_uint(bp[0]);
            uint32_t b1 = __float_as_uint(bp[4]);
            mma_tf32(acc[0][nf], a[0][0], a[0][1], a[0][2], a[0][3], b0, b1);
            mma_tf32(acc[1][nf], a[1][0], a[1][1], a[1][2], a[1][3], b0, b1);
        }
    }
}

// bf16 GEMM (msg): 32 warps, warp tile 16m x 32n
__device__ __forceinline__ void gemm_bf16(const char* __restrict__ A, const char* __restrict__ B,
                                          float acc[4][4], int mblk, int nblk, int lane) {
    int gid = lane >> 2, tig = lane & 3;
    const char* ap0 = A + (mblk * 16 + gid) * SPB + tig * 4;
    const char* bp0 = B + (nblk * 32 + gid) * SPB + tig * 4;
    #pragma unroll
    for (int ks = 0; ks < 8; ks++) {
        int kb = ks * 32;
        uint32_t a0 = *(const uint32_t*)(ap0 + kb);
        uint32_t a1 = *(const uint32_t*)(ap0 + 8 * SPB + kb);
        uint32_t a2 = *(const uint32_t*)(ap0 + kb + 16);
        uint32_t a3 = *(const uint32_t*)(ap0 + 8 * SPB + kb + 16);
        #pragma unroll
        for (int nf = 0; nf < 4; nf++) {
            const char* bp = bp0 + nf * 8 * SPB + kb;
            uint32_t b0 = *(const uint32_t*)bp;
            uint32_t b1 = *(const uint32_t*)(bp + 16);
            mma_bf16(acc[nf], a0, a1, a2, a3, b0, b1);
        }
    }
}

// ---------------- fast math ----------------
__device__ __forceinline__ float fex2_(float x) { float r; asm("ex2.approx.f32 %0, %1;" : "=f"(r) : "f"(x)); return r; }
__device__ __forceinline__ float frcp_(float x) { float r; asm("rcp.approx.f32 %0, %1;" : "=f"(r) : "f"(x)); return r; }
__device__ __forceinline__ float ftanh_(float x) { return fmaf(-2.0f, frcp_(fex2_(x * 2.885390081777927f) + 1.0f), 1.0f); }
__device__ __forceinline__ float fsig_(float x)  { return frcp_(1.0f + fex2_(-1.4426950408889634f * x)); }
__device__ __forceinline__ float ftanha_(float x){ float r; asm("tanh.approx.f32 %0, %1;" : "=f"(r) : "f"(x)); return r; }

// ---------------- init ----------------
__global__ void init_kernel() {
    int i = blockIdx.x * blockDim.x + threadIdx.x;
    if (i < BB*NN*HH) g_hidden[i] = 0.0f;
    if (i < BB*NN*DD) g_pred[i]   = 0.0f;
}

// ---------------- prep ----------------
__global__ __launch_bounds__(256)
void prep_kernel(const float* __restrict__ W1, const float* __restrict__ W2) {
    int s = blockIdx.x;
    if (s < 8) {
        const float* src = W1 + s * 16384;
        float* dst = g_W1T + s * 128 * SPW;
        for (int t = threadIdx.x; t < 16384; t += 256) {
            int n = t >> 7, f = t & 127;
            dst[n * SPW + f] = src[f * 128 + n];
        }
    } else {
        const float* src = W2 + (s - 8) * 16384;
        __nv_bfloat16* dst = g_W2T + (s - 8) * 128 * SP;
        for (int t = threadIdx.x; t < 16384; t += 256) {
            int n = t >> 7, f = t & 127;
            dst[n * SP + f] = __float2bfloat16_rn(src[f * 128 + n]);
        }
    }
}

// ---------------- UV: tf32 GEMM, bf16 output ----------------
#define UV_A  0
#define UV_B  TILEF_B
#define UV_MB (2*TILEF_B)
#define UV_SMEM (UV_MB + 32)

__global__ __launch_bounds__(512)
void uv_kernel() {
    extern __shared__ char sm[];
    uint32_t smb = smem_u32(sm);
    int tid = threadIdx.x;
    int ks = blockIdx.x, bp = blockIdx.y;
    uint32_t mbt = smb + UV_MB;
    float* A = (float*)(sm + UV_A);
    const float* Bt = (const float*)(sm + UV_B);

    if (tid == 0) {
        MBAR_INIT(mbt, 1);
        FENCE_ASYNC();
        MBAR_EXPECT_TX(mbt, TILEF_B);
        BULK_CP(smb + UV_B, (const char*)(g_W1T + (size_t)ks * 128 * SPW), TILEF_B, mbt);
    }
    for (int idx = tid; idx < 128 * 32; idx += 512) {
        int row = idx >> 5, f4 = (idx & 31) * 4;
        int b = bp * 2 + (row >> 6), node = row & 63;
        float4 v = *(const float4*)(g_hidden + ((size_t)(b * NN + node)) * HH + f4);
        *(float4*)&A[row * SPW + f4] = v;
    }
    __syncthreads();
    MBAR_WAIT(mbt, 0);

    int w = tid >> 5, lane = tid & 31;
    int mblk = w & 3, nblk = w >> 2;
    int gid = lane >> 2, tig = lane & 3;

    float acc[2][4][4];
    #pragma unroll
    for (int mf = 0; mf < 2; mf++)
        #pragma unroll
        for (int nf = 0; nf < 4; nf++)
            #pragma unroll
            for (int j = 0; j < 4; j++) acc[mf][nf][j] = 0.0f;

    gemm_tf32(A, Bt, acc, mblk, nblk, lane);
    __syncthreads();

    #pragma unroll
    for (int mf = 0; mf < 2; mf++) {
        int r0 = mblk * 32 + mf * 16 + gid;
        #pragma unroll
        for (int nf = 0; nf < 4; nf++) {
            int c = nblk * 32 + nf * 8 + tig * 2;
            *(float2*)&A[r0 * SPW + c]       = make_float2(acc[mf][nf][0], acc[mf][nf][1]);
            *(float2*)&A[(r0 + 8) * SPW + c] = make_float2(acc[mf][nf][2], acc[mf][nf][3]);
        }
    }
    __syncthreads();
    // write bf16
    for (int idx = tid; idx < 128 * 16; idx += 512) {
        int row = idx >> 4, c8 = (idx & 15) * 8;
        float4 v0 = *(const float4*)&A[row * SPW + c8];
        float4 v1 = *(const float4*)&A[row * SPW + c8 + 4];
        __nv_bfloat162 p0 = __floats2bfloat162_rn(v0.x, v0.y);
        __nv_bfloat162 p1 = __floats2bfloat162_rn(v0.z, v0.w);
        __nv_bfloat162 p2 = __floats2bfloat162_rn(v1.x, v1.y);
        __nv_bfloat162 p3 = __floats2bfloat162_rn(v1.z, v1.w);
        int b = bp * 2 + (row >> 6), node = row & 63;
        __nv_bfloat162* dst = (__nv_bfloat162*)(g_uv + ((size_t)(b * 8 + ks) * 64 + node) * 128 + c8);
        dst[0] = p0; dst[1] = p1; dst[2] = p2; dst[3] = p3;
    }
}

// ---------------- MSG kernel: 1024 threads, bf16 GEMM ----------------
#define MS_A   0                       /* bf16 128x136  34816 */
#define MS_B0  TILEH_B                 /* 34816 */
#define MS_B1  (2*TILEH_B)             /* 69632 */
#define MS_MS  TILEH_B                 /* fp32 staging reuses B0+B1 */
#define MS_REL  104448                 /* 128x4 f = 2048 */
#define MS_SEND 106496                 /* 512 */
#define MS_B1S  107008                 /* 2048 */
#define MS_B2S  109056                 /* 2048 */
#define MS_VS   111104                 /* 1024 */
#define MS_SCR  112128                 /* 8x128 f = 4096 */
#define MS_MB   116224
#define MSG_SMEM 116256

__global__ __launch_bounds__(1024, 1)
void msg_kernel(const float* __restrict__ b1, const float* __restrict__ b2,
                const float* __restrict__ rel,
                const int* __restrict__ recv_idx, const int* __restrict__ send_idx) {
    extern __shared__ char sm[];
    uint32_t smb = smem_u32(sm);
    int tid = threadIdx.x;
    int p = blockIdx.x, b = blockIdx.y;

    float* RelS  = (float*)(sm + MS_REL);
    int*   SendS = (int*)(sm + MS_SEND);
    float* b1S   = (float*)(sm + MS_B1S);
    float* b2S   = (float*)(sm + MS_B2S);
    float* vS    = (float*)(sm + MS_VS);
    float* scr   = (float*)(sm + MS_SCR);
    uint32_t mb_t0 = smb + MS_MB, mb_t1 = smb + MS_MB + 8;

    if (tid == 0) {
        MBAR_INIT(mb_t0, 1);
        MBAR_INIT(mb_t1, 1);
        FENCE_ASYNC();
        MBAR_EXPECT_TX(mb_t0, TILEH_B);
        BULK_CP(smb + MS_B0, (const char*)(g_W2T + 0), TILEH_B, mb_t0);
        MBAR_EXPECT_TX(mb_t1, TILEH_B);
        BULK_CP(smb + MS_B1, (const char*)(g_W2T + 128 * SP), TILEH_B, mb_t1);
    }
    if (tid < 128) {
        int row = tid;
        float r0 = 0, r1 = 0, r2 = 0, r3 = 0;
        int sn = 0;
        if (row != 63 && row != 127) {
            int e = (row < 64) ? (p * 126 + row) : (p * 126 + row - 1);
            sn = send_idx[e];
            const float* rp = rel + ((size_t)(b * EE + e)) * KK;
            r0 = rp[0]; r1 = rp[1]; r2 = rp[2]; r3 = rp[3];
        }
        SendS[row] = sn;
        RelS[row * 4 + 0] = r0; RelS[row * 4 + 1] = r1;
        RelS[row * 4 + 2] = r2; RelS[row * 4 + 3] = r3;
        #pragma unroll
        for (int k = 0; k < 4; k++) {
            b1S[k * 128 + tid] = b1[k * 128 + tid];
            b2S[k * 128 + tid] = b2[k * 128 + tid];
        }
    }
    int r0n = recv_idx[p * 126];
    int r1n = recv_idx[p * 126 + 63];
    __syncthreads();

    int w = tid >> 5, lane = tid & 31;
    int mblk = w & 7, nblk = w >> 3;      // warp tile 16m x 32n
    int gid = lane >> 2, tig = lane & 3;

    float macc[4][4];
    #pragma unroll
    for (int nf = 0; nf < 4; nf++)
        #pragma unroll
        for (int j = 0; j < 4; j++) macc[nf][j] = 0.0f;

    for (int k = 0; k < 4; k++) {
        // vS = float(v[recv]) + b1[k]
        if (tid < 256) {
            int f = tid & 127, rh = tid >> 7;
            int rv = rh ? r1n : r0n;
            const __nv_bfloat16* v = g_uv + ((size_t)(b * 8 + 2 * k + 1)) * NN * HH + rv * 128;
            vS[rh * 128 + f] = __bfloat162float(v[f]) + b1S[k * 128 + f];
        }
        __syncthreads();
        // A = bf16(tanh(u[send] + vS)); rows 63/127 zero
        const __nv_bfloat16* u = g_uv + ((size_t)(b * 8 + 2 * k)) * NN * HH;
        for (int idx = tid; idx < 128 * 32; idx += 1024) {
            int row = idx >> 5, f4 = (idx & 31) * 4;
            uint32_t o01 = 0, o23 = 0;
            if (row != 63 && row != 127) {
                int sn = SendS[row];
                int rh = row >> 6;
                uint2 q = *(const uint2*)(u + sn * 128 + f4);
                float2 f0 = __bfloat1622float2(*(__nv_bfloat162*)&q.x);
                float2 f1 = __bfloat1622float2(*(__nv_bfloat162*)&q.y);
                const float* vv = vS + rh * 128 + f4;
                __nv_bfloat162 p0 = __floats2bfloat162_rn(ftanha_(f0.x + vv[0]), ftanha_(f0.y + vv[1]));
                __nv_bfloat162 p1 = __floats2bfloat162_rn(ftanha_(f1.x + vv[2]), ftanha_(f1.y + vv[3]));
                o01 = *(uint32_t*)&p0; o23 = *(uint32_t*)&p1;
            }
            *(uint2*)(sm + MS_A + row * SPB + f4 * 2) = make_uint2(o01, o23);
        }
        __syncthreads();

        uint32_t mbt = (k & 1) ? mb_t1 : mb_t0;
        MBAR_WAIT(mbt, (k >> 1) & 1);
        const char* Bt = sm + ((k & 1) ? MS_B1 : MS_B0);

        float acc[4][4];
        #pragma unroll
        for (int nf = 0; nf < 4; nf++)
            #pragma unroll
            for (int j = 0; j < 4; j++) acc[nf][j] = 0.0f;

        gemm_bf16(sm + MS_A, Bt, acc, mblk, nblk, lane);

        // macc += relw * tanh(acc + b2)
        {
            int r0 = mblk * 16 + gid;
            float relw0 = RelS[r0 * 4 + k];
            float relw1 = RelS[(r0 + 8) * 4 + k];
            #pragma unroll
            for (int nf = 0; nf < 4; nf++) {
                int c = nblk * 32 + nf * 8 + tig * 2;
                float bb0 = b2S[k * 128 + c], bb1 = b2S[k * 128 + c + 1];
                macc[nf][0] += relw0 * ftanha_(acc[nf][0] + bb0);
                macc[nf][1] += relw0 * ftanha_(acc[nf][1] + bb1);
                macc[nf][2] += relw1 * ftanha_(acc[nf][2] + bb0);
                macc[nf][3] += relw1 * ftanha_(acc[nf][3] + bb1);
            }
        }
        __syncthreads();
        if (tid == 0 && k < 2) {
            uint32_t mbn = ((k + 2) & 1) ? mb_t1 : mb_t0;
            uint32_t dst = ((k + 2) & 1) ? (smb + MS_B1) : (smb + MS_B0);
            MBAR_EXPECT_TX(mbn, TILEH_B);
            BULK_CP(dst, (const char*)(g_W2T + (size_t)(k + 2) * 128 * SP), TILEH_B, mbn);
        }
    }

    // stage macc (fp32, stride 132) into B region, then segment-sum
    float* Msm = (float*)(sm + MS_MS);
    {
        int r0 = mblk * 16 + gid;
        #pragma unroll
        for (int nf = 0; nf < 4; nf++) {
            int c = nblk * 32 + nf * 8 + tig * 2;
            *(float2*)&Msm[r0 * 132 + c]       = make_float2(macc[nf][0], macc[nf][1]);
            *(float2*)&Msm[(r0 + 8) * 132 + c] = make_float2(macc[nf][2], macc[nf][3]);
        }
    }
    __syncthreads();
    // partial sums: 8 segments = (receiver, quarter); pad rows are zero (relw=0)
    {
        int h = tid & 127, seg = tid >> 7;
        int rh = seg & 1, part = seg >> 1;
        const float* src = Msm + (rh * 64 + part * 16) * 132 + h;
        float acc = 0.0f;
        #pragma unroll
        for (int r = 0; r < 16; r++) acc += src[r * 132];
        scr[seg * 128 + h] = acc;
    }
    __syncthreads();
    if (tid < 256) {
        int h = tid & 127, rh = tid >> 7;
        float acc = scr[rh * 128 + h] + scr[(2 + rh) * 128 + h]
                  + scr[(4 + rh) * 128 + h] + scr[(6 + rh) * 128 + h];
        int rv = rh ? r1n : r0n;
        g_agg[((size_t)(b * NN + rv)) * HH + h] = acc * (1.0f / 16.0f);
    }
}

// ---------------- NODE kernel ----------------
#define ND_WB0 0
#define ND_WB1 65536
#define ND_AGG 131072
#define ND_HID 135168
#define ND_T1  139264
#define ND_T2  143360
#define ND_INS 147456
#define ND_WIN 147712
#define ND_BIA 153856
#define ND_WO3 156416
#define ND_BO3 158464
#define ND_MB  158480
#define NODE_SMEM 158592

__global__ __launch_bounds__(256)
void node_kernel(const float* __restrict__ data, int step,
                 const float* __restrict__ Wr_h, const float* __restrict__ Wi_h,
                 const float* __restrict__ Wh_h,
                 const float* __restrict__ Wr_in, const float* __restrict__ br_in,
                 const float* __restrict__ Wi_in, const float* __restrict__ bi_in,
                 const float* __restrict__ Wn_in, const float* __restrict__ bn_in,
                 const float* __restrict__ Wo1, const float* __restrict__ bo1,
                 const float* __restrict__ Wo2, const float* __restrict__ bo2,
                 const float* __restrict__ Wo3, const float* __restrict__ bo3,
                 float* __restrict__ out) {
    extern __shared__ char sm[];
    uint32_t smb = smem_u32(sm);
    int q = blockIdx.x, b = blockIdx.y;
    int n0 = q * 8;
    int tid = threadIdx.x;

    float* aggS = (float*)(sm + ND_AGG);
    float* hidS = (float*)(sm + ND_HID);
    float* t1   = (float*)(sm + ND_T1);
    float* t2   = (float*)(sm + ND_T2);
    float* insS = (float*)(sm + ND_INS);
    float* WinS = (float*)(sm + ND_WIN);
    float* biaS = (float*)(sm + ND_BIA);
    float* Wo3S = (float*)(sm + ND_WO3);
    float* bo3S = (float*)(sm + ND_BO3);
    uint32_t mb0 = smb + ND_MB, mb1 = smb + ND_MB + 8;

    if (tid == 0) {
        MBAR_INIT(mb0, 1);
        MBAR_INIT(mb1, 1);
        FENCE_ASYNC();
        MBAR_EXPECT_TX(mb0, 65536);
        BULK_CP(smb + ND_WB0, (const void*)Wr_h, 65536, mb0);
        MBAR_EXPECT_TX(mb1, 65536);
        BULK_CP(smb + ND_WB1, (const void*)Wi_h, 65536, mb1);
    }
    {
        const float* ag = g_agg    + ((size_t)(b * NN + n0)) * HH;
        const float* hg = g_hidden + ((size_t)(b * NN + n0)) * HH;
        ((float4*)aggS)[tid] = ((const float4*)ag)[tid];
        ((float4*)hidS)[tid] = ((const float4*)hg)[tid];
    }
    if (tid < 32) {
        int n = tid >> 2, d = tid & 3;
        float v;
        if (step < TT) v = data[(((size_t)(b * NN + n0 + n)) * DD + d) * TT + step];
        else           v = g_pred[(b * NN + n0 + n) * DD + d];
        insS[tid] = v;
    }
    for (int i = tid; i < 512; i += 256) {
        WinS[i]        = Wr_in[i];
        WinS[512 + i]  = Wi_in[i];
        WinS[1024 + i] = Wn_in[i];
        Wo3S[i]        = Wo3[i];
    }
    if (tid < 128) {
        biaS[tid]       = br_in[tid];
        biaS[128 + tid] = bi_in[tid];
        biaS[256 + tid] = bn_in[tid];
        biaS[384 + tid] = bo1[tid];
        biaS[512 + tid] = bo2[tid];
    }
    if (tid < 4) bo3S[tid] = bo3[tid];
    __syncthreads();

    int h = tid & 127, ng = (tid >> 7) * 4;

    #define GEMV4(ACT, WB, OUTARR) do { \
        const float* _wb = (WB); \
        _Pragma("unroll") \
        for (int nn = 0; nn < 4; nn++) { \
            const float* av = (ACT) + (ng + nn) * 128; \
            float a = 0.0f; \
            _Pragma("unroll 8") \
            for (int f4 = 0; f4 < 32; f4++) { \
                float4 x = ((const float4*)av)[f4]; \
                a += x.x * _wb[(f4*4+0)*128 + h] + x.y * _wb[(f4*4+1)*128 + h] \
                   + x.z * _wb[(f4*4+2)*128 + h] + x.w * _wb[(f4*4+3)*128 + h]; \
            } \
            (OUTARR)[nn] = a; \
        } \
    } while (0)

    float acc[4];
    float rr[4], ii[4];

    MBAR_WAIT(mb0, 0);
    GEMV4(aggS, (const float*)(sm + ND_WB0), acc);
    #pragma unroll
    for (int nn = 0; nn < 4; nn++) {
        int n = ng + nn;
        float a = acc[nn] + biaS[h];
        #pragma unroll
        for (int d = 0; d < 4; d++) a += insS[n*4+d] * WinS[d*128 + h];
        t1[n*128 + h] = fsig_(a);
    }
    __syncthreads();
    if (tid == 0) { MBAR_EXPECT_TX(mb0, 65536); BULK_CP(smb + ND_WB0, (const void*)Wh_h, 65536, mb0); }

    MBAR_WAIT(mb1, 0);
    GEMV4(aggS, (const float*)(sm + ND_WB1), acc);
    #pragma unroll
    for (int nn = 0; nn < 4; nn++) {
        int n = ng + nn;
        float a = acc[nn] + biaS[128 + h];
        #pragma unroll
        for (int d = 0; d < 4; d++) a += insS[n*4+d] * WinS[512 + d*128 + h];
        ii[nn] = fsig_(a);
        rr[nn] = t1[n*128 + h];
    }
    __syncthreads();
    if (tid == 0) { MBAR_EXPECT_TX(mb1, 65536); BULK_CP(smb + ND_WB1, (const void*)Wo1, 65536, mb1); }

    MBAR_WAIT(mb0, 1);
    GEMV4(aggS, (const float*)(sm + ND_WB0), acc);
    #pragma unroll
    for (int nn = 0; nn < 4; nn++) {
        int n = ng + nn;
        float a = biaS[256 + h];
        #pragma unroll
        for (int d = 0; d < 4; d++) a += insS[n*4+d] * WinS[1024 + d*128 + h];
        float nv = ftanh_(a + rr[nn] * acc[nn]);
        float hn = (1.0f - ii[nn]) * nv + ii[nn] * hidS[n*128 + h];
        hidS[n*128 + h] = hn;
        g_hidden[((size_t)(b * NN + n0 + n)) * HH + h] = hn;
    }
    __syncthreads();
    if (tid == 0) { MBAR_EXPECT_TX(mb0, 65536); BULK_CP(smb + ND_WB0, (const void*)Wo2, 65536, mb0); }

    MBAR_WAIT(mb1, 1);
    GEMV4(hidS, (const float*)(sm + ND_WB1), acc);
    #pragma unroll
    for (int nn = 0; nn < 4; nn++)
        t1[(ng+nn)*128 + h] = fmaxf(acc[nn] + biaS[384 + h], 0.0f);
    __syncthreads();

    MBAR_WAIT(mb0, 0);
    GEMV4(t1, (const float*)(sm + ND_WB0), acc);
    #pragma unroll
    for (int nn = 0; nn < 4; nn++)
        t2[(ng+nn)*128 + h] = fmaxf(acc[nn] + biaS[512 + h], 0.0f);
    __syncthreads();

    if (tid < 32) {
        int n = tid >> 2, d = tid & 3;
        float a = bo3S[d];
        const float* vv = t2 + n*128;
        #pragma unroll 8
        for (int hh = 0; hh < 128; hh++) a += vv[hh] * Wo3S[hh*4 + d];
        float pred = insS[tid] + a;
        g_pred[(b * NN + n0 + n) * DD + d] = pred;
        if (step >= TT)
            out[(((size_t)(b * NN + n0 + n)) * DD + d) * LL + (step - TT)] = pred;
    }
    #undef GEMV4
}

// ---------------- launch ----------------
extern "C" void kernel_launch(void* const* d_in, const int* in_sizes, int n_in,
                              void* d_out, int out_size) {
    const float* data  = (const float*)d_in[0];
    const float* rel   = (const float*)d_in[1];
    const float* W1    = (const float*)d_in[2];
    const float* b1    = (const float*)d_in[3];
    const float* W2    = (const float*)d_in[4];
    const float* b2    = (const float*)d_in[5];
    const float* Wr_h  = (const float*)d_in[6];
    const float* Wi_h  = (const float*)d_in[7];
    const float* Wh_h  = (const float*)d_in[8];
    const float* Wr_in = (const float*)d_in[9];
    const float* br_in = (const float*)d_in[10];
    const float* Wi_in = (const float*)d_in[11];
    const float* bi_in = (const float*)d_in[12];
    const float* Wn_in = (const float*)d_in[13];
    const float* bn_in = (const float*)d_in[14];
    const float* Wo1   = (const float*)d_in[15];
    const float* bo1   = (const float*)d_in[16];
    const float* Wo2   = (const float*)d_in[17];
    const float* bo2   = (const float*)d_in[18];
    const float* Wo3   = (const float*)d_in[19];
    const float* bo3   = (const float*)d_in[20];
    const int* recv_idx = (const int*)d_in[21];
    const int* send_idx = (const int*)d_in[22];
    float* out = (float*)d_out;

    cudaFuncSetAttribute(uv_kernel,   cudaFuncAttributeMaxDynamicSharedMemorySize, UV_SMEM);
    cudaFuncSetAttribute(msg_kernel,  cudaFuncAttributeMaxDynamicSharedMemorySize, MSG_SMEM);
    cudaFuncSetAttribute(node_kernel, cudaFuncAttributeMaxDynamicSharedMemorySize, NODE_SMEM);

    init_kernel<<<512, 256>>>();
    prep_kernel<<<12, 256>>>(W1, W2);
    for (int s = 0; s < TT + LL; s++) {
        uv_kernel<<<dim3(8, 8), 512, UV_SMEM>>>();
        msg_kernel<<<dim3(32, BB), 1024, MSG_SMEM>>>(b1, b2, rel, recv_idx, send_idx);
        node_kernel<<<dim3(8, BB), 256, NODE_SMEM>>>(data, s,
            Wr_h, Wi_h, Wh_h, Wr_in, br_in, Wi_in, bi_in, Wn_in, bn_in,
            Wo1, bo1, Wo2, bo2, Wo3, bo3, out);
    }
}

// round 9
// speedup vs baseline: 4.2552x; 1.1430x over previous
#include <cuda_runtime.h>
#include <cuda_bf16.h>
#include <stdint.h>
#include <math.h>

#define BB 16
#define NN 64
#define DD 4
#define TT 40
#define LL 10
#define HH 128
#define KK 4
#define EE (NN*(NN-1))

// fp32 tile (uv): 128 x 132 words
#define SPW  132
#define TILEF_B (128*SPW*4)   // 67584
// bf16 tile (msg): 128 x 136 halves (272 B/row)
#define SP   136
#define SPB  272
#define TILEH_B (128*SPB)     // 34816

// ---------------- persistent device state ----------------
__device__ float g_hidden[BB*NN*HH];
__device__ float g_pred[BB*NN*DD];
__device__ __align__(16) __nv_bfloat16 g_uv[BB*8*NN*HH];  // [B][ks][N][H] bf16
__device__ float g_agg[BB*NN*HH];
__device__ __align__(16) float g_W1T[8*128*SPW];          // fp32 [ks][128][132]
__device__ __align__(16) __nv_bfloat16 g_W2T[4*128*SP];   // bf16 [k][128][136]

// ---------------- PTX helpers ----------------
__device__ __forceinline__ uint32_t smem_u32(const void* p) {
    uint32_t a;
    asm("{ .reg .u64 t; cvta.to.shared.u64 t, %1; cvt.u32.u64 %0, t; }" : "=r"(a) : "l"(p));
    return a;
}
#define MBAR_INIT(mb, c)  asm volatile("mbarrier.init.shared.b64 [%0], %1;" :: "r"(mb), "r"(c) : "memory")
#define MBAR_EXPECT_TX(mb, n) asm volatile("mbarrier.arrive.expect_tx.shared.b64 _, [%0], %1;" :: "r"(mb), "r"(n) : "memory")
#define FENCE_ASYNC()     asm volatile("fence.proxy.async.shared::cta;" ::: "memory")
#define BULK_CP(dst, src, bytes, mb) \
    asm volatile("cp.async.bulk.shared::cta.global.mbarrier::complete_tx::bytes [%0], [%1], %2, [%3];" \
        :: "r"(dst), "l"(src), "r"(bytes), "r"(mb) : "memory")

#define MBAR_WAIT(mb, ph) do { \
    uint32_t _m = (mb); uint32_t _p = (ph); uint32_t _d; \
    asm volatile("{\n\t.reg .pred p;\n\tmbarrier.try_wait.parity.acquire.cta.shared::cta.b64 p, [%1], %2;\n\tselp.b32 %0, 1, 0, p;\n\t}" \
        : "=r"(_d) : "r"(_m), "r"(_p) : "memory"); \
    if (!_d) { \
        asm volatile("{\n\t.reg .pred P1;\n\tWL_%=:\n\tmbarrier.try_wait.parity.acquire.cta.shared::cta.b64 P1, [%0], %1, 0x989680;\n\t@P1 bra.uni WD_%=;\n\tbra.uni WL_%=;\n\tWD_%=:\n\t}" \
            :: "r"(_m), "r"(_p) : "memory"); \
    } \
} while (0)

#define BAR_SYNC_N(id, cnt)   asm volatile("bar.sync %0, %1;"   :: "r"(id), "r"(cnt) : "memory")
#define BAR_ARRIVE_N(id, cnt) asm volatile("bar.arrive %0, %1;" :: "r"(id), "r"(cnt) : "memory")
#define MEMBAR_CTA()          asm volatile("membar.cta;" ::: "memory")

// tf32 mma m16n8k8
__device__ __forceinline__ void mma_tf32(float d[4], uint32_t a0, uint32_t a1, uint32_t a2, uint32_t a3,
                                         uint32_t b0, uint32_t b1) {
    asm volatile("mma.sync.aligned.m16n8k8.row.col.f32.tf32.tf32.f32 "
        "{%0,%1,%2,%3}, {%4,%5,%6,%7}, {%8,%9}, {%0,%1,%2,%3};"
        : "+f"(d[0]), "+f"(d[1]), "+f"(d[2]), "+f"(d[3])
        : "r"(a0), "r"(a1), "r"(a2), "r"(a3), "r"(b0), "r"(b1));
}
// bf16 mma m16n8k16
__device__ __forceinline__ void mma_bf16(float d[4], uint32_t a0, uint32_t a1, uint32_t a2, uint32_t a3,
                                         uint32_t b0, uint32_t b1) {
    asm volatile("mma.sync.aligned.m16n8k16.row.col.f32.bf16.bf16.f32 "
        "{%0,%1,%2,%3}, {%4,%5,%6,%7}, {%8,%9}, {%0,%1,%2,%3};"
        : "+f"(d[0]), "+f"(d[1]), "+f"(d[2]), "+f"(d[3])
        : "r"(a0), "r"(a1), "r"(a2), "r"(a3), "r"(b0), "r"(b1));
}

// tf32 GEMM (uv): 16 warps, warp tile 32m x 32n
__device__ __forceinline__ void gemm_tf32(const float* __restrict__ A, const float* __restrict__ B,
                                          float acc[2][4][4], int mblk, int nblk, int lane) {
    int gid = lane >> 2, tig = lane & 3;
    const float* ap0 = A + (mblk * 32 + gid) * SPW + tig;
    const float* bp0 = B + (nblk * 32 + gid) * SPW + tig;
    #pragma unroll
    for (int ks = 0; ks < 16; ks++) {
        int k0 = ks * 8;
        uint32_t a[2][4];
        #pragma unroll
        for (int mf = 0; mf < 2; mf++) {
            const float* ap = ap0 + mf * 16 * SPW + k0;
            a[mf][0] = __float_as_uint(ap[0]);
            a[mf][1] = __float_as_uint(ap[8 * SPW]);
            a[mf][2] = __float_as_uint(ap[4]);
            a[mf][3] = __float_as_uint(ap[8 * SPW + 4]);
        }
        #pragma unroll
        for (int nf = 0; nf < 4; nf++) {
            const float* bp = bp0 + nf * 8 * SPW + k0;
            uint32_t b0 = __float_as_uint(bp[0]);
            uint32_t b1 = __float_as_uint(bp[4]);
            mma_tf32(acc[0][nf], a[0][0], a[0][1], a[0][2], a[0][3], b0, b1);
            mma_tf32(acc[1][nf], a[1][0], a[1][1], a[1][2], a[1][3], b0, b1);
        }
    }
}

// bf16 GEMM (msg): 16 compute warps, warp tile 32m x 32n
__device__ __forceinline__ void gemm_bf16_2(const char* __restrict__ A, const char* __restrict__ B,
                                            float acc[2][4][4], int mblk, int nblk, int lane) {
    int gid = lane >> 2, tig = lane & 3;
    const char* ap0 = A + (mblk * 32 + gid) * SPB + tig * 4;
    const char* bp0 = B + (nblk * 32 + gid) * SPB + tig * 4;
    #pragma unroll
    for (int ks = 0; ks < 8; ks++) {
        int kb = ks * 32;
        uint32_t a[2][4];
        #pragma unroll
        for (int mf = 0; mf < 2; mf++) {
            const char* ap = ap0 + mf * 16 * SPB + kb;
            a[mf][0] = *(const uint32_t*)ap;
            a[mf][1] = *(const uint32_t*)(ap + 8 * SPB);
            a[mf][2] = *(const uint32_t*)(ap + 16);
            a[mf][3] = *(const uint32_t*)(ap + 8 * SPB + 16);
        }
        #pragma unroll
        for (int nf = 0; nf < 4; nf++) {
            const char* bp = bp0 + nf * 8 * SPB + kb;
            uint32_t b0 = *(const uint32_t*)bp;
            uint32_t b1 = *(const uint32_t*)(bp + 16);
            mma_bf16(acc[0][nf], a[0][0], a[0][1], a[0][2], a[0][3], b0, b1);
            mma_bf16(acc[1][nf], a[1][0], a[1][1], a[1][2], a[1][3], b0, b1);
        }
    }
}

// ---------------- fast math ----------------
__device__ __forceinline__ float fex2_(float x) { float r; asm("ex2.approx.f32 %0, %1;" : "=f"(r) : "f"(x)); return r; }
__device__ __forceinline__ float frcp_(float x) { float r; asm("rcp.approx.f32 %0, %1;" : "=f"(r) : "f"(x)); return r; }
__device__ __forceinline__ float ftanh_(float x) { return fmaf(-2.0f, frcp_(fex2_(x * 2.885390081777927f) + 1.0f), 1.0f); }
__device__ __forceinline__ float fsig_(float x)  { return frcp_(1.0f + fex2_(-1.4426950408889634f * x)); }
__device__ __forceinline__ float ftanha_(float x){ float r; asm("tanh.approx.f32 %0, %1;" : "=f"(r) : "f"(x)); return r; }

// ---------------- init ----------------
__global__ void init_kernel() {
    int i = blockIdx.x * blockDim.x + threadIdx.x;
    if (i < BB*NN*HH) g_hidden[i] = 0.0f;
    if (i < BB*NN*DD) g_pred[i]   = 0.0f;
}

// ---------------- prep ----------------
__global__ __launch_bounds__(256)
void prep_kernel(const float* __restrict__ W1, const float* __restrict__ W2) {
    int s = blockIdx.x;
    if (s < 8) {
        const float* src = W1 + s * 16384;
        float* dst = g_W1T + s * 128 * SPW;
        for (int t = threadIdx.x; t < 16384; t += 256) {
            int n = t >> 7, f = t & 127;
            dst[n * SPW + f] = src[f * 128 + n];
        }
    } else {
        const float* src = W2 + (s - 8) * 16384;
        __nv_bfloat16* dst = g_W2T + (s - 8) * 128 * SP;
        for (int t = threadIdx.x; t < 16384; t += 256) {
            int n = t >> 7, f = t & 127;
            dst[n * SP + f] = __float2bfloat16_rn(src[f * 128 + n]);
        }
    }
}

// ---------------- UV: tf32 GEMM, bf16 output ----------------
#define UV_A  0
#define UV_B  TILEF_B
#define UV_MB (2*TILEF_B)
#define UV_SMEM (UV_MB + 32)

__global__ __launch_bounds__(512)
void uv_kernel() {
    extern __shared__ char sm[];
    uint32_t smb = smem_u32(sm);
    int tid = threadIdx.x;
    int ks = blockIdx.x, bp = blockIdx.y;
    uint32_t mbt = smb + UV_MB;
    float* A = (float*)(sm + UV_A);
    const float* Bt = (const float*)(sm + UV_B);

    if (tid == 0) {
        MBAR_INIT(mbt, 1);
        FENCE_ASYNC();
        MBAR_EXPECT_TX(mbt, TILEF_B);
        BULK_CP(smb + UV_B, (const char*)(g_W1T + (size_t)ks * 128 * SPW), TILEF_B, mbt);
    }
    for (int idx = tid; idx < 128 * 32; idx += 512) {
        int row = idx >> 5, f4 = (idx & 31) * 4;
        int b = bp * 2 + (row >> 6), node = row & 63;
        float4 v = *(const float4*)(g_hidden + ((size_t)(b * NN + node)) * HH + f4);
        *(float4*)&A[row * SPW + f4] = v;
    }
    __syncthreads();
    MBAR_WAIT(mbt, 0);

    int w = tid >> 5, lane = tid & 31;
    int mblk = w & 3, nblk = w >> 2;
    int gid = lane >> 2, tig = lane & 3;

    float acc[2][4][4];
    #pragma unroll
    for (int mf = 0; mf < 2; mf++)
        #pragma unroll
        for (int nf = 0; nf < 4; nf++)
            #pragma unroll
            for (int j = 0; j < 4; j++) acc[mf][nf][j] = 0.0f;

    gemm_tf32(A, Bt, acc, mblk, nblk, lane);
    __syncthreads();

    #pragma unroll
    for (int mf = 0; mf < 2; mf++) {
        int r0 = mblk * 32 + mf * 16 + gid;
        #pragma unroll
        for (int nf = 0; nf < 4; nf++) {
            int c = nblk * 32 + nf * 8 + tig * 2;
            *(float2*)&A[r0 * SPW + c]       = make_float2(acc[mf][nf][0], acc[mf][nf][1]);
            *(float2*)&A[(r0 + 8) * SPW + c] = make_float2(acc[mf][nf][2], acc[mf][nf][3]);
        }
    }
    __syncthreads();
    for (int idx = tid; idx < 128 * 16; idx += 512) {
        int row = idx >> 4, c8 = (idx & 15) * 8;
        float4 v0 = *(const float4*)&A[row * SPW + c8];
        float4 v1 = *(const float4*)&A[row * SPW + c8 + 4];
        __nv_bfloat162 p0 = __floats2bfloat162_rn(v0.x, v0.y);
        __nv_bfloat162 p1 = __floats2bfloat162_rn(v0.z, v0.w);
        __nv_bfloat162 p2 = __floats2bfloat162_rn(v1.x, v1.y);
        __nv_bfloat162 p3 = __floats2bfloat162_rn(v1.z, v1.w);
        int b = bp * 2 + (row >> 6), node = row & 63;
        __nv_bfloat162* dst = (__nv_bfloat162*)(g_uv + ((size_t)(b * 8 + ks) * 64 + node) * 128 + c8);
        dst[0] = p0; dst[1] = p1; dst[2] = p2; dst[3] = p3;
    }
}

// ---------------- MSG kernel: warp-specialized producer/consumer ----------------
#define MS_A0  0
#define MS_A1  34816
#define MS_B0  69632
#define MS_B1  104448
#define MS_U0  139264
#define MS_U1  155648
#define MS_REL 172032
#define MS_SEND 174080
#define MS_B1S 174592
#define MS_B2S 176640
#define MS_VS  178688      /* [4][2][128] f = 4096 */
#define MS_SCR 182784      /* [4][128]    f = 2048 */
#define MS_MB  184832      /* bbar0 bbar1 ubar0 ubar1 */
#define MSG_SMEM 184864

__global__ __launch_bounds__(1024, 1)
void msg_kernel(const float* __restrict__ b1, const float* __restrict__ b2,
                const float* __restrict__ rel,
                const int* __restrict__ recv_idx, const int* __restrict__ send_idx) {
    extern __shared__ char sm[];
    uint32_t smb = smem_u32(sm);
    int tid = threadIdx.x;
    int p = blockIdx.x, b = blockIdx.y;

    float* RelS  = (float*)(sm + MS_REL);
    int*   SendS = (int*)(sm + MS_SEND);
    float* b1S   = (float*)(sm + MS_B1S);
    float* b2S   = (float*)(sm + MS_B2S);
    float* vS    = (float*)(sm + MS_VS);
    float* scr   = (float*)(sm + MS_SCR);
    uint32_t bbar0 = smb + MS_MB, bbar1 = smb + MS_MB + 8;
    uint32_t ubar0 = smb + MS_MB + 16, ubar1 = smb + MS_MB + 24;

    if (tid == 0) {
        MBAR_INIT(bbar0, 1); MBAR_INIT(bbar1, 1);
        MBAR_INIT(ubar0, 1); MBAR_INIT(ubar1, 1);
        FENCE_ASYNC();
        MBAR_EXPECT_TX(bbar0, TILEH_B);
        BULK_CP(smb + MS_B0, (const char*)(g_W2T + 0), TILEH_B, bbar0);
        MBAR_EXPECT_TX(bbar1, TILEH_B);
        BULK_CP(smb + MS_B1, (const char*)(g_W2T + 128 * SP), TILEH_B, bbar1);
        MBAR_EXPECT_TX(ubar0, 16384);
        BULK_CP(smb + MS_U0, (const char*)(g_uv + (size_t)(b * 8 + 0) * 8192), 16384, ubar0);
        MBAR_EXPECT_TX(ubar1, 16384);
        BULK_CP(smb + MS_U1, (const char*)(g_uv + (size_t)(b * 8 + 2) * 8192), 16384, ubar1);
    }
    if (tid < 128) {
        int row = tid;
        float r0 = 0, r1 = 0, r2 = 0, r3 = 0;
        int sn = 0;
        if (row != 63 && row != 127) {
            int e = (row < 64) ? (p * 126 + row) : (p * 126 + row - 1);
            sn = send_idx[e];
            const float* rp = rel + ((size_t)(b * EE + e)) * KK;
            r0 = rp[0]; r1 = rp[1]; r2 = rp[2]; r3 = rp[3];
        }
        SendS[row] = sn;
        RelS[row * 4 + 0] = r0; RelS[row * 4 + 1] = r1;
        RelS[row * 4 + 2] = r2; RelS[row * 4 + 3] = r3;
        #pragma unroll
        for (int k = 0; k < 4; k++) {
            b1S[k * 128 + tid] = b1[k * 128 + tid];
            b2S[k * 128 + tid] = b2[k * 128 + tid];
        }
    }
    int r0n = recv_idx[p * 126];
    int r1n = recv_idx[p * 126 + 63];
    __syncthreads();
    // vS[k][rh][f] = float(v_k[recv_rh][f]) + b1[k][f]  (one element per thread)
    {
        int k = tid >> 8, rh = (tid >> 7) & 1, f = tid & 127;
        int rv = rh ? r1n : r0n;
        const __nv_bfloat16* v = g_uv + ((size_t)(b * 8 + 2 * k + 1)) * 8192 + rv * 128;
        vS[tid] = __bfloat162float(v[f]) + b1S[k * 128 + f];
    }
    __syncthreads();

    if (tid >= 512) {
        // ================= BUILDER warps (16) =================
        int btid = tid - 512;
        for (int j = 0; j < 4; j++) {
            if (j >= 2) BAR_SYNC_N(3 + (j & 1), 1024);          // A buffer free
            MBAR_WAIT((j & 1) ? ubar1 : ubar0, j >> 1);         // u tile ready
            const __nv_bfloat16* U = (const __nv_bfloat16*)(sm + ((j & 1) ? MS_U1 : MS_U0));
            char* Ab = sm + ((j & 1) ? MS_A1 : MS_A0);
            const float* vj = vS + j * 256;
            for (int idx = btid; idx < 128 * 32; idx += 512) {
                int row = idx >> 5, f4 = (idx & 31) * 4;
                uint32_t o01 = 0, o23 = 0;
                if (row != 63 && row != 127) {
                    int sn = SendS[row], rh = row >> 6;
                    uint2 q = *(const uint2*)(U + sn * 128 + f4);
                    float2 f0 = __bfloat1622float2(*(__nv_bfloat162*)&q.x);
                    float2 f1 = __bfloat1622float2(*(__nv_bfloat162*)&q.y);
                    const float* vv = vj + rh * 128 + f4;
                    __nv_bfloat162 p0 = __floats2bfloat162_rn(ftanha_(f0.x + vv[0]), ftanha_(f0.y + vv[1]));
                    __nv_bfloat162 p1 = __floats2bfloat162_rn(ftanha_(f1.x + vv[2]), ftanha_(f1.y + vv[3]));
                    o01 = *(uint32_t*)&p0; o23 = *(uint32_t*)&p1;
                }
                *(uint2*)(Ab + row * SPB + f4 * 2) = make_uint2(o01, o23);
            }
            MEMBAR_CTA();
            BAR_ARRIVE_N(1 + (j & 1), 1024);                    // A(j) ready
            BAR_SYNC_N(5, 512);                                  // builders done with ubuf
            if (btid == 0 && j < 2) {
                uint32_t ub = (j & 1) ? ubar1 : ubar0;
                uint32_t ud = (j & 1) ? (smb + MS_U1) : (smb + MS_U0);
                MBAR_EXPECT_TX(ub, 16384);
                BULK_CP(ud, (const char*)(g_uv + (size_t)(b * 8 + 2 * (j + 2)) * 8192), 16384, ub);
            }
        }
    } else {
        // ================= COMPUTE warps (16) =================
        int w = tid >> 5, lane = tid & 31;
        int mblk = w & 3, nblk = w >> 2;
        int gid = lane >> 2, tig = lane & 3;

        float sum[4][2];
        #pragma unroll
        for (int nf = 0; nf < 4; nf++) { sum[nf][0] = 0.0f; sum[nf][1] = 0.0f; }

        for (int k = 0; k < 4; k++) {
            BAR_SYNC_N(1 + (k & 1), 1024);                      // A(k) ready
            MBAR_WAIT((k & 1) ? bbar1 : bbar0, k >> 1);         // B(k) ready
            const char* Ab = sm + ((k & 1) ? MS_A1 : MS_A0);
            const char* Bt = sm + ((k & 1) ? MS_B1 : MS_B0);

            float acc[2][4][4];
            #pragma unroll
            for (int mf = 0; mf < 2; mf++)
                #pragma unroll
                for (int nf = 0; nf < 4; nf++)
                    #pragma unroll
                    for (int j = 0; j < 4; j++) acc[mf][nf][j] = 0.0f;

            gemm_bf16_2(Ab, Bt, acc, mblk, nblk, lane);

            // fused epilogue + row-sum: sum over this warp's 4 row-groups
            int r0 = mblk * 32 + gid;
            float rw0 = RelS[r0 * 4 + k];
            float rw1 = RelS[(r0 + 8) * 4 + k];
            float rw2 = RelS[(r0 + 16) * 4 + k];
            float rw3 = RelS[(r0 + 24) * 4 + k];
            #pragma unroll
            for (int nf = 0; nf < 4; nf++) {
                int c = nblk * 32 + nf * 8 + tig * 2;
                float bb0 = b2S[k * 128 + c], bb1 = b2S[k * 128 + c + 1];
                sum[nf][0] += rw0 * ftanha_(acc[0][nf][0] + bb0)
                            + rw1 * ftanha_(acc[0][nf][2] + bb0)
                            + rw2 * ftanha_(acc[1][nf][0] + bb0)
                            + rw3 * ftanha_(acc[1][nf][2] + bb0);
                sum[nf][1] += rw0 * ftanha_(acc[0][nf][1] + bb1)
                            + rw1 * ftanha_(acc[0][nf][3] + bb1)
                            + rw2 * ftanha_(acc[1][nf][1] + bb1)
                            + rw3 * ftanha_(acc[1][nf][3] + bb1);
            }
            BAR_ARRIVE_N(3 + (k & 1), 1024);                    // A buffer free
            BAR_SYNC_N(6, 512);                                  // compute internal (B buf free)
            if (tid == 0 && k < 2) {
                uint32_t bb = (k & 1) ? bbar1 : bbar0;
                uint32_t bd = (k & 1) ? (smb + MS_B1) : (smb + MS_B0);
                MBAR_EXPECT_TX(bb, TILEH_B);
                BULK_CP(bd, (const char*)(g_W2T + (size_t)(k + 2) * 128 * SP), TILEH_B, bb);
            }
        }
        // reduce over gid lanes (rows of warp tile)
        #pragma unroll
        for (int off = 16; off >= 4; off >>= 1)
            #pragma unroll
            for (int nf = 0; nf < 4; nf++) {
                sum[nf][0] += __shfl_down_sync(0xffffffffu, sum[nf][0], off);
                sum[nf][1] += __shfl_down_sync(0xffffffffu, sum[nf][1], off);
            }
        if (gid == 0) {
            #pragma unroll
            for (int nf = 0; nf < 4; nf++) {
                int c = nblk * 32 + nf * 8 + tig * 2;
                *(float2*)&scr[mblk * 128 + c] = make_float2(sum[nf][0], sum[nf][1]);
            }
        }
    }
    __syncthreads();
    if (tid < 256) {
        int h = tid & 127, rh = tid >> 7;
        float a = scr[(rh * 2) * 128 + h] + scr[(rh * 2 + 1) * 128 + h];
        int rv = rh ? r1n : r0n;
        g_agg[((size_t)(b * NN + rv)) * HH + h] = a * (1.0f / 16.0f);
    }
}

// ---------------- NODE kernel ----------------
#define ND_WB0 0
#define ND_WB1 65536
#define ND_AGG 131072
#define ND_HID 135168
#define ND_T1  139264
#define ND_T2  143360
#define ND_INS 147456
#define ND_WIN 147712
#define ND_BIA 153856
#define ND_WO3 156416
#define ND_BO3 158464
#define ND_MB  158480
#define NODE_SMEM 158592

__global__ __launch_bounds__(256)
void node_kernel(const float* __restrict__ data, int step,
                 const float* __restrict__ Wr_h, const float* __restrict__ Wi_h,
                 const float* __restrict__ Wh_h,
                 const float* __restrict__ Wr_in, const float* __restrict__ br_in,
                 const float* __restrict__ Wi_in, const float* __restrict__ bi_in,
                 const float* __restrict__ Wn_in, const float* __restrict__ bn_in,
                 const float* __restrict__ Wo1, const float* __restrict__ bo1,
                 const float* __restrict__ Wo2, const float* __restrict__ bo2,
                 const float* __restrict__ Wo3, const float* __restrict__ bo3,
                 float* __restrict__ out) {
    extern __shared__ char sm[];
    uint32_t smb = smem_u32(sm);
    int q = blockIdx.x, b = blockIdx.y;
    int n0 = q * 8;
    int tid = threadIdx.x;

    float* aggS = (float*)(sm + ND_AGG);
    float* hidS = (float*)(sm + ND_HID);
    float* t1   = (float*)(sm + ND_T1);
    float* t2   = (float*)(sm + ND_T2);
    float* insS = (float*)(sm + ND_INS);
    float* WinS = (float*)(sm + ND_WIN);
    float* biaS = (float*)(sm + ND_BIA);
    float* Wo3S = (float*)(sm + ND_WO3);
    float* bo3S = (float*)(sm + ND_BO3);
    uint32_t mb0 = smb + ND_MB, mb1 = smb + ND_MB + 8;

    if (tid == 0) {
        MBAR_INIT(mb0, 1);
        MBAR_INIT(mb1, 1);
        FENCE_ASYNC();
        MBAR_EXPECT_TX(mb0, 65536);
        BULK_CP(smb + ND_WB0, (const void*)Wr_h, 65536, mb0);
        MBAR_EXPECT_TX(mb1, 65536);
        BULK_CP(smb + ND_WB1, (const void*)Wi_h, 65536, mb1);
    }
    {
        const float* ag = g_agg    + ((size_t)(b * NN + n0)) * HH;
        const float* hg = g_hidden + ((size_t)(b * NN + n0)) * HH;
        ((float4*)aggS)[tid] = ((const float4*)ag)[tid];
        ((float4*)hidS)[tid] = ((const float4*)hg)[tid];
    }
    if (tid < 32) {
        int n = tid >> 2, d = tid & 3;
        float v;
        if (step < TT) v = data[(((size_t)(b * NN + n0 + n)) * DD + d) * TT + step];
        else           v = g_pred[(b * NN + n0 + n) * DD + d];
        insS[tid] = v;
    }
    for (int i = tid; i < 512; i += 256) {
        WinS[i]        = Wr_in[i];
        WinS[512 + i]  = Wi_in[i];
        WinS[1024 + i] = Wn_in[i];
        Wo3S[i]        = Wo3[i];
    }
    if (tid < 128) {
        biaS[tid]       = br_in[tid];
        biaS[128 + tid] = bi_in[tid];
        biaS[256 + tid] = bn_in[tid];
        biaS[384 + tid] = bo1[tid];
        biaS[512 + tid] = bo2[tid];
    }
    if (tid < 4) bo3S[tid] = bo3[tid];
    __syncthreads();

    int h = tid & 127, ng = (tid >> 7) * 4;

    #define GEMV4(ACT, WB, OUTARR) do { \
        const float* _wb = (WB); \
        _Pragma("unroll") \
        for (int nn = 0; nn < 4; nn++) { \
            const float* av = (ACT) + (ng + nn) * 128; \
            float a = 0.0f; \
            _Pragma("unroll 8") \
            for (int f4 = 0; f4 < 32; f4++) { \
                float4 x = ((const float4*)av)[f4]; \
                a += x.x * _wb[(f4*4+0)*128 + h] + x.y * _wb[(f4*4+1)*128 + h] \
                   + x.z * _wb[(f4*4+2)*128 + h] + x.w * _wb[(f4*4+3)*128 + h]; \
            } \
            (OUTARR)[nn] = a; \
        } \
    } while (0)

    float acc[4];
    float rr[4], ii[4];

    MBAR_WAIT(mb0, 0);
    GEMV4(aggS, (const float*)(sm + ND_WB0), acc);
    #pragma unroll
    for (int nn = 0; nn < 4; nn++) {
        int n = ng + nn;
        float a = acc[nn] + biaS[h];
        #pragma unroll
        for (int d = 0; d < 4; d++) a += insS[n*4+d] * WinS[d*128 + h];
        t1[n*128 + h] = fsig_(a);
    }
    __syncthreads();
    if (tid == 0) { MBAR_EXPECT_TX(mb0, 65536); BULK_CP(smb + ND_WB0, (const void*)Wh_h, 65536, mb0); }

    MBAR_WAIT(mb1, 0);
    GEMV4(aggS, (const float*)(sm + ND_WB1), acc);
    #pragma unroll
    for (int nn = 0; nn < 4; nn++) {
        int n = ng + nn;
        float a = acc[nn] + biaS[128 + h];
        #pragma unroll
        for (int d = 0; d < 4; d++) a += insS[n*4+d] * WinS[512 + d*128 + h];
        ii[nn] = fsig_(a);
        rr[nn] = t1[n*128 + h];
    }
    __syncthreads();
    if (tid == 0) { MBAR_EXPECT_TX(mb1, 65536); BULK_CP(smb + ND_WB1, (const void*)Wo1, 65536, mb1); }

    MBAR_WAIT(mb0, 1);
    GEMV4(aggS, (const float*)(sm + ND_WB0), acc);
    #pragma unroll
    for (int nn = 0; nn < 4; nn++) {
        int n = ng + nn;
        float a = biaS[256 + h];
        #pragma unroll
        for (int d = 0; d < 4; d++) a += insS[n*4+d] * WinS[1024 + d*128 + h];
        float nv = ftanh_(a + rr[nn] * acc[nn]);
        float hn = (1.0f - ii[nn]) * nv + ii[nn] * hidS[n*128 + h];
        hidS[n*128 + h] = hn;
        g_hidden[((size_t)(b * NN + n0 + n)) * HH + h] = hn;
    }
    __syncthreads();
    if (tid == 0) { MBAR_EXPECT_TX(mb0, 65536); BULK_CP(smb + ND_WB0, (const void*)Wo2, 65536, mb0); }

    MBAR_WAIT(mb1, 1);
    GEMV4(hidS, (const float*)(sm + ND_WB1), acc);
    #pragma unroll
    for (int nn = 0; nn < 4; nn++)
        t1[(ng+nn)*128 + h] = fmaxf(acc[nn] + biaS[384 + h], 0.0f);
    __syncthreads();

    MBAR_WAIT(mb0, 0);
    GEMV4(t1, (const float*)(sm + ND_WB0), acc);
    #pragma unroll
    for (int nn = 0; nn < 4; nn++)
        t2[(ng+nn)*128 + h] = fmaxf(acc[nn] + biaS[512 + h], 0.0f);
    __syncthreads();

    if (tid < 32) {
        int n = tid >> 2, d = tid & 3;
        float a = bo3S[d];
        const float* vv = t2 + n*128;
        #pragma unroll 8
        for (int hh = 0; hh < 128; hh++) a += vv[hh] * Wo3S[hh*4 + d];
        float pred = insS[tid] + a;
        g_pred[(b * NN + n0 + n) * DD + d] = pred;
        if (step >= TT)
            out[(((size_t)(b * NN + n0 + n)) * DD + d) * LL + (step - TT)] = pred;
    }
    #undef GEMV4
}

// ---------------- launch ----------------
extern "C" void kernel_launch(void* const* d_in, const int* in_sizes, int n_in,
                              void* d_out, int out_size) {
    const float* data  = (const float*)d_in[0];
    const float* rel   = (const float*)d_in[1];
    const float* W1    = (const float*)d_in[2];
    const float* b1    = (const float*)d_in[3];
    const float* W2    = (const float*)d_in[4];
    const float* b2    = (const float*)d_in[5];
    const float* Wr_h  = (const float*)d_in[6];
    const float* Wi_h  = (const float*)d_in[7];
    const float* Wh_h  = (const float*)d_in[8];
    const float* Wr_in = (const float*)d_in[9];
    const float* br_in = (const float*)d_in[10];
    const float* Wi_in = (const float*)d_in[11];
    const float* bi_in = (const float*)d_in[12];
    const float* Wn_in = (const float*)d_in[13];
    const float* bn_in = (const float*)d_in[14];
    const float* Wo1   = (const float*)d_in[15];
    const float* bo1   = (const float*)d_in[16];
    const float* Wo2   = (const float*)d_in[17];
    const float* bo2   = (const float*)d_in[18];
    const float* Wo3   = (const float*)d_in[19];
    const float* bo3   = (const float*)d_in[20];
    const int* recv_idx = (const int*)d_in[21];
    const int* send_idx = (const int*)d_in[22];
    float* out = (float*)d_out;

    cudaFuncSetAttribute(uv_kernel,   cudaFuncAttributeMaxDynamicSharedMemorySize, UV_SMEM);
    cudaFuncSetAttribute(msg_kernel,  cudaFuncAttributeMaxDynamicSharedMemorySize, MSG_SMEM);
    cudaFuncSetAttribute(node_kernel, cudaFuncAttributeMaxDynamicSharedMemorySize, NODE_SMEM);

    init_kernel<<<512, 256>>>();
    prep_kernel<<<12, 256>>>(W1, W2);
    for (int s = 0; s < TT + LL; s++) {
        uv_kernel<<<dim3(8, 8), 512, UV_SMEM>>>();
        msg_kernel<<<dim3(32, BB), 1024, MSG_SMEM>>>(b1, b2, rel, recv_idx, send_idx);
        node_kernel<<<dim3(8, BB), 256, NODE_SMEM>>>(data, s,
            Wr_h, Wi_h, Wh_h, Wr_in, br_in, Wi_in, bi_in, Wn_in, bn_in,
            Wo1, bo1, Wo2, bo2, Wo3, bo3, out);
    }
}

// round 10
// speedup vs baseline: 5.2008x; 1.2222x over previous
#include <cuda_runtime.h>
#include <cuda_bf16.h>
#include <stdint.h>
#include <math.h>

#define BB 16
#define NN 64
#define DD 4
#define TT 40
#define LL 10
#define HH 128
#define KK 4
#define EE (NN*(NN-1))

// fp32 tile (uv): 128 x 132 words
#define SPW  132
#define TILEF_B (128*SPW*4)   // 67584
// bf16 tile (msg): 128 x 136 halves (272 B/row)
#define SP   136
#define SPB  272
#define TILEH_B (128*SPB)     // 34816

// ---------------- persistent device state ----------------
__device__ float g_hidden[BB*NN*HH];
__device__ float g_pred[BB*NN*DD];
__device__ __align__(16) __nv_bfloat16 g_uv[BB*8*NN*HH];  // [B][ks][N][H] bf16
__device__ float g_aggk[KK*BB*NN*HH];                     // per-k partial aggregates
__device__ __align__(16) float g_W1T[8*128*SPW];          // fp32 [ks][128][132]
__device__ __align__(16) __nv_bfloat16 g_W2T[4*128*SP];   // bf16 [k][128][136]

// ---------------- PTX helpers ----------------
__device__ __forceinline__ uint32_t smem_u32(const void* p) {
    uint32_t a;
    asm("{ .reg .u64 t; cvta.to.shared.u64 t, %1; cvt.u32.u64 %0, t; }" : "=r"(a) : "l"(p));
    return a;
}
#define MBAR_INIT(mb, c)  asm volatile("mbarrier.init.shared.b64 [%0], %1;" :: "r"(mb), "r"(c) : "memory")
#define MBAR_EXPECT_TX(mb, n) asm volatile("mbarrier.arrive.expect_tx.shared.b64 _, [%0], %1;" :: "r"(mb), "r"(n) : "memory")
#define FENCE_ASYNC()     asm volatile("fence.proxy.async.shared::cta;" ::: "memory")
#define BULK_CP(dst, src, bytes, mb) \
    asm volatile("cp.async.bulk.shared::cta.global.mbarrier::complete_tx::bytes [%0], [%1], %2, [%3];" \
        :: "r"(dst), "l"(src), "r"(bytes), "r"(mb) : "memory")

#define MBAR_WAIT(mb, ph) do { \
    uint32_t _m = (mb); uint32_t _p = (ph); uint32_t _d; \
    asm volatile("{\n\t.reg .pred p;\n\tmbarrier.try_wait.parity.acquire.cta.shared::cta.b64 p, [%1], %2;\n\tselp.b32 %0, 1, 0, p;\n\t}" \
        : "=r"(_d) : "r"(_m), "r"(_p) : "memory"); \
    if (!_d) { \
        asm volatile("{\n\t.reg .pred P1;\n\tWL_%=:\n\tmbarrier.try_wait.parity.acquire.cta.shared::cta.b64 P1, [%0], %1, 0x989680;\n\t@P1 bra.uni WD_%=;\n\tbra.uni WL_%=;\n\tWD_%=:\n\t}" \
            :: "r"(_m), "r"(_p) : "memory"); \
    } \
} while (0)

// tf32 mma m16n8k8
__device__ __forceinline__ void mma_tf32(float d[4], uint32_t a0, uint32_t a1, uint32_t a2, uint32_t a3,
                                         uint32_t b0, uint32_t b1) {
    asm volatile("mma.sync.aligned.m16n8k8.row.col.f32.tf32.tf32.f32 "
        "{%0,%1,%2,%3}, {%4,%5,%6,%7}, {%8,%9}, {%0,%1,%2,%3};"
        : "+f"(d[0]), "+f"(d[1]), "+f"(d[2]), "+f"(d[3])
        : "r"(a0), "r"(a1), "r"(a2), "r"(a3), "r"(b0), "r"(b1));
}
// bf16 mma m16n8k16
__device__ __forceinline__ void mma_bf16(float d[4], uint32_t a0, uint32_t a1, uint32_t a2, uint32_t a3,
                                         uint32_t b0, uint32_t b1) {
    asm volatile("mma.sync.aligned.m16n8k16.row.col.f32.bf16.bf16.f32 "
        "{%0,%1,%2,%3}, {%4,%5,%6,%7}, {%8,%9}, {%0,%1,%2,%3};"
        : "+f"(d[0]), "+f"(d[1]), "+f"(d[2]), "+f"(d[3])
        : "r"(a0), "r"(a1), "r"(a2), "r"(a3), "r"(b0), "r"(b1));
}

// tf32 GEMM (uv): 16 warps, warp tile 32m x 32n
__device__ __forceinline__ void gemm_tf32(const float* __restrict__ A, const float* __restrict__ B,
                                          float acc[2][4][4], int mblk, int nblk, int lane) {
    int gid = lane >> 2, tig = lane & 3;
    const float* ap0 = A + (mblk * 32 + gid) * SPW + tig;
    const float* bp0 = B + (nblk * 32 + gid) * SPW + tig;
    #pragma unroll
    for (int ks = 0; ks < 16; ks++) {
        int k0 = ks * 8;
        uint32_t a[2][4];
        #pragma unroll
        for (int mf = 0; mf < 2; mf++) {
            const float* ap = ap0 + mf * 16 * SPW + k0;
            a[mf][0] = __float_as_uint(ap[0]);
            a[mf][1] = __float_as_uint(ap[8 * SPW]);
            a[mf][2] = __float_as_uint(ap[4]);
            a[mf][3] = __float_as_uint(ap[8 * SPW + 4]);
        }
        #pragma unroll
        for (int nf = 0; nf < 4; nf++) {
            const float* bp = bp0 + nf * 8 * SPW + k0;
            uint32_t b0 = __float_as_uint(bp[0]);
            uint32_t b1 = __float_as_uint(bp[4]);
            mma_tf32(acc[0][nf], a[0][0], a[0][1], a[0][2], a[0][3], b0, b1);
            mma_tf32(acc[1][nf], a[1][0], a[1][1], a[1][2], a[1][3], b0, b1);
        }
    }
}

// bf16 GEMM (msg): 16 warps, warp tile 32m x 32n
__device__ __forceinline__ void gemm_bf16_2(const char* __restrict__ A, const char* __restrict__ B,
                                            float acc[2][4][4], int mblk, int nblk, int lane) {
    int gid = lane >> 2, tig = lane & 3;
    const char* ap0 = A + (mblk * 32 + gid) * SPB + tig * 4;
    const char* bp0 = B + (nblk * 32 + gid) * SPB + tig * 4;
    #pragma unroll
    for (int ks = 0; ks < 8; ks++) {
        int kb = ks * 32;
        uint32_t a[2][4];
        #pragma unroll
        for (int mf = 0; mf < 2; mf++) {
            const char* ap = ap0 + mf * 16 * SPB + kb;
            a[mf][0] = *(const uint32_t*)ap;
            a[mf][1] = *(const uint32_t*)(ap + 8 * SPB);
            a[mf][2] = *(const uint32_t*)(ap + 16);
            a[mf][3] = *(const uint32_t*)(ap + 8 * SPB + 16);
        }
        #pragma unroll
        for (int nf = 0; nf < 4; nf++) {
            const char* bp = bp0 + nf * 8 * SPB + kb;
            uint32_t b0 = *(const uint32_t*)bp;
            uint32_t b1 = *(const uint32_t*)(bp + 16);
            mma_bf16(acc[0][nf], a[0][0], a[0][1], a[0][2], a[0][3], b0, b1);
            mma_bf16(acc[1][nf], a[1][0], a[1][1], a[1][2], a[1][3], b0, b1);
        }
    }
}

// ---------------- fast math ----------------
__device__ __forceinline__ float fex2_(float x) { float r; asm("ex2.approx.f32 %0, %1;" : "=f"(r) : "f"(x)); return r; }
__device__ __forceinline__ float frcp_(float x) { float r; asm("rcp.approx.f32 %0, %1;" : "=f"(r) : "f"(x)); return r; }
__device__ __forceinline__ float ftanh_(float x) { return fmaf(-2.0f, frcp_(fex2_(x * 2.885390081777927f) + 1.0f), 1.0f); }
__device__ __forceinline__ float fsig_(float x)  { return frcp_(1.0f + fex2_(-1.4426950408889634f * x)); }
__device__ __forceinline__ float ftanha_(float x){ float r; asm("tanh.approx.f32 %0, %1;" : "=f"(r) : "f"(x)); return r; }

// ---------------- init ----------------
__global__ void init_kernel() {
    int i = blockIdx.x * blockDim.x + threadIdx.x;
    if (i < BB*NN*HH) g_hidden[i] = 0.0f;
    if (i < BB*NN*DD) g_pred[i]   = 0.0f;
}

// ---------------- prep ----------------
__global__ __launch_bounds__(256)
void prep_kernel(const float* __restrict__ W1, const float* __restrict__ W2) {
    int s = blockIdx.x;
    if (s < 8) {
        const float* src = W1 + s * 16384;
        float* dst = g_W1T + s * 128 * SPW;
        for (int t = threadIdx.x; t < 16384; t += 256) {
            int n = t >> 7, f = t & 127;
            dst[n * SPW + f] = src[f * 128 + n];
        }
    } else {
        const float* src = W2 + (s - 8) * 16384;
        __nv_bfloat16* dst = g_W2T + (s - 8) * 128 * SP;
        for (int t = threadIdx.x; t < 16384; t += 256) {
            int n = t >> 7, f = t & 127;
            dst[n * SP + f] = __float2bfloat16_rn(src[f * 128 + n]);
        }
    }
}

// ---------------- UV: tf32 GEMM, bf16 output ----------------
#define UV_A  0
#define UV_B  TILEF_B
#define UV_MB (2*TILEF_B)
#define UV_SMEM (UV_MB + 32)

__global__ __launch_bounds__(512)
void uv_kernel() {
    extern __shared__ char sm[];
    uint32_t smb = smem_u32(sm);
    int tid = threadIdx.x;
    int ks = blockIdx.x, bp = blockIdx.y;
    uint32_t mbt = smb + UV_MB;
    float* A = (float*)(sm + UV_A);
    const float* Bt = (const float*)(sm + UV_B);

    if (tid == 0) {
        MBAR_INIT(mbt, 1);
        FENCE_ASYNC();
        MBAR_EXPECT_TX(mbt, TILEF_B);
        BULK_CP(smb + UV_B, (const char*)(g_W1T + (size_t)ks * 128 * SPW), TILEF_B, mbt);
    }
    for (int idx = tid; idx < 128 * 32; idx += 512) {
        int row = idx >> 5, f4 = (idx & 31) * 4;
        int b = bp * 2 + (row >> 6), node = row & 63;
        float4 v = *(const float4*)(g_hidden + ((size_t)(b * NN + node)) * HH + f4);
        *(float4*)&A[row * SPW + f4] = v;
    }
    __syncthreads();
    MBAR_WAIT(mbt, 0);

    int w = tid >> 5, lane = tid & 31;
    int mblk = w & 3, nblk = w >> 2;
    int gid = lane >> 2, tig = lane & 3;

    float acc[2][4][4];
    #pragma unroll
    for (int mf = 0; mf < 2; mf++)
        #pragma unroll
        for (int nf = 0; nf < 4; nf++)
            #pragma unroll
            for (int j = 0; j < 4; j++) acc[mf][nf][j] = 0.0f;

    gemm_tf32(A, Bt, acc, mblk, nblk, lane);
    __syncthreads();

    #pragma unroll
    for (int mf = 0; mf < 2; mf++) {
        int r0 = mblk * 32 + mf * 16 + gid;
        #pragma unroll
        for (int nf = 0; nf < 4; nf++) {
            int c = nblk * 32 + nf * 8 + tig * 2;
            *(float2*)&A[r0 * SPW + c]       = make_float2(acc[mf][nf][0], acc[mf][nf][1]);
            *(float2*)&A[(r0 + 8) * SPW + c] = make_float2(acc[mf][nf][2], acc[mf][nf][3]);
        }
    }
    __syncthreads();
    for (int idx = tid; idx < 128 * 16; idx += 512) {
        int row = idx >> 4, c8 = (idx & 15) * 8;
        float4 v0 = *(const float4*)&A[row * SPW + c8];
        float4 v1 = *(const float4*)&A[row * SPW + c8 + 4];
        __nv_bfloat162 p0 = __floats2bfloat162_rn(v0.x, v0.y);
        __nv_bfloat162 p1 = __floats2bfloat162_rn(v0.z, v0.w);
        __nv_bfloat162 p2 = __floats2bfloat162_rn(v1.x, v1.y);
        __nv_bfloat162 p3 = __floats2bfloat162_rn(v1.z, v1.w);
        int b = bp * 2 + (row >> 6), node = row & 63;
        __nv_bfloat162* dst = (__nv_bfloat162*)(g_uv + ((size_t)(b * 8 + ks) * 64 + node) * 128 + c8);
        dst[0] = p0; dst[1] = p1; dst[2] = p2; dst[3] = p3;
    }
}

// ---------------- MSG kernel: one block per (pair, batch, k); 2 CTAs/SM ----------------
#define MS_A    0                  /* bf16 128x136 = 34816 */
#define MS_B    34816              /* bf16 128x136 = 34816 */
#define MS_U    69632              /* bf16 64x128  = 16384 */
#define MS_VS   86016              /* [2][128] f = 1024 */
#define MS_SCR  87040              /* [4][128] f = 2048 */
#define MS_REL  89088              /* 128 f = 512 */
#define MS_SEND 89600              /* 128 i = 512 */
#define MS_B2   90112              /* 128 f = 512 */
#define MS_MB   90624              /* 2 mbars */
#define MSG_SMEM 90656

__global__ __launch_bounds__(512, 2)
void msg_kernel(const float* __restrict__ b1, const float* __restrict__ b2,
                const float* __restrict__ rel,
                const int* __restrict__ recv_idx, const int* __restrict__ send_idx) {
    extern __shared__ char sm[];
    uint32_t smb = smem_u32(sm);
    int tid = threadIdx.x;
    int p = blockIdx.x, b = blockIdx.y, k = blockIdx.z;

    float* RelS  = (float*)(sm + MS_REL);
    int*   SendS = (int*)(sm + MS_SEND);
    float* b2S   = (float*)(sm + MS_B2);
    float* vS    = (float*)(sm + MS_VS);
    float* scr   = (float*)(sm + MS_SCR);
    uint32_t bbar = smb + MS_MB, ubar = smb + MS_MB + 8;

    if (tid == 0) {
        MBAR_INIT(bbar, 1);
        MBAR_INIT(ubar, 1);
        FENCE_ASYNC();
        MBAR_EXPECT_TX(bbar, TILEH_B);
        BULK_CP(smb + MS_B, (const char*)(g_W2T + (size_t)k * 128 * SP), TILEH_B, bbar);
        MBAR_EXPECT_TX(ubar, 16384);
        BULK_CP(smb + MS_U, (const char*)(g_uv + (size_t)(b * 8 + 2 * k) * 8192), 16384, ubar);
    }
    int r0n = recv_idx[p * 126];
    int r1n = recv_idx[p * 126 + 63];
    if (tid < 128) {
        int row = tid;
        float rw = 0.0f;
        int sn = 0;
        if (row != 63 && row != 127) {
            int e = (row < 64) ? (p * 126 + row) : (p * 126 + row - 1);
            sn = send_idx[e];
            rw = rel[((size_t)(b * EE + e)) * KK + k];
        }
        SendS[row] = sn;
        RelS[row] = rw;
        b2S[row] = b2[k * 128 + row];
    } else if (tid < 384) {
        int f = tid & 127, rh = (tid >> 7) & 1;
        int rv = rh ? r1n : r0n;
        const __nv_bfloat16* v = g_uv + ((size_t)(b * 8 + 2 * k + 1)) * 8192 + rv * 128;
        vS[rh * 128 + f] = __bfloat162float(v[f]) + b1[k * 128 + f];
    }
    __syncthreads();

    // build A = bf16(tanh(u[send] + vS)); rows 63/127 zero
    MBAR_WAIT(ubar, 0);
    {
        const __nv_bfloat16* U = (const __nv_bfloat16*)(sm + MS_U);
        for (int idx = tid; idx < 128 * 32; idx += 512) {
            int row = idx >> 5, f4 = (idx & 31) * 4;
            uint32_t o01 = 0, o23 = 0;
            if (row != 63 && row != 127) {
                int sn = SendS[row], rh = row >> 6;
                uint2 q = *(const uint2*)(U + sn * 128 + f4);
                float2 f0 = __bfloat1622float2(*(__nv_bfloat162*)&q.x);
                float2 f1 = __bfloat1622float2(*(__nv_bfloat162*)&q.y);
                float4 vv = *(const float4*)&vS[rh * 128 + f4];
                __nv_bfloat162 p0 = __floats2bfloat162_rn(ftanha_(f0.x + vv.x), ftanha_(f0.y + vv.y));
                __nv_bfloat162 p1 = __floats2bfloat162_rn(ftanha_(f1.x + vv.z), ftanha_(f1.y + vv.w));
                o01 = *(uint32_t*)&p0; o23 = *(uint32_t*)&p1;
            }
            *(uint2*)(sm + MS_A + row * SPB + f4 * 2) = make_uint2(o01, o23);
        }
    }
    __syncthreads();

    MBAR_WAIT(bbar, 0);
    int w = tid >> 5, lane = tid & 31;
    int mblk = w & 3, nblk = w >> 2;
    int gid = lane >> 2, tig = lane & 3;

    float acc[2][4][4];
    #pragma unroll
    for (int mf = 0; mf < 2; mf++)
        #pragma unroll
        for (int nf = 0; nf < 4; nf++)
            #pragma unroll
            for (int j = 0; j < 4; j++) acc[mf][nf][j] = 0.0f;

    gemm_bf16_2(sm + MS_A, sm + MS_B, acc, mblk, nblk, lane);

    // fused epilogue + row-sum (all 32 rows of this warp tile share one receiver)
    float sum[4][2];
    #pragma unroll
    for (int nf = 0; nf < 4; nf++) { sum[nf][0] = 0.0f; sum[nf][1] = 0.0f; }
    {
        int r0 = mblk * 32 + gid;
        float rw0 = RelS[r0];
        float rw1 = RelS[r0 + 8];
        float rw2 = RelS[r0 + 16];
        float rw3 = RelS[r0 + 24];
        #pragma unroll
        for (int nf = 0; nf < 4; nf++) {
            int c = nblk * 32 + nf * 8 + tig * 2;
            float bb0 = b2S[c], bb1 = b2S[c + 1];
            sum[nf][0] += rw0 * ftanha_(acc[0][nf][0] + bb0)
                        + rw1 * ftanha_(acc[0][nf][2] + bb0)
                        + rw2 * ftanha_(acc[1][nf][0] + bb0)
                        + rw3 * ftanha_(acc[1][nf][2] + bb0);
            sum[nf][1] += rw0 * ftanha_(acc[0][nf][1] + bb1)
                        + rw1 * ftanha_(acc[0][nf][3] + bb1)
                        + rw2 * ftanha_(acc[1][nf][1] + bb1)
                        + rw3 * ftanha_(acc[1][nf][3] + bb1);
        }
    }
    // reduce over gid lanes
    #pragma unroll
    for (int off = 16; off >= 4; off >>= 1)
        #pragma unroll
        for (int nf = 0; nf < 4; nf++) {
            sum[nf][0] += __shfl_down_sync(0xffffffffu, sum[nf][0], off);
            sum[nf][1] += __shfl_down_sync(0xffffffffu, sum[nf][1], off);
        }
    if (gid == 0) {
        #pragma unroll
        for (int nf = 0; nf < 4; nf++) {
            int c = nblk * 32 + nf * 8 + tig * 2;
            *(float2*)&scr[mblk * 128 + c] = make_float2(sum[nf][0], sum[nf][1]);
        }
    }
    __syncthreads();
    if (tid < 256) {
        int h = tid & 127, rh = tid >> 7;
        float a = scr[(rh * 2) * 128 + h] + scr[(rh * 2 + 1) * 128 + h];
        int rv = rh ? r1n : r0n;
        g_aggk[(((size_t)k * BB + b) * NN + rv) * HH + h] = a;
    }
}

// ---------------- NODE kernel ----------------
#define ND_WB0 0
#define ND_WB1 65536
#define ND_AGG 131072
#define ND_HID 135168
#define ND_T1  139264
#define ND_T2  143360
#define ND_INS 147456
#define ND_WIN 147712
#define ND_BIA 153856
#define ND_WO3 156416
#define ND_BO3 158464
#define ND_MB  158480
#define NODE_SMEM 158592

__global__ __launch_bounds__(256)
void node_kernel(const float* __restrict__ data, int step,
                 const float* __restrict__ Wr_h, const float* __restrict__ Wi_h,
                 const float* __restrict__ Wh_h,
                 const float* __restrict__ Wr_in, const float* __restrict__ br_in,
                 const float* __restrict__ Wi_in, const float* __restrict__ bi_in,
                 const float* __restrict__ Wn_in, const float* __restrict__ bn_in,
                 const float* __restrict__ Wo1, const float* __restrict__ bo1,
                 const float* __restrict__ Wo2, const float* __restrict__ bo2,
                 const float* __restrict__ Wo3, const float* __restrict__ bo3,
                 float* __restrict__ out) {
    extern __shared__ char sm[];
    uint32_t smb = smem_u32(sm);
    int q = blockIdx.x, b = blockIdx.y;
    int n0 = q * 8;
    int tid = threadIdx.x;

    float* aggS = (float*)(sm + ND_AGG);
    float* hidS = (float*)(sm + ND_HID);
    float* t1   = (float*)(sm + ND_T1);
    float* t2   = (float*)(sm + ND_T2);
    float* insS = (float*)(sm + ND_INS);
    float* WinS = (float*)(sm + ND_WIN);
    float* biaS = (float*)(sm + ND_BIA);
    float* Wo3S = (float*)(sm + ND_WO3);
    float* bo3S = (float*)(sm + ND_BO3);
    uint32_t mb0 = smb + ND_MB, mb1 = smb + ND_MB + 8;

    if (tid == 0) {
        MBAR_INIT(mb0, 1);
        MBAR_INIT(mb1, 1);
        FENCE_ASYNC();
        MBAR_EXPECT_TX(mb0, 65536);
        BULK_CP(smb + ND_WB0, (const void*)Wr_h, 65536, mb0);
        MBAR_EXPECT_TX(mb1, 65536);
        BULK_CP(smb + ND_WB1, (const void*)Wi_h, 65536, mb1);
    }
    {
        size_t base = ((size_t)(b * NN + n0)) * HH;
        const float4* a0 = (const float4*)(g_aggk + base);
        const float4* a1 = (const float4*)(g_aggk + base + (size_t)BB * NN * HH);
        const float4* a2 = (const float4*)(g_aggk + base + (size_t)2 * BB * NN * HH);
        const float4* a3 = (const float4*)(g_aggk + base + (size_t)3 * BB * NN * HH);
        float4 s0 = a0[tid], s1 = a1[tid], s2 = a2[tid], s3 = a3[tid];
        float4 s;
        s.x = (s0.x + s1.x + s2.x + s3.x) * (1.0f / 16.0f);
        s.y = (s0.y + s1.y + s2.y + s3.y) * (1.0f / 16.0f);
        s.z = (s0.z + s1.z + s2.z + s3.z) * (1.0f / 16.0f);
        s.w = (s0.w + s1.w + s2.w + s3.w) * (1.0f / 16.0f);
        ((float4*)aggS)[tid] = s;
        const float* hg = g_hidden + base;
        ((float4*)hidS)[tid] = ((const float4*)hg)[tid];
    }
    if (tid < 32) {
        int n = tid >> 2, d = tid & 3;
        float v;
        if (step < TT) v = data[(((size_t)(b * NN + n0 + n)) * DD + d) * TT + step];
        else           v = g_pred[(b * NN + n0 + n) * DD + d];
        insS[tid] = v;
    }
    for (int i = tid; i < 512; i += 256) {
        WinS[i]        = Wr_in[i];
        WinS[512 + i]  = Wi_in[i];
        WinS[1024 + i] = Wn_in[i];
        Wo3S[i]        = Wo3[i];
    }
    if (tid < 128) {
        biaS[tid]       = br_in[tid];
        biaS[128 + tid] = bi_in[tid];
        biaS[256 + tid] = bn_in[tid];
        biaS[384 + tid] = bo1[tid];
        biaS[512 + tid] = bo2[tid];
    }
    if (tid < 4) bo3S[tid] = bo3[tid];
    __syncthreads();

    int h = tid & 127, ng = (tid >> 7) * 4;

    #define GEMV4(ACT, WB, OUTARR) do { \
        const float* _wb = (WB); \
        _Pragma("unroll") \
        for (int nn = 0; nn < 4; nn++) { \
            const float* av = (ACT) + (ng + nn) * 128; \
            float a = 0.0f; \
            _Pragma("unroll 8") \
            for (int f4 = 0; f4 < 32; f4++) { \
                float4 x = ((const float4*)av)[f4]; \
                a += x.x * _wb[(f4*4+0)*128 + h] + x.y * _wb[(f4*4+1)*128 + h] \
                   + x.z * _wb[(f4*4+2)*128 + h] + x.w * _wb[(f4*4+3)*128 + h]; \
            } \
            (OUTARR)[nn] = a; \
        } \
    } while (0)

    float acc[4];
    float rr[4], ii[4];

    MBAR_WAIT(mb0, 0);
    GEMV4(aggS, (const float*)(sm + ND_WB0), acc);
    #pragma unroll
    for (int nn = 0; nn < 4; nn++) {
        int n = ng + nn;
        float a = acc[nn] + biaS[h];
        #pragma unroll
        for (int d = 0; d < 4; d++) a += insS[n*4+d] * WinS[d*128 + h];
        t1[n*128 + h] = fsig_(a);
    }
    __syncthreads();
    if (tid == 0) { MBAR_EXPECT_TX(mb0, 65536); BULK_CP(smb + ND_WB0, (const void*)Wh_h, 65536, mb0); }

    MBAR_WAIT(mb1, 0);
    GEMV4(aggS, (const float*)(sm + ND_WB1), acc);
    #pragma unroll
    for (int nn = 0; nn < 4; nn++) {
        int n = ng + nn;
        float a = acc[nn] + biaS[128 + h];
        #pragma unroll
        for (int d = 0; d < 4; d++) a += insS[n*4+d] * WinS[512 + d*128 + h];
        ii[nn] = fsig_(a);
        rr[nn] = t1[n*128 + h];
    }
    __syncthreads();
    if (tid == 0) { MBAR_EXPECT_TX(mb1, 65536); BULK_CP(smb + ND_WB1, (const void*)Wo1, 65536, mb1); }

    MBAR_WAIT(mb0, 1);
    GEMV4(aggS, (const float*)(sm + ND_WB0), acc);
    #pragma unroll
    for (int nn = 0; nn < 4; nn++) {
        int n = ng + nn;
        float a = biaS[256 + h];
        #pragma unroll
        for (int d = 0; d < 4; d++) a += insS[n*4+d] * WinS[1024 + d*128 + h];
        float nv = ftanh_(a + rr[nn] * acc[nn]);
        float hn = (1.0f - ii[nn]) * nv + ii[nn] * hidS[n*128 + h];
        hidS[n*128 + h] = hn;
        g_hidden[((size_t)(b * NN + n0 + n)) * HH + h] = hn;
    }
    __syncthreads();
    if (tid == 0) { MBAR_EXPECT_TX(mb0, 65536); BULK_CP(smb + ND_WB0, (const void*)Wo2, 65536, mb0); }

    MBAR_WAIT(mb1, 1);
    GEMV4(hidS, (const float*)(sm + ND_WB1), acc);
    #pragma unroll
    for (int nn = 0; nn < 4; nn++)
        t1[(ng+nn)*128 + h] = fmaxf(acc[nn] + biaS[384 + h], 0.0f);
    __syncthreads();

    MBAR_WAIT(mb0, 0);
    GEMV4(t1, (const float*)(sm + ND_WB0), acc);
    #pragma unroll
    for (int nn = 0; nn < 4; nn++)
        t2[(ng+nn)*128 + h] = fmaxf(acc[nn] + biaS[512 + h], 0.0f);
    __syncthreads();

    if (tid < 32) {
        int n = tid >> 2, d = tid & 3;
        float a = bo3S[d];
        const float* vv = t2 + n*128;
        #pragma unroll 8
        for (int hh = 0; hh < 128; hh++) a += vv[hh] * Wo3S[hh*4 + d];
        float pred = insS[tid] + a;
        g_pred[(b * NN + n0 + n) * DD + d] = pred;
        if (step >= TT)
            out[(((size_t)(b * NN + n0 + n)) * DD + d) * LL + (step - TT)] = pred;
    }
    #undef GEMV4
}

// ---------------- launch ----------------
extern "C" void kernel_launch(void* const* d_in, const int* in_sizes, int n_in,
                              void* d_out, int out_size) {
    const float* data  = (const float*)d_in[0];
    const float* rel   = (const float*)d_in[1];
    const float* W1    = (const float*)d_in[2];
    const float* b1    = (const float*)d_in[3];
    const float* W2    = (const float*)d_in[4];
    const float* b2    = (const float*)d_in[5];
    const float* Wr_h  = (const float*)d_in[6];
    const float* Wi_h  = (const float*)d_in[7];
    const float* Wh_h  = (const float*)d_in[8];
    const float* Wr_in = (const float*)d_in[9];
    const float* br_in = (const float*)d_in[10];
    const float* Wi_in = (const float*)d_in[11];
    const float* bi_in = (const float*)d_in[12];
    const float* Wn_in = (const float*)d_in[13];
    const float* bn_in = (const float*)d_in[14];
    const float* Wo1   = (const float*)d_in[15];
    const float* bo1   = (const float*)d_in[16];
    const float* Wo2   = (const float*)d_in[17];
    const float* bo2   = (const float*)d_in[18];
    const float* Wo3   = (const float*)d_in[19];
    const float* bo3   = (const float*)d_in[20];
    const int* recv_idx = (const int*)d_in[21];
    const int* send_idx = (const int*)d_in[22];
    float* out = (float*)d_out;

    cudaFuncSetAttribute(uv_kernel,   cudaFuncAttributeMaxDynamicSharedMemorySize, UV_SMEM);
    cudaFuncSetAttribute(msg_kernel,  cudaFuncAttributeMaxDynamicSharedMemorySize, MSG_SMEM);
    cudaFuncSetAttribute(node_kernel, cudaFuncAttributeMaxDynamicSharedMemorySize, NODE_SMEM);

    init_kernel<<<512, 256>>>();
    prep_kernel<<<12, 256>>>(W1, W2);
    for (int s = 0; s < TT + LL; s++) {
        uv_kernel<<<dim3(8, 8), 512, UV_SMEM>>>();
        msg_kernel<<<dim3(32, BB, KK), 512, MSG_SMEM>>>(b1, b2, rel, recv_idx, send_idx);
        node_kernel<<<dim3(8, BB), 256, NODE_SMEM>>>(data, s,
            Wr_h, Wi_h, Wh_h, Wr_in, br_in, Wi_in, bi_in, Wn_in, bn_in,
            Wo1, bo1, Wo2, bo2, Wo3, bo3, out);
    }
}

// round 11
// speedup vs baseline: 5.6151x; 1.0797x over previous
#include <cuda_runtime.h>
#include <cuda_bf16.h>
#include <stdint.h>
#include <math.h>

#define BB 16
#define NN 64
#define DD 4
#define TT 40
#define LL 10
#define HH 128
#define KK 4
#define EE (NN*(NN-1))

// fp32 tile: 128 x 132 words
#define SPW  132
#define TILEF_B (128*SPW*4)   // 67584
// bf16 tile (msg): 128 x 136 halves (272 B/row)
#define SP   136
#define SPB  272
#define TILEH_B (128*SPB)     // 34816

// ---------------- persistent device state ----------------
__device__ float g_hidden[BB*NN*HH];
__device__ float g_pred[BB*NN*DD];
__device__ __align__(16) __nv_bfloat16 g_uv[BB*8*NN*HH];  // [B][ks][N][H] bf16
__device__ float g_aggk[KK*BB*NN*HH];                     // per-k partial aggregates
__device__ __align__(16) float g_W1T[8*128*SPW];          // fp32 [ks][128][132]
__device__ __align__(16) __nv_bfloat16 g_W2T[4*128*SP];   // bf16 [k][128][136]
__device__ __align__(16) float g_WnT[5*128*SPW];          // node weights^T padded [m][h][132]

// ---------------- PTX helpers ----------------
__device__ __forceinline__ uint32_t smem_u32(const void* p) {
    uint32_t a;
    asm("{ .reg .u64 t; cvta.to.shared.u64 t, %1; cvt.u32.u64 %0, t; }" : "=r"(a) : "l"(p));
    return a;
}
#define MBAR_INIT(mb, c)  asm volatile("mbarrier.init.shared.b64 [%0], %1;" :: "r"(mb), "r"(c) : "memory")
#define MBAR_EXPECT_TX(mb, n) asm volatile("mbarrier.arrive.expect_tx.shared.b64 _, [%0], %1;" :: "r"(mb), "r"(n) : "memory")
#define FENCE_ASYNC()     asm volatile("fence.proxy.async.shared::cta;" ::: "memory")
#define BULK_CP(dst, src, bytes, mb) \
    asm volatile("cp.async.bulk.shared::cta.global.mbarrier::complete_tx::bytes [%0], [%1], %2, [%3];" \
        :: "r"(dst), "l"(src), "r"(bytes), "r"(mb) : "memory")

#define MBAR_WAIT(mb, ph) do { \
    uint32_t _m = (mb); uint32_t _p = (ph); uint32_t _d; \
    asm volatile("{\n\t.reg .pred p;\n\tmbarrier.try_wait.parity.acquire.cta.shared::cta.b64 p, [%1], %2;\n\tselp.b32 %0, 1, 0, p;\n\t}" \
        : "=r"(_d) : "r"(_m), "r"(_p) : "memory"); \
    if (!_d) { \
        asm volatile("{\n\t.reg .pred P1;\n\tWL_%=:\n\tmbarrier.try_wait.parity.acquire.cta.shared::cta.b64 P1, [%0], %1, 0x989680;\n\t@P1 bra.uni WD_%=;\n\tbra.uni WL_%=;\n\tWD_%=:\n\t}" \
            :: "r"(_m), "r"(_p) : "memory"); \
    } \
} while (0)

// tf32 mma m16n8k8
__device__ __forceinline__ void mma_tf32(float d[4], uint32_t a0, uint32_t a1, uint32_t a2, uint32_t a3,
                                         uint32_t b0, uint32_t b1) {
    asm volatile("mma.sync.aligned.m16n8k8.row.col.f32.tf32.tf32.f32 "
        "{%0,%1,%2,%3}, {%4,%5,%6,%7}, {%8,%9}, {%0,%1,%2,%3};"
        : "+f"(d[0]), "+f"(d[1]), "+f"(d[2]), "+f"(d[3])
        : "r"(a0), "r"(a1), "r"(a2), "r"(a3), "r"(b0), "r"(b1));
}
// bf16 mma m16n8k16
__device__ __forceinline__ void mma_bf16(float d[4], uint32_t a0, uint32_t a1, uint32_t a2, uint32_t a3,
                                         uint32_t b0, uint32_t b1) {
    asm volatile("mma.sync.aligned.m16n8k16.row.col.f32.bf16.bf16.f32 "
        "{%0,%1,%2,%3}, {%4,%5,%6,%7}, {%8,%9}, {%0,%1,%2,%3};"
        : "+f"(d[0]), "+f"(d[1]), "+f"(d[2]), "+f"(d[3])
        : "r"(a0), "r"(a1), "r"(a2), "r"(a3), "r"(b0), "r"(b1));
}
__device__ __forceinline__ void ldsm_x4(uint32_t& r0, uint32_t& r1, uint32_t& r2, uint32_t& r3, uint32_t addr) {
    asm volatile("ldmatrix.sync.aligned.m8n8.x4.shared.b16 {%0,%1,%2,%3}, [%4];"
        : "=r"(r0), "=r"(r1), "=r"(r2), "=r"(r3) : "r"(addr));
}

// tf32 GEMM (uv): 16 warps, warp tile 32m x 32n
__device__ __forceinline__ void gemm_tf32(const float* __restrict__ A, const float* __restrict__ B,
                                          float acc[2][4][4], int mblk, int nblk, int lane) {
    int gid = lane >> 2, tig = lane & 3;
    const float* ap0 = A + (mblk * 32 + gid) * SPW + tig;
    const float* bp0 = B + (nblk * 32 + gid) * SPW + tig;
    #pragma unroll
    for (int ks = 0; ks < 16; ks++) {
        int k0 = ks * 8;
        uint32_t a[2][4];
        #pragma unroll
        for (int mf = 0; mf < 2; mf++) {
            const float* ap = ap0 + mf * 16 * SPW + k0;
            a[mf][0] = __float_as_uint(ap[0]);
            a[mf][1] = __float_as_uint(ap[8 * SPW]);
            a[mf][2] = __float_as_uint(ap[4]);
            a[mf][3] = __float_as_uint(ap[8 * SPW + 4]);
        }
        #pragma unroll
        for (int nf = 0; nf < 4; nf++) {
            const float* bp = bp0 + nf * 8 * SPW + k0;
            uint32_t b0 = __float_as_uint(bp[0]);
            uint32_t b1 = __float_as_uint(bp[4]);
            mma_tf32(acc[0][nf], a[0][0], a[0][1], a[0][2], a[0][3], b0, b1);
            mma_tf32(acc[1][nf], a[1][0], a[1][1], a[1][2], a[1][3], b0, b1);
        }
    }
}

// bf16 GEMM via ldmatrix: 16 warps, warp tile 32m x 32n
__device__ __forceinline__ void gemm_bf16_ldsm(uint32_t smA, uint32_t smB,
                                               float acc[2][4][4], int mblk, int nblk, int lane) {
    // A x4: lanes 0-15 -> rows (l&15) k-lo; lanes 16-31 -> rows (l&15) k-hi
    uint32_t aB0 = smA + (uint32_t)(mblk * 32 + (lane & 15)) * SPB + (uint32_t)(lane >> 4) * 16;
    uint32_t aB1 = aB0 + 16 * SPB;
    // B x4 (covers 16 n): lane groups of 8 -> (n-lo k-lo), (n-lo k-hi), (n-hi k-lo), (n-hi k-hi)
    uint32_t bB0 = smB + (uint32_t)(nblk * 32 + ((lane >> 4) << 3) + (lane & 7)) * SPB
                 + (uint32_t)((lane >> 3) & 1) * 16;
    uint32_t bB1 = bB0 + 16 * SPB;
    #pragma unroll
    for (int ks = 0; ks < 8; ks++) {
        uint32_t kb = (uint32_t)ks * 32;
        uint32_t a0[4], a1[4], b0[4], b1[4];
        ldsm_x4(a0[0], a0[1], a0[2], a0[3], aB0 + kb);
        ldsm_x4(a1[0], a1[1], a1[2], a1[3], aB1 + kb);
        ldsm_x4(b0[0], b0[1], b0[2], b0[3], bB0 + kb);
        ldsm_x4(b1[0], b1[1], b1[2], b1[3], bB1 + kb);
        mma_bf16(acc[0][0], a0[0], a0[1], a0[2], a0[3], b0[0], b0[1]);
        mma_bf16(acc[1][0], a1[0], a1[1], a1[2], a1[3], b0[0], b0[1]);
        mma_bf16(acc[0][1], a0[0], a0[1], a0[2], a0[3], b0[2], b0[3]);
        mma_bf16(acc[1][1], a1[0], a1[1], a1[2], a1[3], b0[2], b0[3]);
        mma_bf16(acc[0][2], a0[0], a0[1], a0[2], a0[3], b1[0], b1[1]);
        mma_bf16(acc[1][2], a1[0], a1[1], a1[2], a1[3], b1[0], b1[1]);
        mma_bf16(acc[0][3], a0[0], a0[1], a0[2], a0[3], b1[2], b1[3]);
        mma_bf16(acc[1][3], a1[0], a1[1], a1[2], a1[3], b1[2], b1[3]);
    }
}

// ---------------- fast math ----------------
__device__ __forceinline__ float fex2_(float x) { float r; asm("ex2.approx.f32 %0, %1;" : "=f"(r) : "f"(x)); return r; }
__device__ __forceinline__ float frcp_(float x) { float r; asm("rcp.approx.f32 %0, %1;" : "=f"(r) : "f"(x)); return r; }
__device__ __forceinline__ float ftanh_(float x) { return fmaf(-2.0f, frcp_(fex2_(x * 2.885390081777927f) + 1.0f), 1.0f); }
__device__ __forceinline__ float fsig_(float x)  { return frcp_(1.0f + fex2_(-1.4426950408889634f * x)); }
__device__ __forceinline__ float ftanha_(float x){ float r; asm("tanh.approx.f32 %0, %1;" : "=f"(r) : "f"(x)); return r; }

// ---------------- init ----------------
__global__ void init_kernel() {
    int i = blockIdx.x * blockDim.x + threadIdx.x;
    if (i < BB*NN*HH) g_hidden[i] = 0.0f;
    if (i < BB*NN*DD) g_pred[i]   = 0.0f;
}

// ---------------- prep ----------------
// grid 17: 0-7 W1 slices; 8-11 W2 slices; 12-16 node weights (Wr_h,Wi_h,Wh_h,Wo1,Wo2)
__global__ __launch_bounds__(256)
void prep_kernel(const float* __restrict__ W1, const float* __restrict__ W2,
                 const float* __restrict__ Wr_h, const float* __restrict__ Wi_h,
                 const float* __restrict__ Wh_h, const float* __restrict__ Wo1,
                 const float* __restrict__ Wo2) {
    int s = blockIdx.x;
    if (s < 8) {
        const float* src = W1 + s * 16384;
        float* dst = g_W1T + s * 128 * SPW;
        for (int t = threadIdx.x; t < 16384; t += 256) {
            int n = t >> 7, f = t & 127;
            dst[n * SPW + f] = src[f * 128 + n];
        }
    } else if (s < 12) {
        const float* src = W2 + (s - 8) * 16384;
        __nv_bfloat16* dst = g_W2T + (s - 8) * 128 * SP;
        for (int t = threadIdx.x; t < 16384; t += 256) {
            int n = t >> 7, f = t & 127;
            dst[n * SP + f] = __float2bfloat16_rn(src[f * 128 + n]);
        }
    } else {
        const float* src;
        switch (s - 12) {
            case 0: src = Wr_h; break;
            case 1: src = Wi_h; break;
            case 2: src = Wh_h; break;
            case 3: src = Wo1;  break;
            default: src = Wo2; break;
        }
        float* dst = g_WnT + (s - 12) * 128 * SPW;
        for (int t = threadIdx.x; t < 16384; t += 256) {
            int h = t >> 7, f = t & 127;
            dst[h * SPW + f] = src[f * 128 + h];
        }
    }
}

// ---------------- UV: tf32 GEMM, bf16 output ----------------
#define UV_A  0
#define UV_B  TILEF_B
#define UV_MB (2*TILEF_B)
#define UV_SMEM (UV_MB + 32)

__global__ __launch_bounds__(512)
void uv_kernel() {
    extern __shared__ char sm[];
    uint32_t smb = smem_u32(sm);
    int tid = threadIdx.x;
    int ks = blockIdx.x, bp = blockIdx.y;
    uint32_t mbt = smb + UV_MB;
    float* A = (float*)(sm + UV_A);
    const float* Bt = (const float*)(sm + UV_B);

    if (tid == 0) {
        MBAR_INIT(mbt, 1);
        FENCE_ASYNC();
        MBAR_EXPECT_TX(mbt, TILEF_B);
        BULK_CP(smb + UV_B, (const char*)(g_W1T + (size_t)ks * 128 * SPW), TILEF_B, mbt);
    }
    for (int idx = tid; idx < 128 * 32; idx += 512) {
        int row = idx >> 5, f4 = (idx & 31) * 4;
        int b = bp * 2 + (row >> 6), node = row & 63;
        float4 v = *(const float4*)(g_hidden + ((size_t)(b * NN + node)) * HH + f4);
        *(float4*)&A[row * SPW + f4] = v;
    }
    __syncthreads();
    MBAR_WAIT(mbt, 0);

    int w = tid >> 5, lane = tid & 31;
    int mblk = w & 3, nblk = w >> 2;
    int gid = lane >> 2, tig = lane & 3;

    float acc[2][4][4];
    #pragma unroll
    for (int mf = 0; mf < 2; mf++)
        #pragma unroll
        for (int nf = 0; nf < 4; nf++)
            #pragma unroll
            for (int j = 0; j < 4; j++) acc[mf][nf][j] = 0.0f;

    gemm_tf32(A, Bt, acc, mblk, nblk, lane);
    __syncthreads();

    #pragma unroll
    for (int mf = 0; mf < 2; mf++) {
        int r0 = mblk * 32 + mf * 16 + gid;
        #pragma unroll
        for (int nf = 0; nf < 4; nf++) {
            int c = nblk * 32 + nf * 8 + tig * 2;
            *(float2*)&A[r0 * SPW + c]       = make_float2(acc[mf][nf][0], acc[mf][nf][1]);
            *(float2*)&A[(r0 + 8) * SPW + c] = make_float2(acc[mf][nf][2], acc[mf][nf][3]);
        }
    }
    __syncthreads();
    for (int idx = tid; idx < 128 * 16; idx += 512) {
        int row = idx >> 4, c8 = (idx & 15) * 8;
        float4 v0 = *(const float4*)&A[row * SPW + c8];
        float4 v1 = *(const float4*)&A[row * SPW + c8 + 4];
        __nv_bfloat162 p0 = __floats2bfloat162_rn(v0.x, v0.y);
        __nv_bfloat162 p1 = __floats2bfloat162_rn(v0.z, v0.w);
        __nv_bfloat162 p2 = __floats2bfloat162_rn(v1.x, v1.y);
        __nv_bfloat162 p3 = __floats2bfloat162_rn(v1.z, v1.w);
        int b = bp * 2 + (row >> 6), node = row & 63;
        __nv_bfloat162* dst = (__nv_bfloat162*)(g_uv + ((size_t)(b * 8 + ks) * 64 + node) * 128 + c8);
        dst[0] = p0; dst[1] = p1; dst[2] = p2; dst[3] = p3;
    }
}

// ---------------- MSG kernel: one block per (pair, batch, k); 2 CTAs/SM ----------------
#define MS_A    0
#define MS_B    34816
#define MS_U    69632
#define MS_VS   86016
#define MS_SCR  87040
#define MS_REL  89088
#define MS_SEND 89600
#define MS_B2   90112
#define MS_MB   90624
#define MSG_SMEM 90656

__global__ __launch_bounds__(512, 2)
void msg_kernel(const float* __restrict__ b1, const float* __restrict__ b2,
                const float* __restrict__ rel,
                const int* __restrict__ recv_idx, const int* __restrict__ send_idx) {
    extern __shared__ char sm[];
    uint32_t smb = smem_u32(sm);
    int tid = threadIdx.x;
    int p = blockIdx.x, b = blockIdx.y, k = blockIdx.z;

    float* RelS  = (float*)(sm + MS_REL);
    int*   SendS = (int*)(sm + MS_SEND);
    float* b2S   = (float*)(sm + MS_B2);
    float* vS    = (float*)(sm + MS_VS);
    float* scr   = (float*)(sm + MS_SCR);
    uint32_t bbar = smb + MS_MB, ubar = smb + MS_MB + 8;

    if (tid == 0) {
        MBAR_INIT(bbar, 1);
        MBAR_INIT(ubar, 1);
        FENCE_ASYNC();
        MBAR_EXPECT_TX(bbar, TILEH_B);
        BULK_CP(smb + MS_B, (const char*)(g_W2T + (size_t)k * 128 * SP), TILEH_B, bbar);
        MBAR_EXPECT_TX(ubar, 16384);
        BULK_CP(smb + MS_U, (const char*)(g_uv + (size_t)(b * 8 + 2 * k) * 8192), 16384, ubar);
    }
    int r0n = recv_idx[p * 126];
    int r1n = recv_idx[p * 126 + 63];
    if (tid < 128) {
        int row = tid;
        float rw = 0.0f;
        int sn = 0;
        if (row != 63 && row != 127) {
            int e = (row < 64) ? (p * 126 + row) : (p * 126 + row - 1);
            sn = send_idx[e];
            rw = rel[((size_t)(b * EE + e)) * KK + k];
        }
        SendS[row] = sn;
        RelS[row] = rw;
        b2S[row] = b2[k * 128 + row];
    } else if (tid < 384) {
        int f = tid & 127, rh = (tid >> 7) & 1;
        int rv = rh ? r1n : r0n;
        const __nv_bfloat16* v = g_uv + ((size_t)(b * 8 + 2 * k + 1)) * 8192 + rv * 128;
        vS[rh * 128 + f] = __bfloat162float(v[f]) + b1[k * 128 + f];
    }
    __syncthreads();

    // build A = bf16(tanh(u[send] + vS)); rows 63/127 zero
    MBAR_WAIT(ubar, 0);
    {
        const __nv_bfloat16* U = (const __nv_bfloat16*)(sm + MS_U);
        for (int idx = tid; idx < 128 * 32; idx += 512) {
            int row = idx >> 5, f4 = (idx & 31) * 4;
            uint32_t o01 = 0, o23 = 0;
            if (row != 63 && row != 127) {
                int sn = SendS[row], rh = row >> 6;
                uint2 q = *(const uint2*)(U + sn * 128 + f4);
                float2 f0 = __bfloat1622float2(*(__nv_bfloat162*)&q.x);
                float2 f1 = __bfloat1622float2(*(__nv_bfloat162*)&q.y);
                float4 vv = *(const float4*)&vS[rh * 128 + f4];
                __nv_bfloat162 p0 = __floats2bfloat162_rn(ftanha_(f0.x + vv.x), ftanha_(f0.y + vv.y));
                __nv_bfloat162 p1 = __floats2bfloat162_rn(ftanha_(f1.x + vv.z), ftanha_(f1.y + vv.w));
                o01 = *(uint32_t*)&p0; o23 = *(uint32_t*)&p1;
            }
            *(uint2*)(sm + MS_A + row * SPB + f4 * 2) = make_uint2(o01, o23);
        }
    }
    __syncthreads();

    MBAR_WAIT(bbar, 0);
    int w = tid >> 5, lane = tid & 31;
    int mblk = w & 3, nblk = w >> 2;
    int gid = lane >> 2, tig = lane & 3;

    float acc[2][4][4];
    #pragma unroll
    for (int mf = 0; mf < 2; mf++)
        #pragma unroll
        for (int nf = 0; nf < 4; nf++)
            #pragma unroll
            for (int j = 0; j < 4; j++) acc[mf][nf][j] = 0.0f;

    gemm_bf16_ldsm(smb + MS_A, smb + MS_B, acc, mblk, nblk, lane);

    // fused epilogue + row-sum (all 32 rows of this warp tile share one receiver)
    float sum[4][2];
    #pragma unroll
    for (int nf = 0; nf < 4; nf++) { sum[nf][0] = 0.0f; sum[nf][1] = 0.0f; }
    {
        int r0 = mblk * 32 + gid;
        float rw0 = RelS[r0];
        float rw1 = RelS[r0 + 8];
        float rw2 = RelS[r0 + 16];
        float rw3 = RelS[r0 + 24];
        #pragma unroll
        for (int nf = 0; nf < 4; nf++) {
            int c = nblk * 32 + nf * 8 + tig * 2;
            float bb0 = b2S[c], bb1 = b2S[c + 1];
            sum[nf][0] += rw0 * ftanha_(acc[0][nf][0] + bb0)
                        + rw1 * ftanha_(acc[0][nf][2] + bb0)
                        + rw2 * ftanha_(acc[1][nf][0] + bb0)
                        + rw3 * ftanha_(acc[1][nf][2] + bb0);
            sum[nf][1] += rw0 * ftanha_(acc[0][nf][1] + bb1)
                        + rw1 * ftanha_(acc[0][nf][3] + bb1)
                        + rw2 * ftanha_(acc[1][nf][1] + bb1)
                        + rw3 * ftanha_(acc[1][nf][3] + bb1);
        }
    }
    #pragma unroll
    for (int off = 16; off >= 4; off >>= 1)
        #pragma unroll
        for (int nf = 0; nf < 4; nf++) {
            sum[nf][0] += __shfl_down_sync(0xffffffffu, sum[nf][0], off);
            sum[nf][1] += __shfl_down_sync(0xffffffffu, sum[nf][1], off);
        }
    if (gid == 0) {
        #pragma unroll
        for (int nf = 0; nf < 4; nf++) {
            int c = nblk * 32 + nf * 8 + tig * 2;
            *(float2*)&scr[mblk * 128 + c] = make_float2(sum[nf][0], sum[nf][1]);
        }
    }
    __syncthreads();
    if (tid < 256) {
        int h = tid & 127, rh = tid >> 7;
        float a = scr[(rh * 2) * 128 + h] + scr[(rh * 2 + 1) * 128 + h];
        int rv = rh ? r1n : r0n;
        g_aggk[(((size_t)k * BB + b) * NN + rv) * HH + h] = a;
    }
}

// ---------------- NODE kernel (transposed padded weights) ----------------
#define ND_WB0 0
#define ND_WB1 67584
#define ND_AGG 135168
#define ND_HID 139264
#define ND_T1  143360
#define ND_T2  147456
#define ND_INS 151552
#define ND_WIN 151808
#define ND_BIA 157952
#define ND_WO3 160512
#define ND_BO3 162560
#define ND_MB  162576
#define NODE_SMEM 162640

__global__ __launch_bounds__(256)
void node_kernel(const float* __restrict__ data, int step,
                 const float* __restrict__ Wr_in, const float* __restrict__ br_in,
                 const float* __restrict__ Wi_in, const float* __restrict__ bi_in,
                 const float* __restrict__ Wn_in, const float* __restrict__ bn_in,
                 const float* __restrict__ bo1, const float* __restrict__ bo2,
                 const float* __restrict__ Wo3, const float* __restrict__ bo3,
                 float* __restrict__ out) {
    extern __shared__ char sm[];
    uint32_t smb = smem_u32(sm);
    int q = blockIdx.x, b = blockIdx.y;
    int n0 = q * 8;
    int tid = threadIdx.x;

    float* aggS = (float*)(sm + ND_AGG);
    float* hidS = (float*)(sm + ND_HID);
    float* t1   = (float*)(sm + ND_T1);
    float* t2   = (float*)(sm + ND_T2);
    float* insS = (float*)(sm + ND_INS);
    float* WinS = (float*)(sm + ND_WIN);
    float* biaS = (float*)(sm + ND_BIA);
    float* Wo3S = (float*)(sm + ND_WO3);
    float* bo3S = (float*)(sm + ND_BO3);
    uint32_t mb0 = smb + ND_MB, mb1 = smb + ND_MB + 8;

    if (tid == 0) {
        MBAR_INIT(mb0, 1);
        MBAR_INIT(mb1, 1);
        FENCE_ASYNC();
        MBAR_EXPECT_TX(mb0, TILEF_B);
        BULK_CP(smb + ND_WB0, (const char*)(g_WnT + 0), TILEF_B, mb0);
        MBAR_EXPECT_TX(mb1, TILEF_B);
        BULK_CP(smb + ND_WB1, (const char*)(g_WnT + (size_t)1 * 128 * SPW), TILEF_B, mb1);
    }
    {
        size_t base = ((size_t)(b * NN + n0)) * HH;
        const float4* a0 = (const float4*)(g_aggk + base);
        const float4* a1 = (const float4*)(g_aggk + base + (size_t)BB * NN * HH);
        const float4* a2 = (const float4*)(g_aggk + base + (size_t)2 * BB * NN * HH);
        const float4* a3 = (const float4*)(g_aggk + base + (size_t)3 * BB * NN * HH);
        float4 s0 = a0[tid], s1 = a1[tid], s2 = a2[tid], s3 = a3[tid];
        float4 s;
        s.x = (s0.x + s1.x + s2.x + s3.x) * (1.0f / 16.0f);
        s.y = (s0.y + s1.y + s2.y + s3.y) * (1.0f / 16.0f);
        s.z = (s0.z + s1.z + s2.z + s3.z) * (1.0f / 16.0f);
        s.w = (s0.w + s1.w + s2.w + s3.w) * (1.0f / 16.0f);
        ((float4*)aggS)[tid] = s;
        const float* hg = g_hidden + base;
        ((float4*)hidS)[tid] = ((const float4*)hg)[tid];
    }
    if (tid < 32) {
        int n = tid >> 2, d = tid & 3;
        float v;
        if (step < TT) v = data[(((size_t)(b * NN + n0 + n)) * DD + d) * TT + step];
        else           v = g_pred[(b * NN + n0 + n) * DD + d];
        insS[tid] = v;
    }
    for (int i = tid; i < 512; i += 256) {
        WinS[i]        = Wr_in[i];
        WinS[512 + i]  = Wi_in[i];
        WinS[1024 + i] = Wn_in[i];
        Wo3S[i]        = Wo3[i];
    }
    if (tid < 128) {
        biaS[tid]       = br_in[tid];
        biaS[128 + tid] = bi_in[tid];
        biaS[256 + tid] = bn_in[tid];
        biaS[384 + tid] = bo1[tid];
        biaS[512 + tid] = bo2[tid];
    }
    if (tid < 4) bo3S[tid] = bo3[tid];
    __syncthreads();

    int h = tid & 127, ng = (tid >> 7) * 4;

    // dot(activation-row, WT-row-of-h) with vectorized weight reads
    #define GEMV4(ACT, WB, OUTARR) do { \
        const float4* _wt = (const float4*)(WB) + h * 33; \
        _Pragma("unroll") \
        for (int nn = 0; nn < 4; nn++) { \
            const float4* av = (const float4*)((ACT) + (ng + nn) * 128); \
            float a = 0.0f; \
            _Pragma("unroll 8") \
            for (int f4 = 0; f4 < 32; f4++) { \
                float4 x = av[f4]; \
                float4 wv = _wt[f4]; \
                a += x.x * wv.x + x.y * wv.y + x.z * wv.z + x.w * wv.w; \
            } \
            (OUTARR)[nn] = a; \
        } \
    } while (0)

    float acc[4];
    float rr[4], ii[4];

    MBAR_WAIT(mb0, 0);
    GEMV4(aggS, (sm + ND_WB0), acc);
    #pragma unroll
    for (int nn = 0; nn < 4; nn++) {
        int n = ng + nn;
        float a = acc[nn] + biaS[h];
        #pragma unroll
        for (int d = 0; d < 4; d++) a += insS[n*4+d] * WinS[d*128 + h];
        t1[n*128 + h] = fsig_(a);
    }
    __syncthreads();
    if (tid == 0) { MBAR_EXPECT_TX(mb0, TILEF_B); BULK_CP(smb + ND_WB0, (const char*)(g_WnT + (size_t)2 * 128 * SPW), TILEF_B, mb0); }

    MBAR_WAIT(mb1, 0);
    GEMV4(aggS, (sm + ND_WB1), acc);
    #pragma unroll
    for (int nn = 0; nn < 4; nn++) {
        int n = ng + nn;
        float a = acc[nn] + biaS[128 + h];
        #pragma unroll
        for (int d = 0; d < 4; d++) a += insS[n*4+d] * WinS[512 + d*128 + h];
        ii[nn] = fsig_(a);
        rr[nn] = t1[n*128 + h];
    }
    __syncthreads();
    if (tid == 0) { MBAR_EXPECT_TX(mb1, TILEF_B); BULK_CP(smb + ND_WB1, (const char*)(g_WnT + (size_t)3 * 128 * SPW), TILEF_B, mb1); }

    MBAR_WAIT(mb0, 1);
    GEMV4(aggS, (sm + ND_WB0), acc);
    #pragma unroll
    for (int nn = 0; nn < 4; nn++) {
        int n = ng + nn;
        float a = biaS[256 + h];
        #pragma unroll
        for (int d = 0; d < 4; d++) a += insS[n*4+d] * WinS[1024 + d*128 + h];
        float nv = ftanh_(a + rr[nn] * acc[nn]);
        float hn = (1.0f - ii[nn]) * nv + ii[nn] * hidS[n*128 + h];
        hidS[n*128 + h] = hn;
        g_hidden[((size_t)(b * NN + n0 + n)) * HH + h] = hn;
    }
    __syncthreads();
    if (tid == 0) { MBAR_EXPECT_TX(mb0, TILEF_B); BULK_CP(smb + ND_WB0, (const char*)(g_WnT + (size_t)4 * 128 * SPW), TILEF_B, mb0); }

    MBAR_WAIT(mb1, 1);
    GEMV4(hidS, (sm + ND_WB1), acc);
    #pragma unroll
    for (int nn = 0; nn < 4; nn++)
        t1[(ng+nn)*128 + h] = fmaxf(acc[nn] + biaS[384 + h], 0.0f);
    __syncthreads();

    MBAR_WAIT(mb0, 0);
    GEMV4(t1, (sm + ND_WB0), acc);
    #pragma unroll
    for (int nn = 0; nn < 4; nn++)
        t2[(ng+nn)*128 + h] = fmaxf(acc[nn] + biaS[512 + h], 0.0f);
    __syncthreads();

    if (tid < 32) {
        int n = tid >> 2, d = tid & 3;
        float a = bo3S[d];
        const float* vv = t2 + n*128;
        #pragma unroll 8
        for (int hh = 0; hh < 128; hh++) a += vv[hh] * Wo3S[hh*4 + d];
        float pred = insS[tid] + a;
        g_pred[(b * NN + n0 + n) * DD + d] = pred;
        if (step >= TT)
            out[(((size_t)(b * NN + n0 + n)) * DD + d) * LL + (step - TT)] = pred;
    }
    #undef GEMV4
}

// ---------------- launch ----------------
extern "C" void kernel_launch(void* const* d_in, const int* in_sizes, int n_in,
                              void* d_out, int out_size) {
    const float* data  = (const float*)d_in[0];
    const float* rel   = (const float*)d_in[1];
    const float* W1    = (const float*)d_in[2];
    const float* b1    = (const float*)d_in[3];
    const float* W2    = (const float*)d_in[4];
    const float* b2    = (const float*)d_in[5];
    const float* Wr_h  = (const float*)d_in[6];
    const float* Wi_h  = (const float*)d_in[7];
    const float* Wh_h  = (const float*)d_in[8];
    const float* Wr_in = (const float*)d_in[9];
    const float* br_in = (const float*)d_in[10];
    const float* Wi_in = (const float*)d_in[11];
    const float* bi_in = (const float*)d_in[12];
    const float* Wn_in = (const float*)d_in[13];
    const float* bn_in = (const float*)d_in[14];
    const float* Wo1   = (const float*)d_in[15];
    const float* bo1   = (const float*)d_in[16];
    const float* Wo2   = (const float*)d_in[17];
    const float* bo2   = (const float*)d_in[18];
    const float* Wo3   = (const float*)d_in[19];
    const float* bo3   = (const float*)d_in[20];
    const int* recv_idx = (const int*)d_in[21];
    const int* send_idx = (const int*)d_in[22];
    float* out = (float*)d_out;

    cudaFuncSetAttribute(uv_kernel,   cudaFuncAttributeMaxDynamicSharedMemorySize, UV_SMEM);
    cudaFuncSetAttribute(msg_kernel,  cudaFuncAttributeMaxDynamicSharedMemorySize, MSG_SMEM);
    cudaFuncSetAttribute(node_kernel, cudaFuncAttributeMaxDynamicSharedMemorySize, NODE_SMEM);

    init_kernel<<<512, 256>>>();
    prep_kernel<<<17, 256>>>(W1, W2, Wr_h, Wi_h, Wh_h, Wo1, Wo2);
    for (int s = 0; s < TT + LL; s++) {
        uv_kernel<<<dim3(8, 8), 512, UV_SMEM>>>();
        msg_kernel<<<dim3(32, BB, KK), 512, MSG_SMEM>>>(b1, b2, rel, recv_idx, send_idx);
        node_kernel<<<dim3(8, BB), 256, NODE_SMEM>>>(data, s,
            Wr_in, br_in, Wi_in, bi_in, Wn_in, bn_in,
            bo1, bo2, Wo3, bo3, out);
    }
}